// round 8
// baseline (speedup 1.0000x reference)
#include <cuda_runtime.h>

// B=4, H=W=128, C=256, heads=8, d=32, win=16 -> 256 windows x 256 tokens
// g_q: [win][head][tok][d]; g_k: [win][head][key][d]; g_v TRANSPOSED: [win][head][d][key]
__device__ float g_q[16777216];
__device__ float g_k[16777216];
__device__ float g_v[16777216];
__device__ float g_o[16777216];
__device__ float g_bias[524288];   // [head][256 q][256 k], pre-scaled by log2(e)

__device__ __forceinline__ float to_tf32(float x) {
    unsigned u;
    asm("cvt.rna.tf32.f32 %0, %1;" : "=r"(u) : "f"(x));
    return __uint_as_float(u);
}

__device__ __forceinline__ float ex2(float x) {
    float r;
    asm("ex2.approx.ftz.f32 %0, %1;" : "=f"(r) : "f"(x));
    return r;
}

__device__ __forceinline__ void mma_tf32(float* c, const unsigned* a, const unsigned* b) {
    asm volatile(
        "mma.sync.aligned.m16n8k8.row.col.f32.tf32.tf32.f32 "
        "{%0,%1,%2,%3},{%4,%5,%6,%7},{%8,%9},{%0,%1,%2,%3};"
        : "+f"(c[0]), "+f"(c[1]), "+f"(c[2]), "+f"(c[3])
        : "r"(a[0]), "r"(a[1]), "r"(a[2]), "r"(a[3]), "r"(b[0]), "r"(b[1]));
}

// tf32 fragments via b16 ldmatrix: an 8-row x 4-float block is isomorphic to
// a b16 8x8 tile (lane l gets 4 bytes at row l/4, 4B-col l%4).
__device__ __forceinline__ void ldsm4(unsigned* r, const float* p) {
    unsigned a = (unsigned)__cvta_generic_to_shared(p);
    asm volatile("ldmatrix.sync.aligned.m8n8.x4.shared.b16 {%0,%1,%2,%3}, [%4];"
                 : "=r"(r[0]), "=r"(r[1]), "=r"(r[2]), "=r"(r[3]) : "r"(a));
}

__device__ __forceinline__ void cpa16(float* dst, const float* src) {
    unsigned d = (unsigned)__cvta_generic_to_shared(dst);
    asm volatile("cp.async.cg.shared.global [%0], [%1], 16;" :: "r"(d), "l"(src));
}

// ---------------------------------------------------------------------------
// Bias expansion: g_bias[hd][q][k] = bias_table[rel_index(q,k)][hd] * log2(e)
// ---------------------------------------------------------------------------
__global__ void bias_expand(const float* __restrict__ bt) {
    const int kt = threadIdx.x, qt = blockIdx.x, hd = blockIdx.y;
    const int qy = qt >> 4, qx = qt & 15, ky = kt >> 4, kx = kt & 15;
    const int rel = (qy - ky + 15) * 31 + (qx - kx + 15);
    g_bias[(hd << 16) + (qt << 8) + kt] = bt[rel * 8 + hd] * 1.4426950408889634f;
}

// ---------------------------------------------------------------------------
// Conv 5x5 grouped (pad 2, groups=8) as implicit GEMM on tensor cores.
// K scattered as [key][d]; V scattered TRANSPOSED as [d][key].
// ---------------------------------------------------------------------------
#define CONV_PATCH_FL 14400   // 20*20*36
#define CONV_WBUF_FL  2304    // 32*72
#define CONV_SMEM_B   ((CONV_PATCH_FL + 2*CONV_WBUF_FL) * 4)

__global__ __launch_bounds__(256, 2) void convkv_mma(const float* __restrict__ X,
                                                     const float* __restrict__ Wc,
                                                     const float* __restrict__ bias) {
    extern __shared__ float smem[];
    float* patch = smem;
    float* wsm = smem + CONV_PATCH_FL;

    const int tid = threadIdx.x;
    const int lane = tid & 31, warp = tid >> 5;
    const int wm = warp & 3, wn = warp >> 2;
    const int g8 = lane >> 3, r8 = lane & 7;
    const int tile = blockIdx.x;
    const int ty0 = (tile >> 3) * 16, tx0 = (tile & 7) * 16;
    const int b = blockIdx.y >> 3, g = blockIdx.y & 7;

    for (int p = tid; p < 400; p += 256) {
        int py = p / 20, px = p - py * 20;
        int gy = ty0 + py - 2, gx = tx0 + px - 2;
        bool ok = (gy >= 0 && gy < 128 && gx >= 0 && gx < 128);
        const float4* src = (const float4*)(X + ((b * 128 + gy) * 128 + gx) * 256 + g * 32);
#pragma unroll
        for (int c8 = 0; c8 < 8; c8++) {
            float4 v = ok ? src[c8] : make_float4(0.f, 0.f, 0.f, 0.f);
            float4 w = make_float4(to_tf32(v.x), to_tf32(v.y), to_tf32(v.z), to_tf32(v.w));
            *(float4*)&patch[p * 36 + c8 * 4] = w;
        }
    }

    const int wic = tid >> 3, woc = (tid & 7) * 8;
    {
        const float4* gp = (const float4*)(Wc + (0 * 32 + wic) * 512 + g * 64 + woc);
        float4 r0 = gp[0], r1 = gp[1];
        float* dw = wsm + wic * 72 + woc;
        *(float4*)dw = make_float4(to_tf32(r0.x), to_tf32(r0.y), to_tf32(r0.z), to_tf32(r0.w));
        *(float4*)(dw + 4) = make_float4(to_tf32(r1.x), to_tf32(r1.y), to_tf32(r1.z), to_tf32(r1.w));
    }
    __syncthreads();

    float acc[4][4][4] = {};

#pragma unroll 1
    for (int tap = 0; tap < 25; tap++) {
        const int ky = tap / 5, kx = tap - ky * 5;
        float4 r0, r1;
        if (tap < 24) {
            const float4* gp = (const float4*)(Wc + ((tap + 1) * 32 + wic) * 512 + g * 64 + woc);
            r0 = gp[0]; r1 = gp[1];
        }
        const float* wcur = wsm + (tap & 1) * CONV_WBUF_FL;
#pragma unroll
        for (int kc = 0; kc < 4; kc++) {
            unsigned a[4][4];
#pragma unroll
            for (int i = 0; i < 4; i++) {
                const float* ap = patch + ((wm * 4 + i + ky) * 20 + (g8 & 1) * 8 + r8 + kx) * 36
                                  + kc * 8 + (g8 >> 1) * 4;
                ldsm4(a[i], ap);
            }
#pragma unroll
            for (int j = 0; j < 4; j++) {
                const int nn = wn * 32 + j * 8 + (lane >> 2);
                unsigned bf[2];
                bf[0] = __float_as_uint(wcur[(kc * 8 + (lane & 3)) * 72 + nn]);
                bf[1] = __float_as_uint(wcur[(kc * 8 + (lane & 3) + 4) * 72 + nn]);
#pragma unroll
                for (int i = 0; i < 4; i++) mma_tf32(acc[i][j], a[i], bf);
            }
        }
        if (tap < 24) {
            float* dw = wsm + ((tap + 1) & 1) * CONV_WBUF_FL + wic * 72 + woc;
            *(float4*)dw = make_float4(to_tf32(r0.x), to_tf32(r0.y), to_tf32(r0.z), to_tf32(r0.w));
            *(float4*)(dw + 4) = make_float4(to_tf32(r1.x), to_tf32(r1.y), to_tf32(r1.z), to_tf32(r1.w));
        }
        __syncthreads();
    }

    const int win = b * 64 + (tile >> 3) * 8 + (tile & 7);
    const int head = (g & 3) * 2 + wn;
    if (g < 4) {   // K: [key][d]
        float* base = g_k + ((win * 8 + head) * 256) * 32;
#pragma unroll
        for (int i = 0; i < 4; i++) {
            const int p0 = wm * 64 + i * 16 + (lane >> 2);
#pragma unroll
            for (int j = 0; j < 4; j++) {
                const int col = wn * 32 + j * 8 + (lane & 3) * 2;
                const int d = col & 31;
                float b0 = bias[g * 64 + col], b1 = bias[g * 64 + col + 1];
                *(float2*)(base + p0 * 32 + d) =
                    make_float2(to_tf32(acc[i][j][0] + b0), to_tf32(acc[i][j][1] + b1));
                *(float2*)(base + (p0 + 8) * 32 + d) =
                    make_float2(to_tf32(acc[i][j][2] + b0), to_tf32(acc[i][j][3] + b1));
            }
        }
    } else {       // V transposed: [d][key]
        float* base = g_v + ((win * 8 + head) * 32) * 256;
#pragma unroll
        for (int i = 0; i < 4; i++) {
            const int p0 = wm * 64 + i * 16 + (lane >> 2);
#pragma unroll
            for (int j = 0; j < 4; j++) {
                const int col = wn * 32 + j * 8 + (lane & 3) * 2;
                const int d0 = col & 31;
                float b0 = bias[g * 64 + col], b1 = bias[g * 64 + col + 1];
                base[d0 * 256 + p0]           = to_tf32(acc[i][j][0] + b0);
                base[(d0 + 1) * 256 + p0]     = to_tf32(acc[i][j][1] + b1);
                base[d0 * 256 + p0 + 8]       = to_tf32(acc[i][j][2] + b0);
                base[(d0 + 1) * 256 + p0 + 8] = to_tf32(acc[i][j][3] + b1);
            }
        }
    }
}

// ---------------------------------------------------------------------------
// tf32 GEMM: MODE 0 qproj (-> g_q with scale*log2e), MODE 1 outproj (g_o->out)
// ---------------------------------------------------------------------------
#define GEMM_ABUF_FL 4608    // 128*36
#define GEMM_BBUF_FL 2304    // 32*72
#define GEMM_SMEM_B  ((2*GEMM_ABUF_FL + 2*GEMM_BBUF_FL) * 4)

template <int MODE>
__global__ __launch_bounds__(256, 2) void gemm_mma(const float* __restrict__ Aparam,
                                                   const float* __restrict__ Wm,
                                                   const float* __restrict__ bias,
                                                   const float* __restrict__ rz,
                                                   float* __restrict__ out) {
    extern __shared__ float smem[];
    float* as = smem;
    float* bs = smem + 2 * GEMM_ABUF_FL;

    const float* A = (MODE == 1) ? (const float*)g_o : Aparam;

    const int tid = threadIdx.x;
    const int lane = tid & 31, warp = tid >> 5;
    const int wm = warp & 3, wn = warp >> 2;
    const int g8 = lane >> 3, r8 = lane & 7;
    const int m0 = blockIdx.x * 128;
    const int n0 = blockIdx.y * 64;

    const int arow = tid >> 1, akoff = (tid & 1) * 16;
    const int wic = tid >> 3, woc = (tid & 7) * 8;

    {
        const float4* ga = (const float4*)(A + (m0 + arow) * 256 + akoff);
        float* da = as + arow * 36 + akoff;
#pragma unroll
        for (int c4 = 0; c4 < 4; c4++) {
            float4 v = ga[c4];
            *(float4*)(da + c4 * 4) = make_float4(to_tf32(v.x), to_tf32(v.y), to_tf32(v.z), to_tf32(v.w));
        }
        const float4* gb = (const float4*)(Wm + wic * 256 + n0 + woc);
        float4 r0 = gb[0], r1 = gb[1];
        float* db = bs + wic * 72 + woc;
        *(float4*)db = make_float4(to_tf32(r0.x), to_tf32(r0.y), to_tf32(r0.z), to_tf32(r0.w));
        *(float4*)(db + 4) = make_float4(to_tf32(r1.x), to_tf32(r1.y), to_tf32(r1.z), to_tf32(r1.w));
    }
    __syncthreads();

    float acc[2][4][4] = {};

#pragma unroll 1
    for (int kt = 0; kt < 8; kt++) {
        float4 pa[4], pb0, pb1;
        if (kt < 7) {
            const float4* ga = (const float4*)(A + (m0 + arow) * 256 + (kt + 1) * 32 + akoff);
#pragma unroll
            for (int c4 = 0; c4 < 4; c4++) pa[c4] = ga[c4];
            const float4* gb = (const float4*)(Wm + ((kt + 1) * 32 + wic) * 256 + n0 + woc);
            pb0 = gb[0]; pb1 = gb[1];
        }
        const float* acur = as + (kt & 1) * GEMM_ABUF_FL;
        const float* bcur = bs + (kt & 1) * GEMM_BBUF_FL;
#pragma unroll
        for (int kc = 0; kc < 4; kc++) {
            unsigned a[2][4];
#pragma unroll
            for (int i = 0; i < 2; i++) {
                const float* ap = acur + (wm * 32 + i * 16 + (g8 & 1) * 8 + r8) * 36
                                  + kc * 8 + (g8 >> 1) * 4;
                ldsm4(a[i], ap);
            }
#pragma unroll
            for (int j = 0; j < 4; j++) {
                const int nn = wn * 32 + j * 8 + (lane >> 2);
                unsigned bf[2];
                bf[0] = __float_as_uint(bcur[(kc * 8 + (lane & 3)) * 72 + nn]);
                bf[1] = __float_as_uint(bcur[(kc * 8 + (lane & 3) + 4) * 72 + nn]);
#pragma unroll
                for (int i = 0; i < 2; i++) mma_tf32(acc[i][j], a[i], bf);
            }
        }
        if (kt < 7) {
            float* da = as + ((kt + 1) & 1) * GEMM_ABUF_FL + arow * 36 + akoff;
#pragma unroll
            for (int c4 = 0; c4 < 4; c4++)
                *(float4*)(da + c4 * 4) = make_float4(to_tf32(pa[c4].x), to_tf32(pa[c4].y),
                                                      to_tf32(pa[c4].z), to_tf32(pa[c4].w));
            float* db = bs + ((kt + 1) & 1) * GEMM_BBUF_FL + wic * 72 + woc;
            *(float4*)db = make_float4(to_tf32(pb0.x), to_tf32(pb0.y), to_tf32(pb0.z), to_tf32(pb0.w));
            *(float4*)(db + 4) = make_float4(to_tf32(pb1.x), to_tf32(pb1.y), to_tf32(pb1.z), to_tf32(pb1.w));
        }
        __syncthreads();
    }

    const float scale = 0.17677669529663687f * 1.4426950408889634f;  // qproj folds log2(e)
    const float r = (MODE == 1) ? rz[0] : 0.f;
#pragma unroll
    for (int i = 0; i < 2; i++) {
        const int m = m0 + wm * 32 + i * 16 + (lane >> 2);
#pragma unroll
        for (int j = 0; j < 4; j++) {
            const int col = n0 + wn * 32 + j * 8 + (lane & 3) * 2;
            const float b0 = bias[col], b1 = bias[col + 1];
            if (MODE == 0) {
                const int bi = m >> 14, rr = (m >> 7) & 127, cc = m & 127;
                const int win = bi * 64 + ((rr >> 4) << 3) + (cc >> 4);
                const int t = (rr & 15) * 16 + (cc & 15);
                const int head = col >> 5, d = col & 31;
                float* p = g_q + ((win * 8 + head) * 256 + t) * 32 + d;
                *(float2*)p = make_float2(to_tf32((acc[i][j][0] + b0) * scale),
                                          to_tf32((acc[i][j][1] + b1) * scale));
                *(float2*)(p + 8 * 32) = make_float2(to_tf32((acc[i][j][2] + b0) * scale),
                                                     to_tf32((acc[i][j][3] + b1) * scale));
            } else {
                float* p = out + m * 256 + col;
                *(float2*)p = make_float2(r * (acc[i][j][0] + b0), r * (acc[i][j][1] + b1));
                *(float2*)(p + 8 * 256) = make_float2(r * (acc[i][j][2] + b0), r * (acc[i][j][3] + b1));
            }
        }
    }
}

// ---------------------------------------------------------------------------
// Tensor-core flash attention v5: BARRIER-FREE mainloop.
//  - ALL of K (256x36, reusing Q staging region) and V (32x260, [d][key])
//    resident in smem before the loop; no cp.async waits / __syncthreads
//    inside the 8-chunk loop -> compiler overlaps PV(c) with S(c+1).
//  - Q fragments register-resident; K/V/P fragments via ldmatrix.
//  - log2-domain softmax, bias as accumulator init, deferred l reduction.
// ---------------------------------------------------------------------------
#define ATT_K_FL 9216           // 256*36 (shared with Q staging)
#define ATT_V_FL 8320           // 32*260
#define ATT_P_FL 9216           // 8 warps * 32*36
#define ATT_SMEM_B ((ATT_K_FL + ATT_V_FL + ATT_P_FL) * 4)   // 107008 B

__global__ __launch_bounds__(256, 2) void attn_mma() {
    extern __shared__ float sm[];
    float* Qs = sm;                 // staging; becomes K after Q frags read
    float* Ks = sm;                 // [key 256][d 32] pitch 36
    float* Vs = sm + ATT_K_FL;      // [d 32][key 256] pitch 260
    float* Ps = Vs + ATT_V_FL;      // 8 warps x 32x36

    const int win = blockIdx.x, hd = blockIdx.y;
    const int tid = threadIdx.x;
    const int lane = tid & 31, warp = tid >> 5;
    const int q = lane >> 2, t = lane & 3;
    const int g8 = lane >> 3, r8 = lane & 7;
    const int wb = warp * 32;
    float* Pw = Ps + warp * 1152;

    const float* qb = g_q + (win * 8 + hd) * 8192;
    const float* kb = g_k + (win * 8 + hd) * 8192;
    const float* vtb = g_v + (win * 8 + hd) * 8192;   // [32 d][256 key]
    const float* bb = g_bias + (hd << 16);

    // V first (region is free), then Q staging; one wait covers both.
#pragma unroll
    for (int c = 0; c < 8; c++) {
        const int idx = c * 256 + tid;          // 0..2047
        const int d = idx >> 6, seg = (idx & 63) * 4;
        cpa16(Vs + d * 260 + seg, vtb + d * 256 + seg);
    }
    asm volatile("cp.async.commit_group;");
#pragma unroll
    for (int c = 0; c < 8; c++) {
        const int idx = c * 256 + tid;
        const int row = idx >> 3, seg = (idx & 7) * 4;
        cpa16(Qs + row * 36 + seg, qb + idx * 4);
    }
    asm volatile("cp.async.commit_group;");
    asm volatile("cp.async.wait_group 0;");
    __syncthreads();

    // Q fragments -> registers (once)
    unsigned qa[2][4][4];
#pragma unroll
    for (int mt = 0; mt < 2; mt++)
#pragma unroll
        for (int kc = 0; kc < 4; kc++)
            ldsm4(qa[mt][kc], Qs + (wb + mt * 16 + (g8 & 1) * 8 + r8) * 36 + kc * 8 + (g8 >> 1) * 4);
    __syncthreads();   // everyone done reading Q region

    // K overwrites the Q region
#pragma unroll
    for (int c = 0; c < 8; c++) {
        const int idx = c * 256 + tid;
        const int row = idx >> 3, seg = (idx & 7) * 4;
        cpa16(Ks + row * 36 + seg, kb + idx * 4);
    }
    asm volatile("cp.async.commit_group;");
    asm volatile("cp.async.wait_group 0;");
    __syncthreads();   // LAST barrier — mainloop is barrier-free

    float o[2][4][4] = {};
    float mrow[2][2] = {{-1e30f, -1e30f}, {-1e30f, -1e30f}};
    float lrow[2][2] = {};   // per-lane partials, reduced in epilogue

#pragma unroll 2
    for (int sb = 0; sb < 8; sb++) {
        const float* Kb = Ks + sb * 32 * 36;
        const float* Vb = Vs + sb * 32;

        // ---- S = Q K^T for BOTH m-tiles, bias as accumulator init ----
        float s[2][4][4];
#pragma unroll
        for (int mt = 0; mt < 2; mt++) {
            const float* br0 = bb + (wb + mt * 16 + q) * 256 + sb * 32 + t * 2;
            const float* br1 = br0 + 8 * 256;
#pragma unroll
            for (int nt = 0; nt < 4; nt++) {
                float2 b0 = *(const float2*)(br0 + nt * 8);
                float2 b1 = *(const float2*)(br1 + nt * 8);
                s[mt][nt][0] = b0.x; s[mt][nt][1] = b0.y;
                s[mt][nt][2] = b1.x; s[mt][nt][3] = b1.y;
            }
        }
#pragma unroll
        for (int kc = 0; kc < 4; kc++) {
#pragma unroll
            for (int pr = 0; pr < 2; pr++) {
                unsigned kf[4];
                ldsm4(kf, Kb + (pr * 16 + (g8 >> 1) * 8 + r8) * 36 + kc * 8 + (g8 & 1) * 4);
                mma_tf32(s[0][pr * 2 + 0], qa[0][kc], &kf[0]);
                mma_tf32(s[0][pr * 2 + 1], qa[0][kc], &kf[2]);
                mma_tf32(s[1][pr * 2 + 0], qa[1][kc], &kf[0]);
                mma_tf32(s[1][pr * 2 + 1], qa[1][kc], &kf[2]);
            }
        }

        // ---- online softmax per m-tile; raw P -> warp-private smem ----
#pragma unroll
        for (int mt = 0; mt < 2; mt++) {
            float mx0 = fmaxf(fmaxf(s[mt][0][0], s[mt][0][1]), fmaxf(s[mt][1][0], s[mt][1][1]));
            float mx1 = fmaxf(fmaxf(s[mt][0][2], s[mt][0][3]), fmaxf(s[mt][1][2], s[mt][1][3]));
            mx0 = fmaxf(mx0, fmaxf(fmaxf(s[mt][2][0], s[mt][2][1]), fmaxf(s[mt][3][0], s[mt][3][1])));
            mx1 = fmaxf(mx1, fmaxf(fmaxf(s[mt][2][2], s[mt][2][3]), fmaxf(s[mt][3][2], s[mt][3][3])));
            mx0 = fmaxf(mx0, __shfl_xor_sync(0xffffffff, mx0, 1));
            mx0 = fmaxf(mx0, __shfl_xor_sync(0xffffffff, mx0, 2));
            mx1 = fmaxf(mx1, __shfl_xor_sync(0xffffffff, mx1, 1));
            mx1 = fmaxf(mx1, __shfl_xor_sync(0xffffffff, mx1, 2));
            const float mn0 = fmaxf(mrow[mt][0], mx0);
            const float mn1 = fmaxf(mrow[mt][1], mx1);
            const float cor0 = ex2(mrow[mt][0] - mn0);
            const float cor1 = ex2(mrow[mt][1] - mn1);
            mrow[mt][0] = mn0; mrow[mt][1] = mn1;
#pragma unroll
            for (int dn = 0; dn < 4; dn++) {
                o[mt][dn][0] *= cor0; o[mt][dn][1] *= cor0;
                o[mt][dn][2] *= cor1; o[mt][dn][3] *= cor1;
            }
            float sm0 = 0.f, sm1 = 0.f;
#pragma unroll
            for (int nt = 0; nt < 4; nt++) {
                float p0 = ex2(s[mt][nt][0] - mn0);
                float p1 = ex2(s[mt][nt][1] - mn0);
                float p2 = ex2(s[mt][nt][2] - mn1);
                float p3 = ex2(s[mt][nt][3] - mn1);
                sm0 += p0 + p1; sm1 += p2 + p3;
                *(float2*)&Pw[(mt * 16 + q) * 36 + nt * 8 + 2 * t] = make_float2(p0, p1);
                *(float2*)&Pw[(mt * 16 + q + 8) * 36 + nt * 8 + 2 * t] = make_float2(p2, p3);
            }
            lrow[mt][0] = lrow[mt][0] * cor0 + sm0;
            lrow[mt][1] = lrow[mt][1] * cor1 + sm1;
        }
        __syncwarp();

        // ---- O += P V : P and V fragments via ldmatrix ----
#pragma unroll
        for (int kk = 0; kk < 4; kk++) {
            unsigned pa[2][4];
            ldsm4(pa[0], Pw + ((g8 & 1) * 8 + r8) * 36 + kk * 8 + (g8 >> 1) * 4);
            ldsm4(pa[1], Pw + (16 + (g8 & 1) * 8 + r8) * 36 + kk * 8 + (g8 >> 1) * 4);
            unsigned vf0[4], vf1[4];
            ldsm4(vf0, Vb + ((g8 >> 1) * 8 + r8) * 260 + kk * 8 + (g8 & 1) * 4);
            ldsm4(vf1, Vb + ((2 + (g8 >> 1)) * 8 + r8) * 260 + kk * 8 + (g8 & 1) * 4);
            mma_tf32(o[0][0], pa[0], &vf0[0]);
            mma_tf32(o[0][1], pa[0], &vf0[2]);
            mma_tf32(o[0][2], pa[0], &vf1[0]);
            mma_tf32(o[0][3], pa[0], &vf1[2]);
            mma_tf32(o[1][0], pa[1], &vf0[0]);
            mma_tf32(o[1][1], pa[1], &vf0[2]);
            mma_tf32(o[1][2], pa[1], &vf1[0]);
            mma_tf32(o[1][3], pa[1], &vf1[2]);
        }
        __syncwarp();   // P reads done before next chunk's P stores
    }

    // Epilogue: reduce l partials, normalize, write (B,H,W,C) layout
    const int bimg = win >> 6, wh = (win >> 3) & 7, ww = win & 7;
#pragma unroll
    for (int mt = 0; mt < 2; mt++) {
        float l0 = lrow[mt][0], l1 = lrow[mt][1];
        l0 += __shfl_xor_sync(0xffffffff, l0, 1);
        l0 += __shfl_xor_sync(0xffffffff, l0, 2);
        l1 += __shfl_xor_sync(0xffffffff, l1, 1);
        l1 += __shfl_xor_sync(0xffffffff, l1, 2);
        const float inv0 = 1.f / l0;
        const float inv1 = 1.f / l1;
        const int tk0 = wb + mt * 16 + q;
#pragma unroll
        for (int half = 0; half < 2; half++) {
            const int tk = tk0 + half * 8;
            const float inv = half ? inv1 : inv0;
            const int gr = wh * 16 + (tk >> 4), gc = ww * 16 + (tk & 15);
            float* op = g_o + ((bimg * 128 + gr) * 128 + gc) * 256 + hd * 32;
#pragma unroll
            for (int dn = 0; dn < 4; dn++) {
                float a = o[mt][dn][half * 2] * inv;
                float b = o[mt][dn][half * 2 + 1] * inv;
                *(float2*)(op + dn * 8 + t * 2) = make_float2(a, b);
            }
        }
    }
}

// ---------------------------------------------------------------------------
extern "C" void kernel_launch(void* const* d_in, const int* in_sizes, int n_in,
                              void* d_out, int out_size) {
    (void)in_sizes; (void)n_in; (void)out_size;
    const float* x_wsa      = (const float*)d_in[0];
    const float* x_original = (const float*)d_in[1];
    const float* q_w        = (const float*)d_in[2];
    const float* q_b        = (const float*)d_in[3];
    const float* kv_w       = (const float*)d_in[4];
    const float* kv_b       = (const float*)d_in[5];
    const float* out_w      = (const float*)d_in[6];
    const float* out_b      = (const float*)d_in[7];
    const float* bias_table = (const float*)d_in[8];
    const float* rezero     = (const float*)d_in[9];
    float* out = (float*)d_out;

    cudaFuncSetAttribute(convkv_mma, cudaFuncAttributeMaxDynamicSharedMemorySize, CONV_SMEM_B);
    cudaFuncSetAttribute(gemm_mma<0>, cudaFuncAttributeMaxDynamicSharedMemorySize, GEMM_SMEM_B);
    cudaFuncSetAttribute(gemm_mma<1>, cudaFuncAttributeMaxDynamicSharedMemorySize, GEMM_SMEM_B);
    cudaFuncSetAttribute(attn_mma, cudaFuncAttributeMaxDynamicSharedMemorySize, ATT_SMEM_B);

    bias_expand<<<dim3(256, 8), 256>>>(bias_table);
    gemm_mma<0><<<dim3(512, 4), 256, GEMM_SMEM_B>>>(x_wsa, q_w, q_b, nullptr, nullptr);
    convkv_mma<<<dim3(64, 32), 256, CONV_SMEM_B>>>(x_original, kv_w, kv_b);
    attn_mma<<<dim3(256, 8), 256, ATT_SMEM_B>>>();
    gemm_mma<1><<<dim3(512, 4), 256, GEMM_SMEM_B>>>(nullptr, out_w, out_b, rezero, out);
}

// round 9
// speedup vs baseline: 1.4866x; 1.4866x over previous
#include <cuda_runtime.h>

// B=4, H=W=128, C=256, heads=8, d=32, win=16 -> 256 windows x 256 tokens
// g_q: [win][head][tok][d]; g_k: [win][head][key][d]; g_v TRANSPOSED: [win][head][d][key]
__device__ float g_q[16777216];
__device__ float g_k[16777216];
__device__ float g_v[16777216];
__device__ float g_o[16777216];
__device__ float g_bias[524288];   // [head][256 q][256 k], pre-scaled by log2(e)
__device__ float g_wt[133120];     // 2 x [256 n][260 pitch k]: tf32(qw^T), tf32(ow^T)
__device__ float g_wct[409600];    // conv weights: [(g*64+oc)][25 taps * 32 k] pitch 800

__device__ __forceinline__ float to_tf32(float x) {
    unsigned u;
    asm("cvt.rna.tf32.f32 %0, %1;" : "=r"(u) : "f"(x));
    return __uint_as_float(u);
}

__device__ __forceinline__ float ex2(float x) {
    float r;
    asm("ex2.approx.ftz.f32 %0, %1;" : "=f"(r) : "f"(x));
    return r;
}

__device__ __forceinline__ void mma_tf32(float* c, const unsigned* a, const unsigned* b) {
    asm volatile(
        "mma.sync.aligned.m16n8k8.row.col.f32.tf32.tf32.f32 "
        "{%0,%1,%2,%3},{%4,%5,%6,%7},{%8,%9},{%0,%1,%2,%3};"
        : "+f"(c[0]), "+f"(c[1]), "+f"(c[2]), "+f"(c[3])
        : "r"(a[0]), "r"(a[1]), "r"(a[2]), "r"(a[3]), "r"(b[0]), "r"(b[1]));
}

__device__ __forceinline__ void mma_tf32b(float* c, const unsigned* a, unsigned b0, unsigned b1) {
    asm volatile(
        "mma.sync.aligned.m16n8k8.row.col.f32.tf32.tf32.f32 "
        "{%0,%1,%2,%3},{%4,%5,%6,%7},{%8,%9},{%0,%1,%2,%3};"
        : "+f"(c[0]), "+f"(c[1]), "+f"(c[2]), "+f"(c[3])
        : "r"(a[0]), "r"(a[1]), "r"(a[2]), "r"(a[3]), "r"(b0), "r"(b1));
}

// tf32 fragments via b16 ldmatrix: an 8-row x 4-float block is isomorphic to
// a b16 8x8 tile (lane l gets 4 bytes at row l/4, 4B-col l%4).
__device__ __forceinline__ void ldsm4(unsigned* r, const float* p) {
    unsigned a = (unsigned)__cvta_generic_to_shared(p);
    asm volatile("ldmatrix.sync.aligned.m8n8.x4.shared.b16 {%0,%1,%2,%3}, [%4];"
                 : "=r"(r[0]), "=r"(r[1]), "=r"(r[2]), "=r"(r[3]) : "r"(a));
}

__device__ __forceinline__ void cpa16(float* dst, const float* src) {
    unsigned d = (unsigned)__cvta_generic_to_shared(dst);
    asm volatile("cp.async.cg.shared.global [%0], [%1], 16;" :: "r"(d), "l"(src));
}

// ---------------------------------------------------------------------------
// Prep kernels (run once per launch): bias expansion + weight transposes.
// ---------------------------------------------------------------------------
__global__ void bias_expand(const float* __restrict__ bt) {
    const int kt = threadIdx.x, qt = blockIdx.x, hd = blockIdx.y;
    const int qy = qt >> 4, qx = qt & 15, ky = kt >> 4, kx = kt & 15;
    const int rel = (qy - ky + 15) * 31 + (qx - kx + 15);
    g_bias[(hd << 16) + (qt << 8) + kt] = bt[rel * 8 + hd] * 1.4426950408889634f;
}

__global__ void prep_gemm_w(const float* __restrict__ W, int slot) {
    const int idx = blockIdx.x * 256 + threadIdx.x;   // 65536
    const int n = idx >> 8, k = idx & 255;
    g_wt[slot * 66560 + n * 260 + k] = to_tf32(W[k * 256 + n]);
}

__global__ void prep_conv_w(const float* __restrict__ Wc) {
    const int idx = blockIdx.x * 256 + threadIdx.x;   // 409600
    const int k = idx & 31;
    const int tap = (idx >> 5) % 25;
    const int ocg = idx / 800;                        // g*64 + oc
    const int g = ocg >> 6, oc = ocg & 63;
    g_wct[ocg * 800 + tap * 32 + k] = to_tf32(Wc[(tap * 32 + k) * 512 + g * 64 + oc]);
}

// ---------------------------------------------------------------------------
// Conv 5x5 grouped (pad 2, groups=8) as implicit GEMM on tensor cores.
// Weights pre-transposed/tf32 in g_wct -> cp.async 3-slot ring, ldsm B frags.
// K scattered as [key][d]; V scattered TRANSPOSED as [d][key].
// ---------------------------------------------------------------------------
#define CONV_PATCH_FL 14400   // 20*20*36
#define CONV_WBUF_FL  2304    // 64 oc * 36 (32 k + pad)
#define CONV_SMEM_B   ((CONV_PATCH_FL + 3*CONV_WBUF_FL) * 4)

__global__ __launch_bounds__(256, 2) void convkv_mma(const float* __restrict__ X,
                                                     const float* __restrict__ bias) {
    extern __shared__ float smem[];
    float* patch = smem;
    float* wring = smem + CONV_PATCH_FL;

    const int tid = threadIdx.x;
    const int lane = tid & 31, warp = tid >> 5;
    const int wm = warp & 3, wn = warp >> 2;
    const int g8 = lane >> 3, r8 = lane & 7;
    const int tile = blockIdx.x;
    const int ty0 = (tile >> 3) * 16, tx0 = (tile & 7) * 16;
    const int b = blockIdx.y >> 3, g = blockIdx.y & 7;

    const float* wsrc = g_wct + (g * 64) * 800;
    const int wrow = tid >> 3, wseg = (tid & 7) * 4;   // cp.async mapping (2/thread)

    // Issue weight taps 0 and 1 into ring slots 0,1
#pragma unroll
    for (int c = 0; c < 2; c++) {
        const int idx = c * 256 + tid;
        cpa16(wring + 0 * CONV_WBUF_FL + (idx >> 3) * 36 + (idx & 7) * 4,
              wsrc + (idx >> 3) * 800 + 0 * 32 + (idx & 7) * 4);
    }
    asm volatile("cp.async.commit_group;");
#pragma unroll
    for (int c = 0; c < 2; c++) {
        const int idx = c * 256 + tid;
        cpa16(wring + 1 * CONV_WBUF_FL + (idx >> 3) * 36 + (idx & 7) * 4,
              wsrc + (idx >> 3) * 800 + 1 * 32 + (idx & 7) * 4);
    }
    asm volatile("cp.async.commit_group;");

    // Stage input patch (zero-padded), converted to tf32
    for (int p = tid; p < 400; p += 256) {
        int py = p / 20, px = p - py * 20;
        int gy = ty0 + py - 2, gx = tx0 + px - 2;
        bool ok = (gy >= 0 && gy < 128 && gx >= 0 && gx < 128);
        const float4* src = (const float4*)(X + ((b * 128 + gy) * 128 + gx) * 256 + g * 32);
#pragma unroll
        for (int c8 = 0; c8 < 8; c8++) {
            float4 v = ok ? src[c8] : make_float4(0.f, 0.f, 0.f, 0.f);
            float4 w = make_float4(to_tf32(v.x), to_tf32(v.y), to_tf32(v.z), to_tf32(v.w));
            *(float4*)&patch[p * 36 + c8 * 4] = w;
        }
    }

    float acc[4][4][4] = {};

#pragma unroll 1
    for (int tap = 0; tap < 25; tap++) {
        const int ky = tap / 5, kx = tap - ky * 5;
        if (tap < 23) asm volatile("cp.async.wait_group 1;");
        else          asm volatile("cp.async.wait_group 0;");
        __syncthreads();   // tap's weights + (first iter) patch visible; slot (tap+2)%3 free
        if (tap < 23) {
            const int nt = tap + 2;
            float* dst = wring + (nt % 3) * CONV_WBUF_FL;
#pragma unroll
            for (int c = 0; c < 2; c++) {
                const int idx = c * 256 + tid;
                cpa16(dst + (idx >> 3) * 36 + (idx & 7) * 4,
                      wsrc + (idx >> 3) * 800 + nt * 32 + (idx & 7) * 4);
            }
            asm volatile("cp.async.commit_group;");
        }
        const float* wcur = wring + (tap % 3) * CONV_WBUF_FL;
#pragma unroll
        for (int kc = 0; kc < 4; kc++) {
            unsigned a[4][4];
#pragma unroll
            for (int i = 0; i < 4; i++) {
                const float* ap = patch + ((wm * 4 + i + ky) * 20 + (g8 & 1) * 8 + r8 + kx) * 36
                                  + kc * 8 + (g8 >> 1) * 4;
                ldsm4(a[i], ap);
            }
            unsigned bfa[4], bfb[4];
            ldsm4(bfa, wcur + (wn * 32 + g8 * 8 + r8) * 36 + kc * 8);
            ldsm4(bfb, wcur + (wn * 32 + g8 * 8 + r8) * 36 + kc * 8 + 4);
#pragma unroll
            for (int j = 0; j < 4; j++)
#pragma unroll
                for (int i = 0; i < 4; i++) mma_tf32b(acc[i][j], a[i], bfa[j], bfb[j]);
        }
    }

    const int win = b * 64 + (tile >> 3) * 8 + (tile & 7);
    const int head = (g & 3) * 2 + wn;
    if (g < 4) {   // K: [key][d]
        float* base = g_k + ((win * 8 + head) * 256) * 32;
#pragma unroll
        for (int i = 0; i < 4; i++) {
            const int p0 = wm * 64 + i * 16 + (lane >> 2);
#pragma unroll
            for (int j = 0; j < 4; j++) {
                const int col = wn * 32 + j * 8 + (lane & 3) * 2;
                const int d = col & 31;
                float b0 = bias[g * 64 + col], b1 = bias[g * 64 + col + 1];
                *(float2*)(base + p0 * 32 + d) =
                    make_float2(to_tf32(acc[i][j][0] + b0), to_tf32(acc[i][j][1] + b1));
                *(float2*)(base + (p0 + 8) * 32 + d) =
                    make_float2(to_tf32(acc[i][j][2] + b0), to_tf32(acc[i][j][3] + b1));
            }
        }
    } else {       // V transposed: [d][key]
        float* base = g_v + ((win * 8 + head) * 32) * 256;
#pragma unroll
        for (int i = 0; i < 4; i++) {
            const int p0 = wm * 64 + i * 16 + (lane >> 2);
#pragma unroll
            for (int j = 0; j < 4; j++) {
                const int col = wn * 32 + j * 8 + (lane & 3) * 2;
                const int d0 = col & 31;
                float b0 = bias[g * 64 + col], b1 = bias[g * 64 + col + 1];
                base[d0 * 256 + p0]           = to_tf32(acc[i][j][0] + b0);
                base[(d0 + 1) * 256 + p0]     = to_tf32(acc[i][j][1] + b1);
                base[d0 * 256 + p0 + 8]       = to_tf32(acc[i][j][2] + b0);
                base[(d0 + 1) * 256 + p0 + 8] = to_tf32(acc[i][j][3] + b1);
            }
        }
    }
}

// ---------------------------------------------------------------------------
// tf32 GEMM: MODE 0 qproj (-> g_q with scale*log2e), MODE 1 outproj (g_o->out)
// B pre-transposed/tf32 in g_wt -> cp.async 3-slot ring + ldsm fragments.
// ---------------------------------------------------------------------------
#define GEMM_ABUF_FL 4608    // 128*36
#define GEMM_BBUF_FL 2304    // 64 n * 36
#define GEMM_SMEM_B  ((2*GEMM_ABUF_FL + 3*GEMM_BBUF_FL) * 4)

template <int MODE>
__global__ __launch_bounds__(256, 2) void gemm_mma(const float* __restrict__ Aparam,
                                                   const float* __restrict__ bias,
                                                   const float* __restrict__ rz,
                                                   float* __restrict__ out) {
    extern __shared__ float smem[];
    float* as = smem;                        // 2 x [128][36]
    float* bs = smem + 2 * GEMM_ABUF_FL;     // 3 x [64][36]

    const float* A = (MODE == 1) ? (const float*)g_o : Aparam;
    const float* wt = g_wt + MODE * 66560;

    const int tid = threadIdx.x;
    const int lane = tid & 31, warp = tid >> 5;
    const int wm = warp & 3, wn = warp >> 2;
    const int g8 = lane >> 3, r8 = lane & 7;
    const int m0 = blockIdx.x * 128;
    const int n0 = blockIdx.y * 64;

    const int arow = tid >> 1, akoff = (tid & 1) * 16;

    // Issue B chunks 0,1 into ring slots 0,1
#pragma unroll
    for (int c = 0; c < 2; c++) {
        const int idx = c * 256 + tid;
        cpa16(bs + 0 * GEMM_BBUF_FL + (idx >> 3) * 36 + (idx & 7) * 4,
              wt + (n0 + (idx >> 3)) * 260 + 0 * 32 + (idx & 7) * 4);
    }
    asm volatile("cp.async.commit_group;");
#pragma unroll
    for (int c = 0; c < 2; c++) {
        const int idx = c * 256 + tid;
        cpa16(bs + 1 * GEMM_BBUF_FL + (idx >> 3) * 36 + (idx & 7) * 4,
              wt + (n0 + (idx >> 3)) * 260 + 1 * 32 + (idx & 7) * 4);
    }
    asm volatile("cp.async.commit_group;");

    {   // A chunk 0 -> abuf 0
        const float4* ga = (const float4*)(A + (m0 + arow) * 256 + akoff);
        float* da = as + arow * 36 + akoff;
#pragma unroll
        for (int c4 = 0; c4 < 4; c4++) {
            float4 v = ga[c4];
            *(float4*)(da + c4 * 4) = make_float4(to_tf32(v.x), to_tf32(v.y), to_tf32(v.z), to_tf32(v.w));
        }
    }

    float acc[2][4][4] = {};

#pragma unroll 1
    for (int kt = 0; kt < 8; kt++) {
        float4 pa[4];
        if (kt < 7) {
            const float4* ga = (const float4*)(A + (m0 + arow) * 256 + (kt + 1) * 32 + akoff);
#pragma unroll
            for (int c4 = 0; c4 < 4; c4++) pa[c4] = ga[c4];
        }
        if (kt < 6) asm volatile("cp.async.wait_group 1;");
        else        asm volatile("cp.async.wait_group 0;");
        __syncthreads();   // A(kt) STS'd last iter + B(kt) arrived; slot (kt+2)%3 free
        if (kt < 6) {
            const int nt = kt + 2;
            float* dst = bs + (nt % 3) * GEMM_BBUF_FL;
#pragma unroll
            for (int c = 0; c < 2; c++) {
                const int idx = c * 256 + tid;
                cpa16(dst + (idx >> 3) * 36 + (idx & 7) * 4,
                      wt + (n0 + (idx >> 3)) * 260 + nt * 32 + (idx & 7) * 4);
            }
            asm volatile("cp.async.commit_group;");
        }
        const float* acur = as + (kt & 1) * GEMM_ABUF_FL;
        const float* bcur = bs + (kt % 3) * GEMM_BBUF_FL;
#pragma unroll
        for (int kc = 0; kc < 4; kc++) {
            unsigned a[2][4];
#pragma unroll
            for (int i = 0; i < 2; i++) {
                const float* ap = acur + (wm * 32 + i * 16 + (g8 & 1) * 8 + r8) * 36
                                  + kc * 8 + (g8 >> 1) * 4;
                ldsm4(a[i], ap);
            }
            unsigned bfa[4], bfb[4];
            ldsm4(bfa, bcur + (wn * 32 + g8 * 8 + r8) * 36 + kc * 8);
            ldsm4(bfb, bcur + (wn * 32 + g8 * 8 + r8) * 36 + kc * 8 + 4);
#pragma unroll
            for (int j = 0; j < 4; j++)
#pragma unroll
                for (int i = 0; i < 2; i++) mma_tf32b(acc[i][j], a[i], bfa[j], bfb[j]);
        }
        if (kt < 7) {
            float* da = as + ((kt + 1) & 1) * GEMM_ABUF_FL + arow * 36 + akoff;
#pragma unroll
            for (int c4 = 0; c4 < 4; c4++)
                *(float4*)(da + c4 * 4) = make_float4(to_tf32(pa[c4].x), to_tf32(pa[c4].y),
                                                      to_tf32(pa[c4].z), to_tf32(pa[c4].w));
        }
    }

    const float scale = 0.17677669529663687f * 1.4426950408889634f;  // qproj folds log2(e)
    const float r = (MODE == 1) ? rz[0] : 0.f;
#pragma unroll
    for (int i = 0; i < 2; i++) {
        const int m = m0 + wm * 32 + i * 16 + (lane >> 2);
#pragma unroll
        for (int j = 0; j < 4; j++) {
            const int col = n0 + wn * 32 + j * 8 + (lane & 3) * 2;
            const float b0 = bias[col], b1 = bias[col + 1];
            if (MODE == 0) {
                const int bi = m >> 14, rr = (m >> 7) & 127, cc = m & 127;
                const int win = bi * 64 + ((rr >> 4) << 3) + (cc >> 4);
                const int t = (rr & 15) * 16 + (cc & 15);
                const int head = col >> 5, d = col & 31;
                float* p = g_q + ((win * 8 + head) * 256 + t) * 32 + d;
                *(float2*)p = make_float2(to_tf32((acc[i][j][0] + b0) * scale),
                                          to_tf32((acc[i][j][1] + b1) * scale));
                *(float2*)(p + 8 * 32) = make_float2(to_tf32((acc[i][j][2] + b0) * scale),
                                                     to_tf32((acc[i][j][3] + b1) * scale));
            } else {
                float* p = out + m * 256 + col;
                *(float2*)p = make_float2(r * (acc[i][j][0] + b0), r * (acc[i][j][1] + b1));
                *(float2*)(p + 8 * 256) = make_float2(r * (acc[i][j][2] + b0), r * (acc[i][j][3] + b1));
            }
        }
    }
}

// ---------------------------------------------------------------------------
// Tensor-core flash attention (R7 version — best measured: 223 us).
// ---------------------------------------------------------------------------
#define ATT_QS 9216            // 256*36
#define ATT_KS (3*1152)        // 3 stages * 32*36
#define ATT_VS (3*1152)        // 3 stages * 32 d * 36 (keys pitch)
#define ATT_PS 9216            // 8 warps * 32*36
#define ATT_SMEM_B ((ATT_QS + ATT_KS + ATT_VS + ATT_PS) * 4)

__global__ __launch_bounds__(256, 2) void attn_mma() {
    extern __shared__ float sm[];
    float* Qs = sm;
    float* Ks = sm + ATT_QS;
    float* Vs = Ks + ATT_KS;
    float* Ps = Vs + ATT_VS;

    const int win = blockIdx.x, hd = blockIdx.y;
    const int tid = threadIdx.x;
    const int lane = tid & 31, warp = tid >> 5;
    const int q = lane >> 2, t = lane & 3;
    const int g8 = lane >> 3, r8 = lane & 7;
    const int wb = warp * 32;
    float* Pw = Ps + warp * 1152;

    const float* qb = g_q + (win * 8 + hd) * 8192;
    const float* kb = g_k + (win * 8 + hd) * 8192;
    const float* vtb = g_v + (win * 8 + hd) * 8192;   // [32 d][256 key]
    const float* bb = g_bias + (hd << 16);

    // Stage Q into smem (pitch 36)
    for (int i = tid; i < 2048; i += 256) {
        float4 v = ((const float4*)qb)[i];
        *(float4*)&Qs[(i >> 3) * 36 + (i & 7) * 4] = v;
    }
    // cp.async chunks 0 and 1. K: [key][d]; V: [d][key] slices
    {
        const int row = tid >> 3, seg = (tid & 7) * 4;
#pragma unroll
        for (int c = 0; c < 2; c++) {
            cpa16(Ks + c * 1152 + row * 36 + seg, kb + c * 1024 + tid * 4);
            cpa16(Vs + c * 1152 + row * 36 + seg, vtb + row * 256 + c * 32 + seg);
            asm volatile("cp.async.commit_group;");
        }
    }
    __syncthreads();

    // Q fragments -> registers (once)
    unsigned qa[2][4][4];
#pragma unroll
    for (int mt = 0; mt < 2; mt++)
#pragma unroll
        for (int kc = 0; kc < 4; kc++)
            ldsm4(qa[mt][kc], Qs + (wb + mt * 16 + (g8 & 1) * 8 + r8) * 36 + kc * 8 + (g8 >> 1) * 4);

    float o[2][4][4] = {};
    float mrow[2][2] = {{-1e30f, -1e30f}, {-1e30f, -1e30f}};
    float lrow[2][2] = {};   // per-lane partials, reduced in epilogue

#pragma unroll 1
    for (int sb = 0; sb < 8; sb++) {
        asm volatile("cp.async.wait_group 1;");
        __syncthreads();

        if (sb < 6) {
            const int slot = (sb + 2) % 3;
            const int row = tid >> 3, seg = (tid & 7) * 4;
            cpa16(Ks + slot * 1152 + row * 36 + seg, kb + (sb + 2) * 1024 + tid * 4);
            cpa16(Vs + slot * 1152 + row * 36 + seg, vtb + row * 256 + (sb + 2) * 32 + seg);
        }
        asm volatile("cp.async.commit_group;");

        const float* Kb = Ks + (sb % 3) * 1152;
        const float* Vb = Vs + (sb % 3) * 1152;

        // ---- S = Q K^T for BOTH m-tiles, bias as accumulator init ----
        float s[2][4][4];
#pragma unroll
        for (int mt = 0; mt < 2; mt++) {
            const float* br0 = bb + (wb + mt * 16 + q) * 256 + sb * 32 + t * 2;
            const float* br1 = br0 + 8 * 256;
#pragma unroll
            for (int nt = 0; nt < 4; nt++) {
                float2 b0 = *(const float2*)(br0 + nt * 8);
                float2 b1 = *(const float2*)(br1 + nt * 8);
                s[mt][nt][0] = b0.x; s[mt][nt][1] = b0.y;
                s[mt][nt][2] = b1.x; s[mt][nt][3] = b1.y;
            }
        }
#pragma unroll
        for (int kc = 0; kc < 4; kc++) {
#pragma unroll
            for (int pr = 0; pr < 2; pr++) {
                unsigned kf[4];
                ldsm4(kf, Kb + (pr * 16 + (g8 >> 1) * 8 + r8) * 36 + kc * 8 + (g8 & 1) * 4);
                mma_tf32(s[0][pr * 2 + 0], qa[0][kc], &kf[0]);
                mma_tf32(s[0][pr * 2 + 1], qa[0][kc], &kf[2]);
                mma_tf32(s[1][pr * 2 + 0], qa[1][kc], &kf[0]);
                mma_tf32(s[1][pr * 2 + 1], qa[1][kc], &kf[2]);
            }
        }

        // ---- online softmax per m-tile; raw P -> warp-private smem ----
#pragma unroll
        for (int mt = 0; mt < 2; mt++) {
            float mx0 = fmaxf(fmaxf(s[mt][0][0], s[mt][0][1]), fmaxf(s[mt][1][0], s[mt][1][1]));
            float mx1 = fmaxf(fmaxf(s[mt][0][2], s[mt][0][3]), fmaxf(s[mt][1][2], s[mt][1][3]));
            mx0 = fmaxf(mx0, fmaxf(fmaxf(s[mt][2][0], s[mt][2][1]), fmaxf(s[mt][3][0], s[mt][3][1])));
            mx1 = fmaxf(mx1, fmaxf(fmaxf(s[mt][2][2], s[mt][2][3]), fmaxf(s[mt][3][2], s[mt][3][3])));
            mx0 = fmaxf(mx0, __shfl_xor_sync(0xffffffff, mx0, 1));
            mx0 = fmaxf(mx0, __shfl_xor_sync(0xffffffff, mx0, 2));
            mx1 = fmaxf(mx1, __shfl_xor_sync(0xffffffff, mx1, 1));
            mx1 = fmaxf(mx1, __shfl_xor_sync(0xffffffff, mx1, 2));
            const float mn0 = fmaxf(mrow[mt][0], mx0);
            const float mn1 = fmaxf(mrow[mt][1], mx1);
            const float cor0 = ex2(mrow[mt][0] - mn0);
            const float cor1 = ex2(mrow[mt][1] - mn1);
            mrow[mt][0] = mn0; mrow[mt][1] = mn1;
#pragma unroll
            for (int dn = 0; dn < 4; dn++) {
                o[mt][dn][0] *= cor0; o[mt][dn][1] *= cor0;
                o[mt][dn][2] *= cor1; o[mt][dn][3] *= cor1;
            }
            float sm0 = 0.f, sm1 = 0.f;
#pragma unroll
            for (int nt = 0; nt < 4; nt++) {
                float p0 = ex2(s[mt][nt][0] - mn0);
                float p1 = ex2(s[mt][nt][1] - mn0);
                float p2 = ex2(s[mt][nt][2] - mn1);
                float p3 = ex2(s[mt][nt][3] - mn1);
                sm0 += p0 + p1; sm1 += p2 + p3;
                *(float2*)&Pw[(mt * 16 + q) * 36 + nt * 8 + 2 * t] = make_float2(p0, p1);
                *(float2*)&Pw[(mt * 16 + q + 8) * 36 + nt * 8 + 2 * t] = make_float2(p2, p3);
            }
            lrow[mt][0] = lrow[mt][0] * cor0 + sm0;
            lrow[mt][1] = lrow[mt][1] * cor1 + sm1;
        }
        __syncwarp();

        // ---- O += P V : P and V fragments via ldmatrix ----
#pragma unroll
        for (int kk = 0; kk < 4; kk++) {
            unsigned pa[2][4];
            ldsm4(pa[0], Pw + ((g8 & 1) * 8 + r8) * 36 + kk * 8 + (g8 >> 1) * 4);
            ldsm4(pa[1], Pw + (16 + (g8 & 1) * 8 + r8) * 36 + kk * 8 + (g8 >> 1) * 4);
            unsigned vf0[4], vf1[4];
            ldsm4(vf0, Vb + ((g8 >> 1) * 8 + r8) * 36 + kk * 8 + (g8 & 1) * 4);
            ldsm4(vf1, Vb + ((2 + (g8 >> 1)) * 8 + r8) * 36 + kk * 8 + (g8 & 1) * 4);
            mma_tf32(o[0][0], pa[0], &vf0[0]);
            mma_tf32(o[0][1], pa[0], &vf0[2]);
            mma_tf32(o[0][2], pa[0], &vf1[0]);
            mma_tf32(o[0][3], pa[0], &vf1[2]);
            mma_tf32(o[1][0], pa[1], &vf0[0]);
            mma_tf32(o[1][1], pa[1], &vf0[2]);
            mma_tf32(o[1][2], pa[1], &vf1[0]);
            mma_tf32(o[1][3], pa[1], &vf1[2]);
        }
        __syncwarp();
    }

    // Epilogue: reduce l partials, normalize, write (B,H,W,C) layout
    const int bimg = win >> 6, wh = (win >> 3) & 7, ww = win & 7;
#pragma unroll
    for (int mt = 0; mt < 2; mt++) {
        float l0 = lrow[mt][0], l1 = lrow[mt][1];
        l0 += __shfl_xor_sync(0xffffffff, l0, 1);
        l0 += __shfl_xor_sync(0xffffffff, l0, 2);
        l1 += __shfl_xor_sync(0xffffffff, l1, 1);
        l1 += __shfl_xor_sync(0xffffffff, l1, 2);
        const float inv0 = 1.f / l0;
        const float inv1 = 1.f / l1;
        const int tk0 = wb + mt * 16 + q;
#pragma unroll
        for (int half = 0; half < 2; half++) {
            const int tk = tk0 + half * 8;
            const float inv = half ? inv1 : inv0;
            const int gr = wh * 16 + (tk >> 4), gc = ww * 16 + (tk & 15);
            float* op = g_o + ((bimg * 128 + gr) * 128 + gc) * 256 + hd * 32;
#pragma unroll
            for (int dn = 0; dn < 4; dn++) {
                float a = o[mt][dn][half * 2] * inv;
                float b = o[mt][dn][half * 2 + 1] * inv;
                *(float2*)(op + dn * 8 + t * 2) = make_float2(a, b);
            }
        }
    }
}

// ---------------------------------------------------------------------------
extern "C" void kernel_launch(void* const* d_in, const int* in_sizes, int n_in,
                              void* d_out, int out_size) {
    (void)in_sizes; (void)n_in; (void)out_size;
    const float* x_wsa      = (const float*)d_in[0];
    const float* x_original = (const float*)d_in[1];
    const float* q_w        = (const float*)d_in[2];
    const float* q_b        = (const float*)d_in[3];
    const float* kv_w       = (const float*)d_in[4];
    const float* kv_b       = (const float*)d_in[5];
    const float* out_w      = (const float*)d_in[6];
    const float* out_b      = (const float*)d_in[7];
    const float* bias_table = (const float*)d_in[8];
    const float* rezero     = (const float*)d_in[9];
    float* out = (float*)d_out;

    cudaFuncSetAttribute(convkv_mma, cudaFuncAttributeMaxDynamicSharedMemorySize, CONV_SMEM_B);
    cudaFuncSetAttribute(gemm_mma<0>, cudaFuncAttributeMaxDynamicSharedMemorySize, GEMM_SMEM_B);
    cudaFuncSetAttribute(gemm_mma<1>, cudaFuncAttributeMaxDynamicSharedMemorySize, GEMM_SMEM_B);
    cudaFuncSetAttribute(attn_mma, cudaFuncAttributeMaxDynamicSharedMemorySize, ATT_SMEM_B);

    bias_expand<<<dim3(256, 8), 256>>>(bias_table);
    prep_gemm_w<<<256, 256>>>(q_w, 0);
    prep_gemm_w<<<256, 256>>>(out_w, 1);
    prep_conv_w<<<1600, 256>>>(kv_w);

    gemm_mma<0><<<dim3(512, 4), 256, GEMM_SMEM_B>>>(x_wsa, q_b, nullptr, nullptr);
    convkv_mma<<<dim3(64, 32), 256, CONV_SMEM_B>>>(x_original, kv_b);
    attn_mma<<<dim3(256, 8), 256, ATT_SMEM_B>>>();
    gemm_mma<1><<<dim3(512, 4), 256, GEMM_SMEM_B>>>(nullptr, out_b, rezero, out);
}

// round 10
// speedup vs baseline: 1.5083x; 1.0146x over previous
#include <cuda_runtime.h>

// B=4, H=W=128, C=256, heads=8, d=32, win=16 -> 256 windows x 256 tokens
// g_q: [win][head][tok][d]; g_k: [win][head][key][d]; g_v TRANSPOSED: [win][head][d][key]
__device__ float g_q[16777216];
__device__ float g_k[16777216];
__device__ float g_v[16777216];
__device__ float g_o[16777216];
__device__ float g_bias[524288];   // [head][256 q][256 k], pre-scaled by log2(e)
__device__ float g_wt[133120];     // 2 x [256 n][260 pitch k]: tf32(qw^T), tf32(ow^T)
__device__ float g_wct[409600];    // conv weights: [(g*64+oc)][25 taps * 32 k] pitch 800

__device__ __forceinline__ float to_tf32(float x) {
    unsigned u;
    asm("cvt.rna.tf32.f32 %0, %1;" : "=r"(u) : "f"(x));
    return __uint_as_float(u);
}

__device__ __forceinline__ float ex2(float x) {
    float r;
    asm("ex2.approx.ftz.f32 %0, %1;" : "=f"(r) : "f"(x));
    return r;
}

__device__ __forceinline__ void mma_tf32(float* c, const unsigned* a, const unsigned* b) {
    asm volatile(
        "mma.sync.aligned.m16n8k8.row.col.f32.tf32.tf32.f32 "
        "{%0,%1,%2,%3},{%4,%5,%6,%7},{%8,%9},{%0,%1,%2,%3};"
        : "+f"(c[0]), "+f"(c[1]), "+f"(c[2]), "+f"(c[3])
        : "r"(a[0]), "r"(a[1]), "r"(a[2]), "r"(a[3]), "r"(b[0]), "r"(b[1]));
}

__device__ __forceinline__ void mma_tf32b(float* c, const unsigned* a, unsigned b0, unsigned b1) {
    asm volatile(
        "mma.sync.aligned.m16n8k8.row.col.f32.tf32.tf32.f32 "
        "{%0,%1,%2,%3},{%4,%5,%6,%7},{%8,%9},{%0,%1,%2,%3};"
        : "+f"(c[0]), "+f"(c[1]), "+f"(c[2]), "+f"(c[3])
        : "r"(a[0]), "r"(a[1]), "r"(a[2]), "r"(a[3]), "r"(b0), "r"(b1));
}

// tf32 fragments via b16 ldmatrix: an 8-row x 4-float block is isomorphic to
// a b16 8x8 tile (lane l gets 4 bytes at row l/4, 4B-col l%4).
__device__ __forceinline__ void ldsm4(unsigned* r, const float* p) {
    unsigned a = (unsigned)__cvta_generic_to_shared(p);
    asm volatile("ldmatrix.sync.aligned.m8n8.x4.shared.b16 {%0,%1,%2,%3}, [%4];"
                 : "=r"(r[0]), "=r"(r[1]), "=r"(r[2]), "=r"(r[3]) : "r"(a));
}

__device__ __forceinline__ void cpa16(float* dst, const float* src) {
    unsigned d = (unsigned)__cvta_generic_to_shared(dst);
    asm volatile("cp.async.cg.shared.global [%0], [%1], 16;" :: "r"(d), "l"(src));
}

// ---------------------------------------------------------------------------
// Prep kernels (run once per launch): bias expansion + weight transposes.
// ---------------------------------------------------------------------------
__global__ void bias_expand(const float* __restrict__ bt) {
    const int kt = threadIdx.x, qt = blockIdx.x, hd = blockIdx.y;
    const int qy = qt >> 4, qx = qt & 15, ky = kt >> 4, kx = kt & 15;
    const int rel = (qy - ky + 15) * 31 + (qx - kx + 15);
    g_bias[(hd << 16) + (qt << 8) + kt] = bt[rel * 8 + hd] * 1.4426950408889634f;
}

__global__ void prep_gemm_w(const float* __restrict__ W, int slot) {
    const int idx = blockIdx.x * 256 + threadIdx.x;   // 65536
    const int n = idx >> 8, k = idx & 255;
    g_wt[slot * 66560 + n * 260 + k] = to_tf32(W[k * 256 + n]);
}

__global__ void prep_conv_w(const float* __restrict__ Wc) {
    const int idx = blockIdx.x * 256 + threadIdx.x;   // 409600
    const int k = idx & 31;
    const int tap = (idx >> 5) % 25;
    const int ocg = idx / 800;                        // g*64 + oc
    const int g = ocg >> 6, oc = ocg & 63;
    g_wct[ocg * 800 + tap * 32 + k] = to_tf32(Wc[(tap * 32 + k) * 512 + g * 64 + oc]);
}

// ---------------------------------------------------------------------------
// Conv 5x5 grouped (pad 2, groups=8) as implicit GEMM on tensor cores.
// TWO taps per pipeline round (13 rounds, halved barrier count), 3-slot ring
// of tap-pairs via cp.async. Weights pre-transposed/tf32 in g_wct.
// K scattered as [key][d]; V scattered TRANSPOSED as [d][key].
// ---------------------------------------------------------------------------
#define CONV_PATCH_FL 14400   // 20*20*36
#define CONV_WTAP_FL  2304    // one tap: 64 oc * 36
#define CONV_WPAIR_FL (2*CONV_WTAP_FL)
#define CONV_SMEM_B   ((CONV_PATCH_FL + 3*CONV_WPAIR_FL) * 4)   // 112896 B

__global__ __launch_bounds__(256, 2) void convkv_mma(const float* __restrict__ X,
                                                     const float* __restrict__ bias) {
    extern __shared__ float smem[];
    float* patch = smem;
    float* wring = smem + CONV_PATCH_FL;

    const int tid = threadIdx.x;
    const int lane = tid & 31, warp = tid >> 5;
    const int wm = warp & 3, wn = warp >> 2;
    const int g8 = lane >> 3, r8 = lane & 7;
    const int tile = blockIdx.x;
    const int ty0 = (tile >> 3) * 16, tx0 = (tile & 7) * 16;
    const int b = blockIdx.y >> 3, g = blockIdx.y & 7;

    const float* wsrc = g_wct + (g * 64) * 800;

    // Issue tap-pairs 0 and 1 into ring slots 0,1 (taps 0..3 all valid)
#pragma unroll
    for (int pr = 0; pr < 2; pr++) {
#pragma unroll
        for (int c = 0; c < 4; c++) {
            const int idx = c * 256 + tid;              // 0..1023
            const int t2 = idx >> 9, rest = idx & 511;
            const int row = rest >> 3, seg = (rest & 7) * 4;
            cpa16(wring + pr * CONV_WPAIR_FL + t2 * CONV_WTAP_FL + row * 36 + seg,
                  wsrc + row * 800 + (pr * 2 + t2) * 32 + seg);
        }
        asm volatile("cp.async.commit_group;");
    }

    // Stage input patch (zero-padded), converted to tf32
    for (int p = tid; p < 400; p += 256) {
        int py = p / 20, px = p - py * 20;
        int gy = ty0 + py - 2, gx = tx0 + px - 2;
        bool ok = (gy >= 0 && gy < 128 && gx >= 0 && gx < 128);
        const float4* src = (const float4*)(X + ((b * 128 + gy) * 128 + gx) * 256 + g * 32);
#pragma unroll
        for (int c8 = 0; c8 < 8; c8++) {
            float4 v = ok ? src[c8] : make_float4(0.f, 0.f, 0.f, 0.f);
            float4 w = make_float4(to_tf32(v.x), to_tf32(v.y), to_tf32(v.z), to_tf32(v.w));
            *(float4*)&patch[p * 36 + c8 * 4] = w;
        }
    }

    float acc[4][4][4] = {};

#pragma unroll 1
    for (int rnd = 0; rnd < 13; rnd++) {
        if (rnd < 11) asm volatile("cp.async.wait_group 1;");
        else          asm volatile("cp.async.wait_group 0;");
        __syncthreads();   // pair rnd ready (+patch on first iter); slot (rnd+2)%3 free
        if (rnd < 11) {
            const int np = rnd + 2;                     // pair index to issue
            float* dst = wring + (np % 3) * CONV_WPAIR_FL;
#pragma unroll
            for (int c = 0; c < 4; c++) {
                const int idx = c * 256 + tid;
                const int t2 = idx >> 9, rest = idx & 511;
                const int row = rest >> 3, seg = (rest & 7) * 4;
                const int tap = np * 2 + t2;
                if (tap < 25)
                    cpa16(dst + t2 * CONV_WTAP_FL + row * 36 + seg,
                          wsrc + row * 800 + tap * 32 + seg);
            }
            asm volatile("cp.async.commit_group;");
        } else {
            asm volatile("cp.async.commit_group;");     // keep group count aligned
        }

#pragma unroll
        for (int t2 = 0; t2 < 2; t2++) {
            const int tap = rnd * 2 + t2;
            if (tap < 25) {
                const int ky = tap / 5, kx = tap - ky * 5;
                const float* wcur = wring + (rnd % 3) * CONV_WPAIR_FL + t2 * CONV_WTAP_FL;
#pragma unroll
                for (int kc = 0; kc < 4; kc++) {
                    unsigned a[4][4];
#pragma unroll
                    for (int i = 0; i < 4; i++) {
                        const float* ap = patch
                            + ((wm * 4 + i + ky) * 20 + (g8 & 1) * 8 + r8 + kx) * 36
                            + kc * 8 + (g8 >> 1) * 4;
                        ldsm4(a[i], ap);
                    }
                    unsigned bfa[4], bfb[4];
                    ldsm4(bfa, wcur + (wn * 32 + g8 * 8 + r8) * 36 + kc * 8);
                    ldsm4(bfb, wcur + (wn * 32 + g8 * 8 + r8) * 36 + kc * 8 + 4);
#pragma unroll
                    for (int j = 0; j < 4; j++)
#pragma unroll
                        for (int i = 0; i < 4; i++) mma_tf32b(acc[i][j], a[i], bfa[j], bfb[j]);
                }
            }
        }
    }

    const int win = b * 64 + (tile >> 3) * 8 + (tile & 7);
    const int head = (g & 3) * 2 + wn;
    if (g < 4) {   // K: [key][d]
        float* base = g_k + ((win * 8 + head) * 256) * 32;
#pragma unroll
        for (int i = 0; i < 4; i++) {
            const int p0 = wm * 64 + i * 16 + (lane >> 2);
#pragma unroll
            for (int j = 0; j < 4; j++) {
                const int col = wn * 32 + j * 8 + (lane & 3) * 2;
                const int d = col & 31;
                float b0 = bias[g * 64 + col], b1 = bias[g * 64 + col + 1];
                *(float2*)(base + p0 * 32 + d) =
                    make_float2(to_tf32(acc[i][j][0] + b0), to_tf32(acc[i][j][1] + b1));
                *(float2*)(base + (p0 + 8) * 32 + d) =
                    make_float2(to_tf32(acc[i][j][2] + b0), to_tf32(acc[i][j][3] + b1));
            }
        }
    } else {       // V transposed: [d][key]
        float* base = g_v + ((win * 8 + head) * 32) * 256;
#pragma unroll
        for (int i = 0; i < 4; i++) {
            const int p0 = wm * 64 + i * 16 + (lane >> 2);
#pragma unroll
            for (int j = 0; j < 4; j++) {
                const int col = wn * 32 + j * 8 + (lane & 3) * 2;
                const int d0 = col & 31;
                float b0 = bias[g * 64 + col], b1 = bias[g * 64 + col + 1];
                base[d0 * 256 + p0]           = to_tf32(acc[i][j][0] + b0);
                base[(d0 + 1) * 256 + p0]     = to_tf32(acc[i][j][1] + b1);
                base[d0 * 256 + p0 + 8]       = to_tf32(acc[i][j][2] + b0);
                base[(d0 + 1) * 256 + p0 + 8] = to_tf32(acc[i][j][3] + b1);
            }
        }
    }
}

// ---------------------------------------------------------------------------
// tf32 GEMM: MODE 0 qproj (x_wsa fp32 -> LDG/cvt/STS A-path),
//            MODE 1 outproj (g_o is pre-rounded tf32 -> pure cp.async A-path)
// B pre-transposed/tf32 in g_wt -> cp.async ring + ldsm fragments.
// ---------------------------------------------------------------------------
#define GEMM_A_FL 4608    // 128*36
#define GEMM_B_FL 2304    // 64 n * 36
#define GEMM_SLOT_FL (GEMM_A_FL + GEMM_B_FL)
#define GEMM_SMEM_B0 ((2*GEMM_A_FL + 3*GEMM_B_FL) * 4)
#define GEMM_SMEM_B1 ((3*GEMM_SLOT_FL) * 4)

template <int MODE>
__global__ __launch_bounds__(256, 2) void gemm_mma(const float* __restrict__ Aparam,
                                                   const float* __restrict__ bias,
                                                   const float* __restrict__ rz,
                                                   float* __restrict__ out) {
    extern __shared__ float smem[];

    const float* A = (MODE == 1) ? (const float*)g_o : Aparam;
    const float* wt = g_wt + MODE * 66560;

    const int tid = threadIdx.x;
    const int lane = tid & 31, warp = tid >> 5;
    const int wm = warp & 3, wn = warp >> 2;
    const int g8 = lane >> 3, r8 = lane & 7;
    const int m0 = blockIdx.x * 128;
    const int n0 = blockIdx.y * 64;

    const int arow = tid >> 1, akoff = (tid & 1) * 16;

    // Prologue: issue chunks 0,1
#pragma unroll
    for (int c0 = 0; c0 < 2; c0++) {
        if (MODE == 1) {
            float* sa = smem + c0 * GEMM_SLOT_FL;
#pragma unroll
            for (int c = 0; c < 4; c++) {
                const int idx = c * 256 + tid;          // 0..1023
                cpa16(sa + (idx >> 3) * 36 + (idx & 7) * 4,
                      A + (m0 + (idx >> 3)) * 256 + c0 * 32 + (idx & 7) * 4);
            }
            float* sb = sa + GEMM_A_FL;
#pragma unroll
            for (int c = 0; c < 2; c++) {
                const int idx = c * 256 + tid;
                cpa16(sb + (idx >> 3) * 36 + (idx & 7) * 4,
                      wt + (n0 + (idx >> 3)) * 260 + c0 * 32 + (idx & 7) * 4);
            }
        } else {
            float* sb = smem + 2 * GEMM_A_FL + c0 * GEMM_B_FL;
#pragma unroll
            for (int c = 0; c < 2; c++) {
                const int idx = c * 256 + tid;
                cpa16(sb + (idx >> 3) * 36 + (idx & 7) * 4,
                      wt + (n0 + (idx >> 3)) * 260 + c0 * 32 + (idx & 7) * 4);
            }
        }
        asm volatile("cp.async.commit_group;");
    }

    if (MODE == 0) {   // A chunk 0 -> abuf 0 (LDG + cvt + STS)
        const float4* ga = (const float4*)(A + (m0 + arow) * 256 + akoff);
        float* da = smem + arow * 36 + akoff;
#pragma unroll
        for (int c4 = 0; c4 < 4; c4++) {
            float4 v = ga[c4];
            *(float4*)(da + c4 * 4) = make_float4(to_tf32(v.x), to_tf32(v.y), to_tf32(v.z), to_tf32(v.w));
        }
    }

    float acc[2][4][4] = {};

#pragma unroll 1
    for (int kt = 0; kt < 8; kt++) {
        float4 pa[4];
        if (MODE == 0 && kt < 7) {
            const float4* ga = (const float4*)(A + (m0 + arow) * 256 + (kt + 1) * 32 + akoff);
#pragma unroll
            for (int c4 = 0; c4 < 4; c4++) pa[c4] = ga[c4];
        }
        if (kt < 6) asm volatile("cp.async.wait_group 1;");
        else        asm volatile("cp.async.wait_group 0;");
        __syncthreads();
        if (kt < 6) {
            const int nt = kt + 2;
            if (MODE == 1) {
                float* sa = smem + (nt % 3) * GEMM_SLOT_FL;
#pragma unroll
                for (int c = 0; c < 4; c++) {
                    const int idx = c * 256 + tid;
                    cpa16(sa + (idx >> 3) * 36 + (idx & 7) * 4,
                          A + (m0 + (idx >> 3)) * 256 + nt * 32 + (idx & 7) * 4);
                }
                float* sb = sa + GEMM_A_FL;
#pragma unroll
                for (int c = 0; c < 2; c++) {
                    const int idx = c * 256 + tid;
                    cpa16(sb + (idx >> 3) * 36 + (idx & 7) * 4,
                          wt + (n0 + (idx >> 3)) * 260 + nt * 32 + (idx & 7) * 4);
                }
            } else {
                float* sb = smem + 2 * GEMM_A_FL + (nt % 3) * GEMM_B_FL;
#pragma unroll
                for (int c = 0; c < 2; c++) {
                    const int idx = c * 256 + tid;
                    cpa16(sb + (idx >> 3) * 36 + (idx & 7) * 4,
                          wt + (n0 + (idx >> 3)) * 260 + nt * 32 + (idx & 7) * 4);
                }
            }
            asm volatile("cp.async.commit_group;");
        }
        const float* acur = (MODE == 1) ? (smem + (kt % 3) * GEMM_SLOT_FL)
                                        : (smem + (kt & 1) * GEMM_A_FL);
        const float* bcur = (MODE == 1) ? (smem + (kt % 3) * GEMM_SLOT_FL + GEMM_A_FL)
                                        : (smem + 2 * GEMM_A_FL + (kt % 3) * GEMM_B_FL);
#pragma unroll
        for (int kc = 0; kc < 4; kc++) {
            unsigned a[2][4];
#pragma unroll
            for (int i = 0; i < 2; i++) {
                const float* ap = acur + (wm * 32 + i * 16 + (g8 & 1) * 8 + r8) * 36
                                  + kc * 8 + (g8 >> 1) * 4;
                ldsm4(a[i], ap);
            }
            unsigned bfa[4], bfb[4];
            ldsm4(bfa, bcur + (wn * 32 + g8 * 8 + r8) * 36 + kc * 8);
            ldsm4(bfb, bcur + (wn * 32 + g8 * 8 + r8) * 36 + kc * 8 + 4);
#pragma unroll
            for (int j = 0; j < 4; j++)
#pragma unroll
                for (int i = 0; i < 2; i++) mma_tf32b(acc[i][j], a[i], bfa[j], bfb[j]);
        }
        if (MODE == 0 && kt < 7) {
            float* da = smem + ((kt + 1) & 1) * GEMM_A_FL + arow * 36 + akoff;
#pragma unroll
            for (int c4 = 0; c4 < 4; c4++)
                *(float4*)(da + c4 * 4) = make_float4(to_tf32(pa[c4].x), to_tf32(pa[c4].y),
                                                      to_tf32(pa[c4].z), to_tf32(pa[c4].w));
        }
    }

    const float scale = 0.17677669529663687f * 1.4426950408889634f;  // qproj folds log2(e)
    const float r = (MODE == 1) ? rz[0] : 0.f;
#pragma unroll
    for (int i = 0; i < 2; i++) {
        const int m = m0 + wm * 32 + i * 16 + (lane >> 2);
#pragma unroll
        for (int j = 0; j < 4; j++) {
            const int col = n0 + wn * 32 + j * 8 + (lane & 3) * 2;
            const float b0 = bias[col], b1 = bias[col + 1];
            if (MODE == 0) {
                const int bi = m >> 14, rr = (m >> 7) & 127, cc = m & 127;
                const int win = bi * 64 + ((rr >> 4) << 3) + (cc >> 4);
                const int t = (rr & 15) * 16 + (cc & 15);
                const int head = col >> 5, d = col & 31;
                float* p = g_q + ((win * 8 + head) * 256 + t) * 32 + d;
                *(float2*)p = make_float2(to_tf32((acc[i][j][0] + b0) * scale),
                                          to_tf32((acc[i][j][1] + b1) * scale));
                *(float2*)(p + 8 * 32) = make_float2(to_tf32((acc[i][j][2] + b0) * scale),
                                                     to_tf32((acc[i][j][3] + b1) * scale));
            } else {
                float* p = out + m * 256 + col;
                *(float2*)p = make_float2(r * (acc[i][j][0] + b0), r * (acc[i][j][1] + b1));
                *(float2*)(p + 8 * 256) = make_float2(r * (acc[i][j][2] + b0), r * (acc[i][j][3] + b1));
            }
        }
    }
}

// ---------------------------------------------------------------------------
// Tensor-core flash attention (R7 structure; epilogue now writes tf32-rounded
// g_o so outproj can stream A via cp.async with identical numerics).
// ---------------------------------------------------------------------------
#define ATT_QS 9216            // 256*36
#define ATT_KS (3*1152)        // 3 stages * 32*36
#define ATT_VS (3*1152)        // 3 stages * 32 d * 36 (keys pitch)
#define ATT_PS 9216            // 8 warps * 32*36
#define ATT_SMEM_B ((ATT_QS + ATT_KS + ATT_VS + ATT_PS) * 4)

__global__ __launch_bounds__(256, 2) void attn_mma() {
    extern __shared__ float sm[];
    float* Qs = sm;
    float* Ks = sm + ATT_QS;
    float* Vs = Ks + ATT_KS;
    float* Ps = Vs + ATT_VS;

    const int win = blockIdx.x, hd = blockIdx.y;
    const int tid = threadIdx.x;
    const int lane = tid & 31, warp = tid >> 5;
    const int q = lane >> 2, t = lane & 3;
    const int g8 = lane >> 3, r8 = lane & 7;
    const int wb = warp * 32;
    float* Pw = Ps + warp * 1152;

    const float* qb = g_q + (win * 8 + hd) * 8192;
    const float* kb = g_k + (win * 8 + hd) * 8192;
    const float* vtb = g_v + (win * 8 + hd) * 8192;   // [32 d][256 key]
    const float* bb = g_bias + (hd << 16);

    // Stage Q into smem (pitch 36)
    for (int i = tid; i < 2048; i += 256) {
        float4 v = ((const float4*)qb)[i];
        *(float4*)&Qs[(i >> 3) * 36 + (i & 7) * 4] = v;
    }
    // cp.async chunks 0 and 1. K: [key][d]; V: [d][key] slices
    {
        const int row = tid >> 3, seg = (tid & 7) * 4;
#pragma unroll
        for (int c = 0; c < 2; c++) {
            cpa16(Ks + c * 1152 + row * 36 + seg, kb + c * 1024 + tid * 4);
            cpa16(Vs + c * 1152 + row * 36 + seg, vtb + row * 256 + c * 32 + seg);
            asm volatile("cp.async.commit_group;");
        }
    }
    __syncthreads();

    // Q fragments -> registers (once)
    unsigned qa[2][4][4];
#pragma unroll
    for (int mt = 0; mt < 2; mt++)
#pragma unroll
        for (int kc = 0; kc < 4; kc++)
            ldsm4(qa[mt][kc], Qs + (wb + mt * 16 + (g8 & 1) * 8 + r8) * 36 + kc * 8 + (g8 >> 1) * 4);

    float o[2][4][4] = {};
    float mrow[2][2] = {{-1e30f, -1e30f}, {-1e30f, -1e30f}};
    float lrow[2][2] = {};   // per-lane partials, reduced in epilogue

#pragma unroll 1
    for (int sb = 0; sb < 8; sb++) {
        asm volatile("cp.async.wait_group 1;");
        __syncthreads();

        if (sb < 6) {
            const int slot = (sb + 2) % 3;
            const int row = tid >> 3, seg = (tid & 7) * 4;
            cpa16(Ks + slot * 1152 + row * 36 + seg, kb + (sb + 2) * 1024 + tid * 4);
            cpa16(Vs + slot * 1152 + row * 36 + seg, vtb + row * 256 + (sb + 2) * 32 + seg);
        }
        asm volatile("cp.async.commit_group;");

        const float* Kb = Ks + (sb % 3) * 1152;
        const float* Vb = Vs + (sb % 3) * 1152;

        // ---- S = Q K^T for BOTH m-tiles, bias as accumulator init ----
        float s[2][4][4];
#pragma unroll
        for (int mt = 0; mt < 2; mt++) {
            const float* br0 = bb + (wb + mt * 16 + q) * 256 + sb * 32 + t * 2;
            const float* br1 = br0 + 8 * 256;
#pragma unroll
            for (int nt = 0; nt < 4; nt++) {
                float2 b0 = *(const float2*)(br0 + nt * 8);
                float2 b1 = *(const float2*)(br1 + nt * 8);
                s[mt][nt][0] = b0.x; s[mt][nt][1] = b0.y;
                s[mt][nt][2] = b1.x; s[mt][nt][3] = b1.y;
            }
        }
#pragma unroll
        for (int kc = 0; kc < 4; kc++) {
#pragma unroll
            for (int pr = 0; pr < 2; pr++) {
                unsigned kf[4];
                ldsm4(kf, Kb + (pr * 16 + (g8 >> 1) * 8 + r8) * 36 + kc * 8 + (g8 & 1) * 4);
                mma_tf32(s[0][pr * 2 + 0], qa[0][kc], &kf[0]);
                mma_tf32(s[0][pr * 2 + 1], qa[0][kc], &kf[2]);
                mma_tf32(s[1][pr * 2 + 0], qa[1][kc], &kf[0]);
                mma_tf32(s[1][pr * 2 + 1], qa[1][kc], &kf[2]);
            }
        }

        // ---- online softmax per m-tile; raw P -> warp-private smem ----
#pragma unroll
        for (int mt = 0; mt < 2; mt++) {
            float mx0 = fmaxf(fmaxf(s[mt][0][0], s[mt][0][1]), fmaxf(s[mt][1][0], s[mt][1][1]));
            float mx1 = fmaxf(fmaxf(s[mt][0][2], s[mt][0][3]), fmaxf(s[mt][1][2], s[mt][1][3]));
            mx0 = fmaxf(mx0, fmaxf(fmaxf(s[mt][2][0], s[mt][2][1]), fmaxf(s[mt][3][0], s[mt][3][1])));
            mx1 = fmaxf(mx1, fmaxf(fmaxf(s[mt][2][2], s[mt][2][3]), fmaxf(s[mt][3][2], s[mt][3][3])));
            mx0 = fmaxf(mx0, __shfl_xor_sync(0xffffffff, mx0, 1));
            mx0 = fmaxf(mx0, __shfl_xor_sync(0xffffffff, mx0, 2));
            mx1 = fmaxf(mx1, __shfl_xor_sync(0xffffffff, mx1, 1));
            mx1 = fmaxf(mx1, __shfl_xor_sync(0xffffffff, mx1, 2));
            const float mn0 = fmaxf(mrow[mt][0], mx0);
            const float mn1 = fmaxf(mrow[mt][1], mx1);
            const float cor0 = ex2(mrow[mt][0] - mn0);
            const float cor1 = ex2(mrow[mt][1] - mn1);
            mrow[mt][0] = mn0; mrow[mt][1] = mn1;
#pragma unroll
            for (int dn = 0; dn < 4; dn++) {
                o[mt][dn][0] *= cor0; o[mt][dn][1] *= cor0;
                o[mt][dn][2] *= cor1; o[mt][dn][3] *= cor1;
            }
            float sm0 = 0.f, sm1 = 0.f;
#pragma unroll
            for (int nt = 0; nt < 4; nt++) {
                float p0 = ex2(s[mt][nt][0] - mn0);
                float p1 = ex2(s[mt][nt][1] - mn0);
                float p2 = ex2(s[mt][nt][2] - mn1);
                float p3 = ex2(s[mt][nt][3] - mn1);
                sm0 += p0 + p1; sm1 += p2 + p3;
                *(float2*)&Pw[(mt * 16 + q) * 36 + nt * 8 + 2 * t] = make_float2(p0, p1);
                *(float2*)&Pw[(mt * 16 + q + 8) * 36 + nt * 8 + 2 * t] = make_float2(p2, p3);
            }
            lrow[mt][0] = lrow[mt][0] * cor0 + sm0;
            lrow[mt][1] = lrow[mt][1] * cor1 + sm1;
        }
        __syncwarp();

        // ---- O += P V : P and V fragments via ldmatrix ----
#pragma unroll
        for (int kk = 0; kk < 4; kk++) {
            unsigned pa[2][4];
            ldsm4(pa[0], Pw + ((g8 & 1) * 8 + r8) * 36 + kk * 8 + (g8 >> 1) * 4);
            ldsm4(pa[1], Pw + (16 + (g8 & 1) * 8 + r8) * 36 + kk * 8 + (g8 >> 1) * 4);
            unsigned vf0[4], vf1[4];
            ldsm4(vf0, Vb + ((g8 >> 1) * 8 + r8) * 36 + kk * 8 + (g8 & 1) * 4);
            ldsm4(vf1, Vb + ((2 + (g8 >> 1)) * 8 + r8) * 36 + kk * 8 + (g8 & 1) * 4);
            mma_tf32(o[0][0], pa[0], &vf0[0]);
            mma_tf32(o[0][1], pa[0], &vf0[2]);
            mma_tf32(o[0][2], pa[0], &vf1[0]);
            mma_tf32(o[0][3], pa[0], &vf1[2]);
            mma_tf32(o[1][0], pa[1], &vf0[0]);
            mma_tf32(o[1][1], pa[1], &vf0[2]);
            mma_tf32(o[1][2], pa[1], &vf1[0]);
            mma_tf32(o[1][3], pa[1], &vf1[2]);
        }
        __syncwarp();
    }

    // Epilogue: reduce l partials, normalize, write tf32-rounded (B,H,W,C)
    const int bimg = win >> 6, wh = (win >> 3) & 7, ww = win & 7;
#pragma unroll
    for (int mt = 0; mt < 2; mt++) {
        float l0 = lrow[mt][0], l1 = lrow[mt][1];
        l0 += __shfl_xor_sync(0xffffffff, l0, 1);
        l0 += __shfl_xor_sync(0xffffffff, l0, 2);
        l1 += __shfl_xor_sync(0xffffffff, l1, 1);
        l1 += __shfl_xor_sync(0xffffffff, l1, 2);
        const float inv0 = 1.f / l0;
        const float inv1 = 1.f / l1;
        const int tk0 = wb + mt * 16 + q;
#pragma unroll
        for (int half = 0; half < 2; half++) {
            const int tk = tk0 + half * 8;
            const float inv = half ? inv1 : inv0;
            const int gr = wh * 16 + (tk >> 4), gc = ww * 16 + (tk & 15);
            float* op = g_o + ((bimg * 128 + gr) * 128 + gc) * 256 + hd * 32;
#pragma unroll
            for (int dn = 0; dn < 4; dn++) {
                float a = to_tf32(o[mt][dn][half * 2] * inv);
                float b = to_tf32(o[mt][dn][half * 2 + 1] * inv);
                *(float2*)(op + dn * 8 + t * 2) = make_float2(a, b);
            }
        }
    }
}

// ---------------------------------------------------------------------------
extern "C" void kernel_launch(void* const* d_in, const int* in_sizes, int n_in,
                              void* d_out, int out_size) {
    (void)in_sizes; (void)n_in; (void)out_size;
    const float* x_wsa      = (const float*)d_in[0];
    const float* x_original = (const float*)d_in[1];
    const float* q_w        = (const float*)d_in[2];
    const float* q_b        = (const float*)d_in[3];
    const float* kv_w       = (const float*)d_in[4];
    const float* kv_b       = (const float*)d_in[5];
    const float* out_w      = (const float*)d_in[6];
    const float* out_b      = (const float*)d_in[7];
    const float* bias_table = (const float*)d_in[8];
    const float* rezero     = (const float*)d_in[9];
    float* out = (float*)d_out;

    cudaFuncSetAttribute(convkv_mma, cudaFuncAttributeMaxDynamicSharedMemorySize, CONV_SMEM_B);
    cudaFuncSetAttribute(gemm_mma<0>, cudaFuncAttributeMaxDynamicSharedMemorySize, GEMM_SMEM_B0);
    cudaFuncSetAttribute(gemm_mma<1>, cudaFuncAttributeMaxDynamicSharedMemorySize, GEMM_SMEM_B1);
    cudaFuncSetAttribute(attn_mma, cudaFuncAttributeMaxDynamicSharedMemorySize, ATT_SMEM_B);

    bias_expand<<<dim3(256, 8), 256>>>(bias_table);
    prep_gemm_w<<<256, 256>>>(q_w, 0);
    prep_gemm_w<<<256, 256>>>(out_w, 1);
    prep_conv_w<<<1600, 256>>>(kv_w);

    gemm_mma<0><<<dim3(512, 4), 256, GEMM_SMEM_B0>>>(x_wsa, q_b, nullptr, nullptr);
    convkv_mma<<<dim3(64, 32), 256, CONV_SMEM_B>>>(x_original, kv_b);
    attn_mma<<<dim3(256, 8), 256, ATT_SMEM_B>>>();
    gemm_mma<1><<<dim3(512, 4), 256, GEMM_SMEM_B1>>>(nullptr, out_b, rezero, out);
}

// round 11
// speedup vs baseline: 1.5155x; 1.0048x over previous
#include <cuda_runtime.h>

// B=4, H=W=128, C=256, heads=8, d=32, win=16 -> 256 windows x 256 tokens
// g_q: [win][head][tok][d]; g_k: [win][head][key][d]; g_v TRANSPOSED: [win][head][d][key]
__device__ float g_q[16777216];
__device__ float g_k[16777216];
__device__ float g_v[16777216];
__device__ float g_o[16777216];
__device__ float g_bias[524288];   // [head][256 q][256 k], pre-scaled by log2(e)
__device__ float g_wt[133120];     // 2 x [256 n][260 pitch k]: tf32(qw^T), tf32(ow^T)
__device__ float g_wct[409600];    // conv weights: [(g*64+oc)][25 taps * 32 k] pitch 800

__device__ __forceinline__ float to_tf32(float x) {
    unsigned u;
    asm("cvt.rna.tf32.f32 %0, %1;" : "=r"(u) : "f"(x));
    return __uint_as_float(u);
}

__device__ __forceinline__ float ex2(float x) {
    float r;
    asm("ex2.approx.ftz.f32 %0, %1;" : "=f"(r) : "f"(x));
    return r;
}

__device__ __forceinline__ void mma_tf32(float* c, const unsigned* a, const unsigned* b) {
    asm volatile(
        "mma.sync.aligned.m16n8k8.row.col.f32.tf32.tf32.f32 "
        "{%0,%1,%2,%3},{%4,%5,%6,%7},{%8,%9},{%0,%1,%2,%3};"
        : "+f"(c[0]), "+f"(c[1]), "+f"(c[2]), "+f"(c[3])
        : "r"(a[0]), "r"(a[1]), "r"(a[2]), "r"(a[3]), "r"(b[0]), "r"(b[1]));
}

__device__ __forceinline__ void mma_tf32b(float* c, const unsigned* a, unsigned b0, unsigned b1) {
    asm volatile(
        "mma.sync.aligned.m16n8k8.row.col.f32.tf32.tf32.f32 "
        "{%0,%1,%2,%3},{%4,%5,%6,%7},{%8,%9},{%0,%1,%2,%3};"
        : "+f"(c[0]), "+f"(c[1]), "+f"(c[2]), "+f"(c[3])
        : "r"(a[0]), "r"(a[1]), "r"(a[2]), "r"(a[3]), "r"(b0), "r"(b1));
}

// tf32 fragments via b16 ldmatrix: an 8-row x 4-float block is isomorphic to
// a b16 8x8 tile (lane l gets 4 bytes at row l/4, 4B-col l%4).
__device__ __forceinline__ void ldsm4(unsigned* r, const float* p) {
    unsigned a = (unsigned)__cvta_generic_to_shared(p);
    asm volatile("ldmatrix.sync.aligned.m8n8.x4.shared.b16 {%0,%1,%2,%3}, [%4];"
                 : "=r"(r[0]), "=r"(r[1]), "=r"(r[2]), "=r"(r[3]) : "r"(a));
}

__device__ __forceinline__ void cpa16(float* dst, const float* src) {
    unsigned d = (unsigned)__cvta_generic_to_shared(dst);
    asm volatile("cp.async.cg.shared.global [%0], [%1], 16;" :: "r"(d), "l"(src));
}

// ---------------------------------------------------------------------------
// Prep: ONE kernel for bias expansion + both GEMM weight transposes,
// plus a separate conv-weight transpose (kept separate so convkv_mma can be
// launch #4 for ncu capture).
// ---------------------------------------------------------------------------
__global__ void prep_misc(const float* __restrict__ bt,
                          const float* __restrict__ qw,
                          const float* __restrict__ ow) {
    const int idx = blockIdx.x * 256 + threadIdx.x;
    if (idx < 524288) {
        const int hd = idx >> 16, qt = (idx >> 8) & 255, kt = idx & 255;
        const int qy = qt >> 4, qx = qt & 15, ky = kt >> 4, kx = kt & 15;
        const int rel = (qy - ky + 15) * 31 + (qx - kx + 15);
        g_bias[idx] = bt[rel * 8 + hd] * 1.4426950408889634f;
    } else {
        const int i2 = idx - 524288;           // 0..131071
        const int slot = i2 >> 16;             // 0: qw, 1: ow
        const int r = i2 & 65535;
        const int n = r >> 8, k = r & 255;
        const float* W = slot ? ow : qw;
        g_wt[slot * 66560 + n * 260 + k] = to_tf32(W[k * 256 + n]);
    }
}

__global__ void prep_conv_w(const float* __restrict__ Wc) {
    const int idx = blockIdx.x * 256 + threadIdx.x;   // 409600
    const int k = idx & 31;
    const int tap = (idx >> 5) % 25;
    const int ocg = idx / 800;                        // g*64 + oc
    const int g = ocg >> 6, oc = ocg & 63;
    g_wct[ocg * 800 + tap * 32 + k] = to_tf32(Wc[(tap * 32 + k) * 512 + g * 64 + oc]);
}

// ---------------------------------------------------------------------------
// Conv 5x5 grouped (pad 2, groups=8) as implicit GEMM on tensor cores.
// TWO taps per pipeline round (13 rounds), 3-slot ring of tap-pairs via
// cp.async. Weights pre-transposed/tf32 in g_wct.
// K scattered as [key][d]; V scattered TRANSPOSED as [d][key].
// ---------------------------------------------------------------------------
#define CONV_PATCH_FL 14400   // 20*20*36
#define CONV_WTAP_FL  2304    // one tap: 64 oc * 36
#define CONV_WPAIR_FL (2*CONV_WTAP_FL)
#define CONV_SMEM_B   ((CONV_PATCH_FL + 3*CONV_WPAIR_FL) * 4)   // 112896 B

__global__ __launch_bounds__(256, 2) void convkv_mma(const float* __restrict__ X,
                                                     const float* __restrict__ bias) {
    extern __shared__ float smem[];
    float* patch = smem;
    float* wring = smem + CONV_PATCH_FL;

    const int tid = threadIdx.x;
    const int lane = tid & 31, warp = tid >> 5;
    const int wm = warp & 3, wn = warp >> 2;
    const int g8 = lane >> 3, r8 = lane & 7;
    const int tile = blockIdx.x;
    const int ty0 = (tile >> 3) * 16, tx0 = (tile & 7) * 16;
    const int b = blockIdx.y >> 3, g = blockIdx.y & 7;

    const float* wsrc = g_wct + (g * 64) * 800;

    // Issue tap-pairs 0 and 1 into ring slots 0,1 (taps 0..3 all valid)
#pragma unroll
    for (int pr = 0; pr < 2; pr++) {
#pragma unroll
        for (int c = 0; c < 4; c++) {
            const int idx = c * 256 + tid;              // 0..1023
            const int t2 = idx >> 9, rest = idx & 511;
            const int row = rest >> 3, seg = (rest & 7) * 4;
            cpa16(wring + pr * CONV_WPAIR_FL + t2 * CONV_WTAP_FL + row * 36 + seg,
                  wsrc + row * 800 + (pr * 2 + t2) * 32 + seg);
        }
        asm volatile("cp.async.commit_group;");
    }

    // Stage input patch (zero-padded), converted to tf32
    for (int p = tid; p < 400; p += 256) {
        int py = p / 20, px = p - py * 20;
        int gy = ty0 + py - 2, gx = tx0 + px - 2;
        bool ok = (gy >= 0 && gy < 128 && gx >= 0 && gx < 128);
        const float4* src = (const float4*)(X + ((b * 128 + gy) * 128 + gx) * 256 + g * 32);
#pragma unroll
        for (int c8 = 0; c8 < 8; c8++) {
            float4 v = ok ? src[c8] : make_float4(0.f, 0.f, 0.f, 0.f);
            float4 w = make_float4(to_tf32(v.x), to_tf32(v.y), to_tf32(v.z), to_tf32(v.w));
            *(float4*)&patch[p * 36 + c8 * 4] = w;
        }
    }

    float acc[4][4][4] = {};

#pragma unroll 1
    for (int rnd = 0; rnd < 13; rnd++) {
        if (rnd < 11) asm volatile("cp.async.wait_group 1;");
        else          asm volatile("cp.async.wait_group 0;");
        __syncthreads();   // pair rnd ready (+patch on first iter); slot (rnd+2)%3 free
        if (rnd < 11) {
            const int np = rnd + 2;                     // pair index to issue
            float* dst = wring + (np % 3) * CONV_WPAIR_FL;
#pragma unroll
            for (int c = 0; c < 4; c++) {
                const int idx = c * 256 + tid;
                const int t2 = idx >> 9, rest = idx & 511;
                const int row = rest >> 3, seg = (rest & 7) * 4;
                const int tap = np * 2 + t2;
                if (tap < 25)
                    cpa16(dst + t2 * CONV_WTAP_FL + row * 36 + seg,
                          wsrc + row * 800 + tap * 32 + seg);
            }
            asm volatile("cp.async.commit_group;");
        } else {
            asm volatile("cp.async.commit_group;");     // keep group count aligned
        }

#pragma unroll
        for (int t2 = 0; t2 < 2; t2++) {
            const int tap = rnd * 2 + t2;
            if (tap < 25) {
                const int ky = tap / 5, kx = tap - ky * 5;
                const float* wcur = wring + (rnd % 3) * CONV_WPAIR_FL + t2 * CONV_WTAP_FL;
#pragma unroll
                for (int kc = 0; kc < 4; kc++) {
                    unsigned a[4][4];
#pragma unroll
                    for (int i = 0; i < 4; i++) {
                        const float* ap = patch
                            + ((wm * 4 + i + ky) * 20 + (g8 & 1) * 8 + r8 + kx) * 36
                            + kc * 8 + (g8 >> 1) * 4;
                        ldsm4(a[i], ap);
                    }
                    unsigned bfa[4], bfb[4];
                    ldsm4(bfa, wcur + (wn * 32 + g8 * 8 + r8) * 36 + kc * 8);
                    ldsm4(bfb, wcur + (wn * 32 + g8 * 8 + r8) * 36 + kc * 8 + 4);
#pragma unroll
                    for (int j = 0; j < 4; j++)
#pragma unroll
                        for (int i = 0; i < 4; i++) mma_tf32b(acc[i][j], a[i], bfa[j], bfb[j]);
                }
            }
        }
    }

    const int win = b * 64 + (tile >> 3) * 8 + (tile & 7);
    const int head = (g & 3) * 2 + wn;
    if (g < 4) {   // K: [key][d]
        float* base = g_k + ((win * 8 + head) * 256) * 32;
#pragma unroll
        for (int i = 0; i < 4; i++) {
            const int p0 = wm * 64 + i * 16 + (lane >> 2);
#pragma unroll
            for (int j = 0; j < 4; j++) {
                const int col = wn * 32 + j * 8 + (lane & 3) * 2;
                const int d = col & 31;
                float b0 = bias[g * 64 + col], b1 = bias[g * 64 + col + 1];
                *(float2*)(base + p0 * 32 + d) =
                    make_float2(to_tf32(acc[i][j][0] + b0), to_tf32(acc[i][j][1] + b1));
                *(float2*)(base + (p0 + 8) * 32 + d) =
                    make_float2(to_tf32(acc[i][j][2] + b0), to_tf32(acc[i][j][3] + b1));
            }
        }
    } else {       // V transposed: [d][key]
        float* base = g_v + ((win * 8 + head) * 32) * 256;
#pragma unroll
        for (int i = 0; i < 4; i++) {
            const int p0 = wm * 64 + i * 16 + (lane >> 2);
#pragma unroll
            for (int j = 0; j < 4; j++) {
                const int col = wn * 32 + j * 8 + (lane & 3) * 2;
                const int d0 = col & 31;
                float b0 = bias[g * 64 + col], b1 = bias[g * 64 + col + 1];
                base[d0 * 256 + p0]           = to_tf32(acc[i][j][0] + b0);
                base[(d0 + 1) * 256 + p0]     = to_tf32(acc[i][j][1] + b1);
                base[d0 * 256 + p0 + 8]       = to_tf32(acc[i][j][2] + b0);
                base[(d0 + 1) * 256 + p0 + 8] = to_tf32(acc[i][j][3] + b1);
            }
        }
    }
}

// ---------------------------------------------------------------------------
// tf32 GEMM: MODE 0 qproj (x_wsa fp32 -> LDG/cvt/STS A-path),
//            MODE 1 outproj (g_o is pre-rounded tf32 -> pure cp.async A-path)
// B pre-transposed/tf32 in g_wt -> cp.async ring + ldsm fragments.
// ---------------------------------------------------------------------------
#define GEMM_A_FL 4608    // 128*36
#define GEMM_B_FL 2304    // 64 n * 36
#define GEMM_SLOT_FL (GEMM_A_FL + GEMM_B_FL)
#define GEMM_SMEM_B0 ((2*GEMM_A_FL + 3*GEMM_B_FL) * 4)
#define GEMM_SMEM_B1 ((3*GEMM_SLOT_FL) * 4)

template <int MODE>
__global__ __launch_bounds__(256, 2) void gemm_mma(const float* __restrict__ Aparam,
                                                   const float* __restrict__ bias,
                                                   const float* __restrict__ rz,
                                                   float* __restrict__ out) {
    extern __shared__ float smem[];

    const float* A = (MODE == 1) ? (const float*)g_o : Aparam;
    const float* wt = g_wt + MODE * 66560;

    const int tid = threadIdx.x;
    const int lane = tid & 31, warp = tid >> 5;
    const int wm = warp & 3, wn = warp >> 2;
    const int g8 = lane >> 3, r8 = lane & 7;
    const int m0 = blockIdx.x * 128;
    const int n0 = blockIdx.y * 64;

    const int arow = tid >> 1, akoff = (tid & 1) * 16;

    // Prologue: issue chunks 0,1
#pragma unroll
    for (int c0 = 0; c0 < 2; c0++) {
        if (MODE == 1) {
            float* sa = smem + c0 * GEMM_SLOT_FL;
#pragma unroll
            for (int c = 0; c < 4; c++) {
                const int idx = c * 256 + tid;          // 0..1023
                cpa16(sa + (idx >> 3) * 36 + (idx & 7) * 4,
                      A + (m0 + (idx >> 3)) * 256 + c0 * 32 + (idx & 7) * 4);
            }
            float* sb = sa + GEMM_A_FL;
#pragma unroll
            for (int c = 0; c < 2; c++) {
                const int idx = c * 256 + tid;
                cpa16(sb + (idx >> 3) * 36 + (idx & 7) * 4,
                      wt + (n0 + (idx >> 3)) * 260 + c0 * 32 + (idx & 7) * 4);
            }
        } else {
            float* sb = smem + 2 * GEMM_A_FL + c0 * GEMM_B_FL;
#pragma unroll
            for (int c = 0; c < 2; c++) {
                const int idx = c * 256 + tid;
                cpa16(sb + (idx >> 3) * 36 + (idx & 7) * 4,
                      wt + (n0 + (idx >> 3)) * 260 + c0 * 32 + (idx & 7) * 4);
            }
        }
        asm volatile("cp.async.commit_group;");
    }

    if (MODE == 0) {   // A chunk 0 -> abuf 0 (LDG + cvt + STS)
        const float4* ga = (const float4*)(A + (m0 + arow) * 256 + akoff);
        float* da = smem + arow * 36 + akoff;
#pragma unroll
        for (int c4 = 0; c4 < 4; c4++) {
            float4 v = ga[c4];
            *(float4*)(da + c4 * 4) = make_float4(to_tf32(v.x), to_tf32(v.y), to_tf32(v.z), to_tf32(v.w));
        }
    }

    float acc[2][4][4] = {};

#pragma unroll 1
    for (int kt = 0; kt < 8; kt++) {
        float4 pa[4];
        if (MODE == 0 && kt < 7) {
            const float4* ga = (const float4*)(A + (m0 + arow) * 256 + (kt + 1) * 32 + akoff);
#pragma unroll
            for (int c4 = 0; c4 < 4; c4++) pa[c4] = ga[c4];
        }
        if (kt < 6) asm volatile("cp.async.wait_group 1;");
        else        asm volatile("cp.async.wait_group 0;");
        __syncthreads();
        if (kt < 6) {
            const int nt = kt + 2;
            if (MODE == 1) {
                float* sa = smem + (nt % 3) * GEMM_SLOT_FL;
#pragma unroll
                for (int c = 0; c < 4; c++) {
                    const int idx = c * 256 + tid;
                    cpa16(sa + (idx >> 3) * 36 + (idx & 7) * 4,
                          A + (m0 + (idx >> 3)) * 256 + nt * 32 + (idx & 7) * 4);
                }
                float* sb = sa + GEMM_A_FL;
#pragma unroll
                for (int c = 0; c < 2; c++) {
                    const int idx = c * 256 + tid;
                    cpa16(sb + (idx >> 3) * 36 + (idx & 7) * 4,
                          wt + (n0 + (idx >> 3)) * 260 + nt * 32 + (idx & 7) * 4);
                }
            } else {
                float* sb = smem + 2 * GEMM_A_FL + (nt % 3) * GEMM_B_FL;
#pragma unroll
                for (int c = 0; c < 2; c++) {
                    const int idx = c * 256 + tid;
                    cpa16(sb + (idx >> 3) * 36 + (idx & 7) * 4,
                          wt + (n0 + (idx >> 3)) * 260 + nt * 32 + (idx & 7) * 4);
                }
            }
            asm volatile("cp.async.commit_group;");
        }
        const float* acur = (MODE == 1) ? (smem + (kt % 3) * GEMM_SLOT_FL)
                                        : (smem + (kt & 1) * GEMM_A_FL);
        const float* bcur = (MODE == 1) ? (smem + (kt % 3) * GEMM_SLOT_FL + GEMM_A_FL)
                                        : (smem + 2 * GEMM_A_FL + (kt % 3) * GEMM_B_FL);
#pragma unroll
        for (int kc = 0; kc < 4; kc++) {
            unsigned a[2][4];
#pragma unroll
            for (int i = 0; i < 2; i++) {
                const float* ap = acur + (wm * 32 + i * 16 + (g8 & 1) * 8 + r8) * 36
                                  + kc * 8 + (g8 >> 1) * 4;
                ldsm4(a[i], ap);
            }
            unsigned bfa[4], bfb[4];
            ldsm4(bfa, bcur + (wn * 32 + g8 * 8 + r8) * 36 + kc * 8);
            ldsm4(bfb, bcur + (wn * 32 + g8 * 8 + r8) * 36 + kc * 8 + 4);
#pragma unroll
            for (int j = 0; j < 4; j++)
#pragma unroll
                for (int i = 0; i < 2; i++) mma_tf32b(acc[i][j], a[i], bfa[j], bfb[j]);
        }
        if (MODE == 0 && kt < 7) {
            float* da = smem + ((kt + 1) & 1) * GEMM_A_FL + arow * 36 + akoff;
#pragma unroll
            for (int c4 = 0; c4 < 4; c4++)
                *(float4*)(da + c4 * 4) = make_float4(to_tf32(pa[c4].x), to_tf32(pa[c4].y),
                                                      to_tf32(pa[c4].z), to_tf32(pa[c4].w));
        }
    }

    const float scale = 0.17677669529663687f * 1.4426950408889634f;  // qproj folds log2(e)
    const float r = (MODE == 1) ? rz[0] : 0.f;
#pragma unroll
    for (int i = 0; i < 2; i++) {
        const int m = m0 + wm * 32 + i * 16 + (lane >> 2);
#pragma unroll
        for (int j = 0; j < 4; j++) {
            const int col = n0 + wn * 32 + j * 8 + (lane & 3) * 2;
            const float b0 = bias[col], b1 = bias[col + 1];
            if (MODE == 0) {
                const int bi = m >> 14, rr = (m >> 7) & 127, cc = m & 127;
                const int win = bi * 64 + ((rr >> 4) << 3) + (cc >> 4);
                const int t = (rr & 15) * 16 + (cc & 15);
                const int head = col >> 5, d = col & 31;
                float* p = g_q + ((win * 8 + head) * 256 + t) * 32 + d;
                *(float2*)p = make_float2(to_tf32((acc[i][j][0] + b0) * scale),
                                          to_tf32((acc[i][j][1] + b1) * scale));
                *(float2*)(p + 8 * 32) = make_float2(to_tf32((acc[i][j][2] + b0) * scale),
                                                     to_tf32((acc[i][j][3] + b1) * scale));
            } else {
                float* p = out + m * 256 + col;
                *(float2*)p = make_float2(r * (acc[i][j][0] + b0), r * (acc[i][j][1] + b1));
                *(float2*)(p + 8 * 256) = make_float2(r * (acc[i][j][2] + b0), r * (acc[i][j][3] + b1));
            }
        }
    }
}

// ---------------------------------------------------------------------------
// Tensor-core flash attention (frozen since R7; epilogue writes tf32-rounded
// g_o so outproj streams A via cp.async with identical numerics).
// ---------------------------------------------------------------------------
#define ATT_QS 9216            // 256*36
#define ATT_KS (3*1152)        // 3 stages * 32*36
#define ATT_VS (3*1152)        // 3 stages * 32 d * 36 (keys pitch)
#define ATT_PS 9216            // 8 warps * 32*36
#define ATT_SMEM_B ((ATT_QS + ATT_KS + ATT_VS + ATT_PS) * 4)

__global__ __launch_bounds__(256, 2) void attn_mma() {
    extern __shared__ float sm[];
    float* Qs = sm;
    float* Ks = sm + ATT_QS;
    float* Vs = Ks + ATT_KS;
    float* Ps = Vs + ATT_VS;

    const int win = blockIdx.x, hd = blockIdx.y;
    const int tid = threadIdx.x;
    const int lane = tid & 31, warp = tid >> 5;
    const int q = lane >> 2, t = lane & 3;
    const int g8 = lane >> 3, r8 = lane & 7;
    const int wb = warp * 32;
    float* Pw = Ps + warp * 1152;

    const float* qb = g_q + (win * 8 + hd) * 8192;
    const float* kb = g_k + (win * 8 + hd) * 8192;
    const float* vtb = g_v + (win * 8 + hd) * 8192;   // [32 d][256 key]
    const float* bb = g_bias + (hd << 16);

    // Stage Q into smem (pitch 36)
    for (int i = tid; i < 2048; i += 256) {
        float4 v = ((const float4*)qb)[i];
        *(float4*)&Qs[(i >> 3) * 36 + (i & 7) * 4] = v;
    }
    // cp.async chunks 0 and 1. K: [key][d]; V: [d][key] slices
    {
        const int row = tid >> 3, seg = (tid & 7) * 4;
#pragma unroll
        for (int c = 0; c < 2; c++) {
            cpa16(Ks + c * 1152 + row * 36 + seg, kb + c * 1024 + tid * 4);
            cpa16(Vs + c * 1152 + row * 36 + seg, vtb + row * 256 + c * 32 + seg);
            asm volatile("cp.async.commit_group;");
        }
    }
    __syncthreads();

    // Q fragments -> registers (once)
    unsigned qa[2][4][4];
#pragma unroll
    for (int mt = 0; mt < 2; mt++)
#pragma unroll
        for (int kc = 0; kc < 4; kc++)
            ldsm4(qa[mt][kc], Qs + (wb + mt * 16 + (g8 & 1) * 8 + r8) * 36 + kc * 8 + (g8 >> 1) * 4);

    float o[2][4][4] = {};
    float mrow[2][2] = {{-1e30f, -1e30f}, {-1e30f, -1e30f}};
    float lrow[2][2] = {};   // per-lane partials, reduced in epilogue

#pragma unroll 1
    for (int sb = 0; sb < 8; sb++) {
        asm volatile("cp.async.wait_group 1;");
        __syncthreads();

        if (sb < 6) {
            const int slot = (sb + 2) % 3;
            const int row = tid >> 3, seg = (tid & 7) * 4;
            cpa16(Ks + slot * 1152 + row * 36 + seg, kb + (sb + 2) * 1024 + tid * 4);
            cpa16(Vs + slot * 1152 + row * 36 + seg, vtb + row * 256 + (sb + 2) * 32 + seg);
        }
        asm volatile("cp.async.commit_group;");

        const float* Kb = Ks + (sb % 3) * 1152;
        const float* Vb = Vs + (sb % 3) * 1152;

        // ---- S = Q K^T for BOTH m-tiles, bias as accumulator init ----
        float s[2][4][4];
#pragma unroll
        for (int mt = 0; mt < 2; mt++) {
            const float* br0 = bb + (wb + mt * 16 + q) * 256 + sb * 32 + t * 2;
            const float* br1 = br0 + 8 * 256;
#pragma unroll
            for (int nt = 0; nt < 4; nt++) {
                float2 b0 = *(const float2*)(br0 + nt * 8);
                float2 b1 = *(const float2*)(br1 + nt * 8);
                s[mt][nt][0] = b0.x; s[mt][nt][1] = b0.y;
                s[mt][nt][2] = b1.x; s[mt][nt][3] = b1.y;
            }
        }
#pragma unroll
        for (int kc = 0; kc < 4; kc++) {
#pragma unroll
            for (int pr = 0; pr < 2; pr++) {
                unsigned kf[4];
                ldsm4(kf, Kb + (pr * 16 + (g8 >> 1) * 8 + r8) * 36 + kc * 8 + (g8 & 1) * 4);
                mma_tf32(s[0][pr * 2 + 0], qa[0][kc], &kf[0]);
                mma_tf32(s[0][pr * 2 + 1], qa[0][kc], &kf[2]);
                mma_tf32(s[1][pr * 2 + 0], qa[1][kc], &kf[0]);
                mma_tf32(s[1][pr * 2 + 1], qa[1][kc], &kf[2]);
            }
        }

        // ---- online softmax per m-tile; raw P -> warp-private smem ----
#pragma unroll
        for (int mt = 0; mt < 2; mt++) {
            float mx0 = fmaxf(fmaxf(s[mt][0][0], s[mt][0][1]), fmaxf(s[mt][1][0], s[mt][1][1]));
            float mx1 = fmaxf(fmaxf(s[mt][0][2], s[mt][0][3]), fmaxf(s[mt][1][2], s[mt][1][3]));
            mx0 = fmaxf(mx0, fmaxf(fmaxf(s[mt][2][0], s[mt][2][1]), fmaxf(s[mt][3][0], s[mt][3][1])));
            mx1 = fmaxf(mx1, fmaxf(fmaxf(s[mt][2][2], s[mt][2][3]), fmaxf(s[mt][3][2], s[mt][3][3])));
            mx0 = fmaxf(mx0, __shfl_xor_sync(0xffffffff, mx0, 1));
            mx0 = fmaxf(mx0, __shfl_xor_sync(0xffffffff, mx0, 2));
            mx1 = fmaxf(mx1, __shfl_xor_sync(0xffffffff, mx1, 1));
            mx1 = fmaxf(mx1, __shfl_xor_sync(0xffffffff, mx1, 2));
            const float mn0 = fmaxf(mrow[mt][0], mx0);
            const float mn1 = fmaxf(mrow[mt][1], mx1);
            const float cor0 = ex2(mrow[mt][0] - mn0);
            const float cor1 = ex2(mrow[mt][1] - mn1);
            mrow[mt][0] = mn0; mrow[mt][1] = mn1;
#pragma unroll
            for (int dn = 0; dn < 4; dn++) {
                o[mt][dn][0] *= cor0; o[mt][dn][1] *= cor0;
                o[mt][dn][2] *= cor1; o[mt][dn][3] *= cor1;
            }
            float sm0 = 0.f, sm1 = 0.f;
#pragma unroll
            for (int nt = 0; nt < 4; nt++) {
                float p0 = ex2(s[mt][nt][0] - mn0);
                float p1 = ex2(s[mt][nt][1] - mn0);
                float p2 = ex2(s[mt][nt][2] - mn1);
                float p3 = ex2(s[mt][nt][3] - mn1);
                sm0 += p0 + p1; sm1 += p2 + p3;
                *(float2*)&Pw[(mt * 16 + q) * 36 + nt * 8 + 2 * t] = make_float2(p0, p1);
                *(float2*)&Pw[(mt * 16 + q + 8) * 36 + nt * 8 + 2 * t] = make_float2(p2, p3);
            }
            lrow[mt][0] = lrow[mt][0] * cor0 + sm0;
            lrow[mt][1] = lrow[mt][1] * cor1 + sm1;
        }
        __syncwarp();

        // ---- O += P V : P and V fragments via ldmatrix ----
#pragma unroll
        for (int kk = 0; kk < 4; kk++) {
            unsigned pa[2][4];
            ldsm4(pa[0], Pw + ((g8 & 1) * 8 + r8) * 36 + kk * 8 + (g8 >> 1) * 4);
            ldsm4(pa[1], Pw + (16 + (g8 & 1) * 8 + r8) * 36 + kk * 8 + (g8 >> 1) * 4);
            unsigned vf0[4], vf1[4];
            ldsm4(vf0, Vb + ((g8 >> 1) * 8 + r8) * 36 + kk * 8 + (g8 & 1) * 4);
            ldsm4(vf1, Vb + ((2 + (g8 >> 1)) * 8 + r8) * 36 + kk * 8 + (g8 & 1) * 4);
            mma_tf32(o[0][0], pa[0], &vf0[0]);
            mma_tf32(o[0][1], pa[0], &vf0[2]);
            mma_tf32(o[0][2], pa[0], &vf1[0]);
            mma_tf32(o[0][3], pa[0], &vf1[2]);
            mma_tf32(o[1][0], pa[1], &vf0[0]);
            mma_tf32(o[1][1], pa[1], &vf0[2]);
            mma_tf32(o[1][2], pa[1], &vf1[0]);
            mma_tf32(o[1][3], pa[1], &vf1[2]);
        }
        __syncwarp();
    }

    // Epilogue: reduce l partials, normalize, write tf32-rounded (B,H,W,C)
    const int bimg = win >> 6, wh = (win >> 3) & 7, ww = win & 7;
#pragma unroll
    for (int mt = 0; mt < 2; mt++) {
        float l0 = lrow[mt][0], l1 = lrow[mt][1];
        l0 += __shfl_xor_sync(0xffffffff, l0, 1);
        l0 += __shfl_xor_sync(0xffffffff, l0, 2);
        l1 += __shfl_xor_sync(0xffffffff, l1, 1);
        l1 += __shfl_xor_sync(0xffffffff, l1, 2);
        const float inv0 = 1.f / l0;
        const float inv1 = 1.f / l1;
        const int tk0 = wb + mt * 16 + q;
#pragma unroll
        for (int half = 0; half < 2; half++) {
            const int tk = tk0 + half * 8;
            const float inv = half ? inv1 : inv0;
            const int gr = wh * 16 + (tk >> 4), gc = ww * 16 + (tk & 15);
            float* op = g_o + ((bimg * 128 + gr) * 128 + gc) * 256 + hd * 32;
#pragma unroll
            for (int dn = 0; dn < 4; dn++) {
                float a = to_tf32(o[mt][dn][half * 2] * inv);
                float b = to_tf32(o[mt][dn][half * 2 + 1] * inv);
                *(float2*)(op + dn * 8 + t * 2) = make_float2(a, b);
            }
        }
    }
}

// ---------------------------------------------------------------------------
// Launch order puts convkv_mma 4th: the ncu capture window (empirically the
// 4th launch) profiles conv this round.
// ---------------------------------------------------------------------------
extern "C" void kernel_launch(void* const* d_in, const int* in_sizes, int n_in,
                              void* d_out, int out_size) {
    (void)in_sizes; (void)n_in; (void)out_size;
    const float* x_wsa      = (const float*)d_in[0];
    const float* x_original = (const float*)d_in[1];
    const float* q_w        = (const float*)d_in[2];
    const float* q_b        = (const float*)d_in[3];
    const float* kv_w       = (const float*)d_in[4];
    const float* kv_b       = (const float*)d_in[5];
    const float* out_w      = (const float*)d_in[6];
    const float* out_b      = (const float*)d_in[7];
    const float* bias_table = (const float*)d_in[8];
    const float* rezero     = (const float*)d_in[9];
    float* out = (float*)d_out;

    cudaFuncSetAttribute(convkv_mma, cudaFuncAttributeMaxDynamicSharedMemorySize, CONV_SMEM_B);
    cudaFuncSetAttribute(gemm_mma<0>, cudaFuncAttributeMaxDynamicSharedMemorySize, GEMM_SMEM_B0);
    cudaFuncSetAttribute(gemm_mma<1>, cudaFuncAttributeMaxDynamicSharedMemorySize, GEMM_SMEM_B1);
    cudaFuncSetAttribute(attn_mma, cudaFuncAttributeMaxDynamicSharedMemorySize, ATT_SMEM_B);

    prep_misc<<<2560, 256>>>(bias_table, q_w, out_w);           // #1
    prep_conv_w<<<1600, 256>>>(kv_w);                           // #2
    gemm_mma<0><<<dim3(512, 4), 256, GEMM_SMEM_B0>>>(x_wsa, q_b, nullptr, nullptr);  // #3
    convkv_mma<<<dim3(64, 32), 256, CONV_SMEM_B>>>(x_original, kv_b);                // #4 <- profiled
    attn_mma<<<dim3(256, 8), 256, ATT_SMEM_B>>>();                                   // #5
    gemm_mma<1><<<dim3(512, 4), 256, GEMM_SMEM_B1>>>(nullptr, out_b, rezero, out);   // #6
}

// round 12
// speedup vs baseline: 1.8608x; 1.2278x over previous
#include <cuda_runtime.h>
#include <cuda_fp16.h>

// B=4, H=W=128, C=256, heads=8, d=32, win=16 -> 256 windows x 256 tokens
// g_q: [win][head][tok][d]; g_k: [win][head][key][d]; g_v TRANSPOSED: [win][head][d][key]
__device__ float g_q[16777216];
__device__ float g_k[16777216];
__device__ float g_v[16777216];
__device__ float g_o[16777216];
__device__ float g_bias[524288];    // [head][256 q][256 k], pre-scaled by log2(e)
__device__ float g_wt[133120];      // 2 x [256 n][260 pitch k]: tf32(qw^T), tf32(ow^T)
__device__ __half g_wcth[204800];   // conv weights fp16: [(g*64+oc)][25 taps * 32 k] pitch 800

__device__ __forceinline__ float to_tf32(float x) {
    unsigned u;
    asm("cvt.rna.tf32.f32 %0, %1;" : "=r"(u) : "f"(x));
    return __uint_as_float(u);
}

__device__ __forceinline__ float ex2(float x) {
    float r;
    asm("ex2.approx.ftz.f32 %0, %1;" : "=f"(r) : "f"(x));
    return r;
}

__device__ __forceinline__ void mma_tf32(float* c, const unsigned* a, const unsigned* b) {
    asm volatile(
        "mma.sync.aligned.m16n8k8.row.col.f32.tf32.tf32.f32 "
        "{%0,%1,%2,%3},{%4,%5,%6,%7},{%8,%9},{%0,%1,%2,%3};"
        : "+f"(c[0]), "+f"(c[1]), "+f"(c[2]), "+f"(c[3])
        : "r"(a[0]), "r"(a[1]), "r"(a[2]), "r"(a[3]), "r"(b[0]), "r"(b[1]));
}

__device__ __forceinline__ void mma_tf32b(float* c, const unsigned* a, unsigned b0, unsigned b1) {
    asm volatile(
        "mma.sync.aligned.m16n8k8.row.col.f32.tf32.tf32.f32 "
        "{%0,%1,%2,%3},{%4,%5,%6,%7},{%8,%9},{%0,%1,%2,%3};"
        : "+f"(c[0]), "+f"(c[1]), "+f"(c[2]), "+f"(c[3])
        : "r"(a[0]), "r"(a[1]), "r"(a[2]), "r"(a[3]), "r"(b0), "r"(b1));
}

// fp16 mma m16n8k16, fp32 accumulate (fp16 mantissa == tf32 mantissa: 10 bits)
__device__ __forceinline__ void mma_f16(float* c, const unsigned* a, unsigned b0, unsigned b1) {
    asm volatile(
        "mma.sync.aligned.m16n8k16.row.col.f32.f16.f16.f32 "
        "{%0,%1,%2,%3},{%4,%5,%6,%7},{%8,%9},{%0,%1,%2,%3};"
        : "+f"(c[0]), "+f"(c[1]), "+f"(c[2]), "+f"(c[3])
        : "r"(a[0]), "r"(a[1]), "r"(a[2]), "r"(a[3]), "r"(b0), "r"(b1));
}

// tf32 fragments via b16 ldmatrix (8-row x 4-float block == b16 8x8 tile)
__device__ __forceinline__ void ldsm4(unsigned* r, const float* p) {
    unsigned a = (unsigned)__cvta_generic_to_shared(p);
    asm volatile("ldmatrix.sync.aligned.m8n8.x4.shared.b16 {%0,%1,%2,%3}, [%4];"
                 : "=r"(r[0]), "=r"(r[1]), "=r"(r[2]), "=r"(r[3]) : "r"(a));
}

__device__ __forceinline__ void ldsm4h(unsigned* r, const __half* p) {
    unsigned a = (unsigned)__cvta_generic_to_shared(p);
    asm volatile("ldmatrix.sync.aligned.m8n8.x4.shared.b16 {%0,%1,%2,%3}, [%4];"
                 : "=r"(r[0]), "=r"(r[1]), "=r"(r[2]), "=r"(r[3]) : "r"(a));
}

__device__ __forceinline__ void cpa16(float* dst, const float* src) {
    unsigned d = (unsigned)__cvta_generic_to_shared(dst);
    asm volatile("cp.async.cg.shared.global [%0], [%1], 16;" :: "r"(d), "l"(src));
}
__device__ __forceinline__ void cpa16h(__half* dst, const __half* src) {
    unsigned d = (unsigned)__cvta_generic_to_shared(dst);
    asm volatile("cp.async.cg.shared.global [%0], [%1], 16;" :: "r"(d), "l"(src));
}

// ---------------------------------------------------------------------------
// Prep: bias expansion + GEMM weight transposes (one kernel) and conv weight
// transpose+fp16 convert (separate, so conv stays launch #4 for ncu).
// ---------------------------------------------------------------------------
__global__ void prep_misc(const float* __restrict__ bt,
                          const float* __restrict__ qw,
                          const float* __restrict__ ow) {
    const int idx = blockIdx.x * 256 + threadIdx.x;
    if (idx < 524288) {
        const int hd = idx >> 16, qt = (idx >> 8) & 255, kt = idx & 255;
        const int qy = qt >> 4, qx = qt & 15, ky = kt >> 4, kx = kt & 15;
        const int rel = (qy - ky + 15) * 31 + (qx - kx + 15);
        g_bias[idx] = bt[rel * 8 + hd] * 1.4426950408889634f;
    } else {
        const int i2 = idx - 524288;           // 0..131071
        const int slot = i2 >> 16;             // 0: qw, 1: ow
        const int r = i2 & 65535;
        const int n = r >> 8, k = r & 255;
        const float* W = slot ? ow : qw;
        g_wt[slot * 66560 + n * 260 + k] = to_tf32(W[k * 256 + n]);
    }
}

__global__ void prep_conv_w(const float* __restrict__ Wc) {
    const int idx = blockIdx.x * 256 + threadIdx.x;   // 409600
    const int k = idx & 31;
    const int tap = (idx >> 5) % 25;
    const int ocg = idx / 800;                        // g*64 + oc
    const int g = ocg >> 6, oc = ocg & 63;
    g_wcth[ocg * 800 + tap * 32 + k] = __float2half_rn(Wc[(tap * 32 + k) * 512 + g * 64 + oc]);
}

// ---------------------------------------------------------------------------
// Conv 5x5 grouped (pad 2, groups=8) as implicit GEMM — fp16 mma m16n8k16.
// Patch: [400 px][40 halfs] (80B rows: 16B-aligned, ldmatrix conflict-free).
// Weights: fp16 pair-ring via cp.async (2 taps/round, 13 rounds).
// K scattered as [key][d] fp32; V scattered TRANSPOSED as [d][key] fp32.
// ---------------------------------------------------------------------------
#define CONV_PATCH_H 16000    // 400 * 40 halfs (32000 B)
#define CONV_WTAP_H  2560     // 64 oc * 40 halfs (5120 B)
#define CONV_WPAIR_H (2*CONV_WTAP_H)
#define CONV_SMEM_B  (CONV_PATCH_H*2 + 3*CONV_WPAIR_H*2)   // 62720 B

__global__ __launch_bounds__(256, 2) void convkv_mma(const float* __restrict__ X,
                                                     const float* __restrict__ bias) {
    extern __shared__ char smc[];
    __half* patch = (__half*)smc;
    __half* wring = patch + CONV_PATCH_H;

    const int tid = threadIdx.x;
    const int lane = tid & 31, warp = tid >> 5;
    const int wm = warp & 3, wn = warp >> 2;
    const int g8 = lane >> 3, r8 = lane & 7;
    const int tile = blockIdx.x;
    const int ty0 = (tile >> 3) * 16, tx0 = (tile & 7) * 16;
    const int b = blockIdx.y >> 3, g = blockIdx.y & 7;

    const __half* wsrc = g_wcth + (g * 64) * 800;

    // Issue weight tap-pairs 0 and 1 into ring slots 0,1 (2 cp.async/thread each)
#pragma unroll
    for (int pr = 0; pr < 2; pr++) {
#pragma unroll
        for (int c = 0; c < 2; c++) {
            const int idx = c * 256 + tid;              // 0..511
            const int t2 = idx >> 8, rest = idx & 255;
            const int row = rest >> 2, seg = (rest & 3) * 8;
            cpa16h(wring + pr * CONV_WPAIR_H + t2 * CONV_WTAP_H + row * 40 + seg,
                   wsrc + row * 800 + (pr * 2 + t2) * 32 + seg);
        }
        asm volatile("cp.async.commit_group;");
    }

    // Stage input patch (zero-padded), fp32 -> fp16
    for (int p = tid; p < 400; p += 256) {
        int py = p / 20, px = p - py * 20;
        int gy = ty0 + py - 2, gx = tx0 + px - 2;
        bool ok = (gy >= 0 && gy < 128 && gx >= 0 && gx < 128);
        const float4* src = (const float4*)(X + ((b * 128 + gy) * 128 + gx) * 256 + g * 32);
#pragma unroll
        for (int s = 0; s < 4; s++) {      // 4 segments of 8 halfs (16B)
            float4 v0 = ok ? src[s * 2]     : make_float4(0.f, 0.f, 0.f, 0.f);
            float4 v1 = ok ? src[s * 2 + 1] : make_float4(0.f, 0.f, 0.f, 0.f);
            __half2 h0 = __floats2half2_rn(v0.x, v0.y);
            __half2 h1 = __floats2half2_rn(v0.z, v0.w);
            __half2 h2 = __floats2half2_rn(v1.x, v1.y);
            __half2 h3 = __floats2half2_rn(v1.z, v1.w);
            uint4 u;
            u.x = *(unsigned*)&h0; u.y = *(unsigned*)&h1;
            u.z = *(unsigned*)&h2; u.w = *(unsigned*)&h3;
            *(uint4*)&patch[p * 40 + s * 8] = u;
        }
    }

    float acc[4][4][4] = {};

#pragma unroll 1
    for (int rnd = 0; rnd < 13; rnd++) {
        if (rnd < 11) asm volatile("cp.async.wait_group 1;");
        else          asm volatile("cp.async.wait_group 0;");
        __syncthreads();   // pair rnd ready (+patch on first iter); slot (rnd+2)%3 free
        if (rnd < 11) {
            const int np = rnd + 2;
            __half* dst = wring + (np % 3) * CONV_WPAIR_H;
#pragma unroll
            for (int c = 0; c < 2; c++) {
                const int idx = c * 256 + tid;
                const int t2 = idx >> 8, rest = idx & 255;
                const int row = rest >> 2, seg = (rest & 3) * 8;
                const int tap = np * 2 + t2;
                if (tap < 25)
                    cpa16h(dst + t2 * CONV_WTAP_H + row * 40 + seg,
                           wsrc + row * 800 + tap * 32 + seg);
            }
            asm volatile("cp.async.commit_group;");
        } else {
            asm volatile("cp.async.commit_group;");
        }

#pragma unroll
        for (int t2 = 0; t2 < 2; t2++) {
            const int tap = rnd * 2 + t2;
            if (tap < 25) {
                const int ky = tap / 5, kx = tap - ky * 5;
                const __half* wcur = wring + (rnd % 3) * CONV_WPAIR_H + t2 * CONV_WTAP_H;
#pragma unroll
                for (int kc = 0; kc < 2; kc++) {   // k16 per mma: 2 steps cover 32 ic
                    unsigned a[4][4];
#pragma unroll
                    for (int i = 0; i < 4; i++) {
                        // tiles: (m0-7,k0-7),(m8-15,k0-7),(m0-7,k8-15),(m8-15,k8-15)
                        const __half* ap = patch
                            + ((wm * 4 + i + ky) * 20 + (g8 & 1) * 8 + r8 + kx) * 40
                            + kc * 16 + (g8 >> 1) * 8;
                        ldsm4h(a[i], ap);
                    }
                    unsigned bf0[4], bf1[4];   // n0-15 and n16-31
                    ldsm4h(bf0, wcur + (wn * 32 + (g8 & 1) * 8 + r8) * 40 + kc * 16 + (g8 >> 1) * 8);
                    ldsm4h(bf1, wcur + (wn * 32 + 16 + (g8 & 1) * 8 + r8) * 40 + kc * 16 + (g8 >> 1) * 8);
#pragma unroll
                    for (int i = 0; i < 4; i++) {
                        mma_f16(acc[i][0], a[i], bf0[0], bf0[2]);
                        mma_f16(acc[i][1], a[i], bf0[1], bf0[3]);
                        mma_f16(acc[i][2], a[i], bf1[0], bf1[2]);
                        mma_f16(acc[i][3], a[i], bf1[1], bf1[3]);
                    }
                }
            }
        }
    }

    const int win = b * 64 + (tile >> 3) * 8 + (tile & 7);
    const int head = (g & 3) * 2 + wn;
    if (g < 4) {   // K: [key][d]
        float* base = g_k + ((win * 8 + head) * 256) * 32;
#pragma unroll
        for (int i = 0; i < 4; i++) {
            const int p0 = wm * 64 + i * 16 + (lane >> 2);
#pragma unroll
            for (int j = 0; j < 4; j++) {
                const int col = wn * 32 + j * 8 + (lane & 3) * 2;
                const int d = col & 31;
                float b0 = bias[g * 64 + col], b1 = bias[g * 64 + col + 1];
                *(float2*)(base + p0 * 32 + d) =
                    make_float2(to_tf32(acc[i][j][0] + b0), to_tf32(acc[i][j][1] + b1));
                *(float2*)(base + (p0 + 8) * 32 + d) =
                    make_float2(to_tf32(acc[i][j][2] + b0), to_tf32(acc[i][j][3] + b1));
            }
        }
    } else {       // V transposed: [d][key]
        float* base = g_v + ((win * 8 + head) * 32) * 256;
#pragma unroll
        for (int i = 0; i < 4; i++) {
            const int p0 = wm * 64 + i * 16 + (lane >> 2);
#pragma unroll
            for (int j = 0; j < 4; j++) {
                const int col = wn * 32 + j * 8 + (lane & 3) * 2;
                const int d0 = col & 31;
                float b0 = bias[g * 64 + col], b1 = bias[g * 64 + col + 1];
                base[d0 * 256 + p0]           = to_tf32(acc[i][j][0] + b0);
                base[(d0 + 1) * 256 + p0]     = to_tf32(acc[i][j][1] + b1);
                base[d0 * 256 + p0 + 8]       = to_tf32(acc[i][j][2] + b0);
                base[(d0 + 1) * 256 + p0 + 8] = to_tf32(acc[i][j][3] + b1);
            }
        }
    }
}

// ---------------------------------------------------------------------------
// tf32 GEMM (unchanged from R11): MODE 0 qproj, MODE 1 outproj.
// ---------------------------------------------------------------------------
#define GEMM_A_FL 4608    // 128*36
#define GEMM_B_FL 2304    // 64 n * 36
#define GEMM_SLOT_FL (GEMM_A_FL + GEMM_B_FL)
#define GEMM_SMEM_B0 ((2*GEMM_A_FL + 3*GEMM_B_FL) * 4)
#define GEMM_SMEM_B1 ((3*GEMM_SLOT_FL) * 4)

template <int MODE>
__global__ __launch_bounds__(256, 2) void gemm_mma(const float* __restrict__ Aparam,
                                                   const float* __restrict__ bias,
                                                   const float* __restrict__ rz,
                                                   float* __restrict__ out) {
    extern __shared__ float smem[];

    const float* A = (MODE == 1) ? (const float*)g_o : Aparam;
    const float* wt = g_wt + MODE * 66560;

    const int tid = threadIdx.x;
    const int lane = tid & 31, warp = tid >> 5;
    const int wm = warp & 3, wn = warp >> 2;
    const int g8 = lane >> 3, r8 = lane & 7;
    const int m0 = blockIdx.x * 128;
    const int n0 = blockIdx.y * 64;

    const int arow = tid >> 1, akoff = (tid & 1) * 16;

#pragma unroll
    for (int c0 = 0; c0 < 2; c0++) {
        if (MODE == 1) {
            float* sa = smem + c0 * GEMM_SLOT_FL;
#pragma unroll
            for (int c = 0; c < 4; c++) {
                const int idx = c * 256 + tid;
                cpa16(sa + (idx >> 3) * 36 + (idx & 7) * 4,
                      A + (m0 + (idx >> 3)) * 256 + c0 * 32 + (idx & 7) * 4);
            }
            float* sb = sa + GEMM_A_FL;
#pragma unroll
            for (int c = 0; c < 2; c++) {
                const int idx = c * 256 + tid;
                cpa16(sb + (idx >> 3) * 36 + (idx & 7) * 4,
                      wt + (n0 + (idx >> 3)) * 260 + c0 * 32 + (idx & 7) * 4);
            }
        } else {
            float* sb = smem + 2 * GEMM_A_FL + c0 * GEMM_B_FL;
#pragma unroll
            for (int c = 0; c < 2; c++) {
                const int idx = c * 256 + tid;
                cpa16(sb + (idx >> 3) * 36 + (idx & 7) * 4,
                      wt + (n0 + (idx >> 3)) * 260 + c0 * 32 + (idx & 7) * 4);
            }
        }
        asm volatile("cp.async.commit_group;");
    }

    if (MODE == 0) {
        const float4* ga = (const float4*)(A + (m0 + arow) * 256 + akoff);
        float* da = smem + arow * 36 + akoff;
#pragma unroll
        for (int c4 = 0; c4 < 4; c4++) {
            float4 v = ga[c4];
            *(float4*)(da + c4 * 4) = make_float4(to_tf32(v.x), to_tf32(v.y), to_tf32(v.z), to_tf32(v.w));
        }
    }

    float acc[2][4][4] = {};

#pragma unroll 1
    for (int kt = 0; kt < 8; kt++) {
        float4 pa[4];
        if (MODE == 0 && kt < 7) {
            const float4* ga = (const float4*)(A + (m0 + arow) * 256 + (kt + 1) * 32 + akoff);
#pragma unroll
            for (int c4 = 0; c4 < 4; c4++) pa[c4] = ga[c4];
        }
        if (kt < 6) asm volatile("cp.async.wait_group 1;");
        else        asm volatile("cp.async.wait_group 0;");
        __syncthreads();
        if (kt < 6) {
            const int nt = kt + 2;
            if (MODE == 1) {
                float* sa = smem + (nt % 3) * GEMM_SLOT_FL;
#pragma unroll
                for (int c = 0; c < 4; c++) {
                    const int idx = c * 256 + tid;
                    cpa16(sa + (idx >> 3) * 36 + (idx & 7) * 4,
                          A + (m0 + (idx >> 3)) * 256 + nt * 32 + (idx & 7) * 4);
                }
                float* sb = sa + GEMM_A_FL;
#pragma unroll
                for (int c = 0; c < 2; c++) {
                    const int idx = c * 256 + tid;
                    cpa16(sb + (idx >> 3) * 36 + (idx & 7) * 4,
                          wt + (n0 + (idx >> 3)) * 260 + nt * 32 + (idx & 7) * 4);
                }
            } else {
                float* sb = smem + 2 * GEMM_A_FL + (nt % 3) * GEMM_B_FL;
#pragma unroll
                for (int c = 0; c < 2; c++) {
                    const int idx = c * 256 + tid;
                    cpa16(sb + (idx >> 3) * 36 + (idx & 7) * 4,
                          wt + (n0 + (idx >> 3)) * 260 + nt * 32 + (idx & 7) * 4);
                }
            }
            asm volatile("cp.async.commit_group;");
        }
        const float* acur = (MODE == 1) ? (smem + (kt % 3) * GEMM_SLOT_FL)
                                        : (smem + (kt & 1) * GEMM_A_FL);
        const float* bcur = (MODE == 1) ? (smem + (kt % 3) * GEMM_SLOT_FL + GEMM_A_FL)
                                        : (smem + 2 * GEMM_A_FL + (kt % 3) * GEMM_B_FL);
#pragma unroll
        for (int kc = 0; kc < 4; kc++) {
            unsigned a[2][4];
#pragma unroll
            for (int i = 0; i < 2; i++) {
                const float* ap = acur + (wm * 32 + i * 16 + (g8 & 1) * 8 + r8) * 36
                                  + kc * 8 + (g8 >> 1) * 4;
                ldsm4(a[i], ap);
            }
            unsigned bfa[4], bfb[4];
            ldsm4(bfa, bcur + (wn * 32 + g8 * 8 + r8) * 36 + kc * 8);
            ldsm4(bfb, bcur + (wn * 32 + g8 * 8 + r8) * 36 + kc * 8 + 4);
#pragma unroll
            for (int j = 0; j < 4; j++)
#pragma unroll
                for (int i = 0; i < 2; i++) mma_tf32b(acc[i][j], a[i], bfa[j], bfb[j]);
        }
        if (MODE == 0 && kt < 7) {
            float* da = smem + ((kt + 1) & 1) * GEMM_A_FL + arow * 36 + akoff;
#pragma unroll
            for (int c4 = 0; c4 < 4; c4++)
                *(float4*)(da + c4 * 4) = make_float4(to_tf32(pa[c4].x), to_tf32(pa[c4].y),
                                                      to_tf32(pa[c4].z), to_tf32(pa[c4].w));
        }
    }

    const float scale = 0.17677669529663687f * 1.4426950408889634f;  // qproj folds log2(e)
    const float r = (MODE == 1) ? rz[0] : 0.f;
#pragma unroll
    for (int i = 0; i < 2; i++) {
        const int m = m0 + wm * 32 + i * 16 + (lane >> 2);
#pragma unroll
        for (int j = 0; j < 4; j++) {
            const int col = n0 + wn * 32 + j * 8 + (lane & 3) * 2;
            const float b0 = bias[col], b1 = bias[col + 1];
            if (MODE == 0) {
                const int bi = m >> 14, rr = (m >> 7) & 127, cc = m & 127;
                const int win = bi * 64 + ((rr >> 4) << 3) + (cc >> 4);
                const int t = (rr & 15) * 16 + (cc & 15);
                const int head = col >> 5, d = col & 31;
                float* p = g_q + ((win * 8 + head) * 256 + t) * 32 + d;
                *(float2*)p = make_float2(to_tf32((acc[i][j][0] + b0) * scale),
                                          to_tf32((acc[i][j][1] + b1) * scale));
                *(float2*)(p + 8 * 32) = make_float2(to_tf32((acc[i][j][2] + b0) * scale),
                                                     to_tf32((acc[i][j][3] + b1) * scale));
            } else {
                float* p = out + m * 256 + col;
                *(float2*)p = make_float2(r * (acc[i][j][0] + b0), r * (acc[i][j][1] + b1));
                *(float2*)(p + 8 * 256) = make_float2(r * (acc[i][j][2] + b0), r * (acc[i][j][3] + b1));
            }
        }
    }
}

// ---------------------------------------------------------------------------
// Tensor-core flash attention (frozen since R7).
// ---------------------------------------------------------------------------
#define ATT_QS 9216
#define ATT_KS (3*1152)
#define ATT_VS (3*1152)
#define ATT_PS 9216
#define ATT_SMEM_B ((ATT_QS + ATT_KS + ATT_VS + ATT_PS) * 4)

__global__ __launch_bounds__(256, 2) void attn_mma() {
    extern __shared__ float sm[];
    float* Qs = sm;
    float* Ks = sm + ATT_QS;
    float* Vs = Ks + ATT_KS;
    float* Ps = Vs + ATT_VS;

    const int win = blockIdx.x, hd = blockIdx.y;
    const int tid = threadIdx.x;
    const int lane = tid & 31, warp = tid >> 5;
    const int q = lane >> 2, t = lane & 3;
    const int g8 = lane >> 3, r8 = lane & 7;
    const int wb = warp * 32;
    float* Pw = Ps + warp * 1152;

    const float* qb = g_q + (win * 8 + hd) * 8192;
    const float* kb = g_k + (win * 8 + hd) * 8192;
    const float* vtb = g_v + (win * 8 + hd) * 8192;
    const float* bb = g_bias + (hd << 16);

    for (int i = tid; i < 2048; i += 256) {
        float4 v = ((const float4*)qb)[i];
        *(float4*)&Qs[(i >> 3) * 36 + (i & 7) * 4] = v;
    }
    {
        const int row = tid >> 3, seg = (tid & 7) * 4;
#pragma unroll
        for (int c = 0; c < 2; c++) {
            cpa16(Ks + c * 1152 + row * 36 + seg, kb + c * 1024 + tid * 4);
            cpa16(Vs + c * 1152 + row * 36 + seg, vtb + row * 256 + c * 32 + seg);
            asm volatile("cp.async.commit_group;");
        }
    }
    __syncthreads();

    unsigned qa[2][4][4];
#pragma unroll
    for (int mt = 0; mt < 2; mt++)
#pragma unroll
        for (int kc = 0; kc < 4; kc++)
            ldsm4(qa[mt][kc], Qs + (wb + mt * 16 + (g8 & 1) * 8 + r8) * 36 + kc * 8 + (g8 >> 1) * 4);

    float o[2][4][4] = {};
    float mrow[2][2] = {{-1e30f, -1e30f}, {-1e30f, -1e30f}};
    float lrow[2][2] = {};

#pragma unroll 1
    for (int sb = 0; sb < 8; sb++) {
        asm volatile("cp.async.wait_group 1;");
        __syncthreads();

        if (sb < 6) {
            const int slot = (sb + 2) % 3;
            const int row = tid >> 3, seg = (tid & 7) * 4;
            cpa16(Ks + slot * 1152 + row * 36 + seg, kb + (sb + 2) * 1024 + tid * 4);
            cpa16(Vs + slot * 1152 + row * 36 + seg, vtb + row * 256 + (sb + 2) * 32 + seg);
        }
        asm volatile("cp.async.commit_group;");

        const float* Kb = Ks + (sb % 3) * 1152;
        const float* Vb = Vs + (sb % 3) * 1152;

        float s[2][4][4];
#pragma unroll
        for (int mt = 0; mt < 2; mt++) {
            const float* br0 = bb + (wb + mt * 16 + q) * 256 + sb * 32 + t * 2;
            const float* br1 = br0 + 8 * 256;
#pragma unroll
            for (int nt = 0; nt < 4; nt++) {
                float2 b0 = *(const float2*)(br0 + nt * 8);
                float2 b1 = *(const float2*)(br1 + nt * 8);
                s[mt][nt][0] = b0.x; s[mt][nt][1] = b0.y;
                s[mt][nt][2] = b1.x; s[mt][nt][3] = b1.y;
            }
        }
#pragma unroll
        for (int kc = 0; kc < 4; kc++) {
#pragma unroll
            for (int pr = 0; pr < 2; pr++) {
                unsigned kf[4];
                ldsm4(kf, Kb + (pr * 16 + (g8 >> 1) * 8 + r8) * 36 + kc * 8 + (g8 & 1) * 4);
                mma_tf32(s[0][pr * 2 + 0], qa[0][kc], &kf[0]);
                mma_tf32(s[0][pr * 2 + 1], qa[0][kc], &kf[2]);
                mma_tf32(s[1][pr * 2 + 0], qa[1][kc], &kf[0]);
                mma_tf32(s[1][pr * 2 + 1], qa[1][kc], &kf[2]);
            }
        }

#pragma unroll
        for (int mt = 0; mt < 2; mt++) {
            float mx0 = fmaxf(fmaxf(s[mt][0][0], s[mt][0][1]), fmaxf(s[mt][1][0], s[mt][1][1]));
            float mx1 = fmaxf(fmaxf(s[mt][0][2], s[mt][0][3]), fmaxf(s[mt][1][2], s[mt][1][3]));
            mx0 = fmaxf(mx0, fmaxf(fmaxf(s[mt][2][0], s[mt][2][1]), fmaxf(s[mt][3][0], s[mt][3][1])));
            mx1 = fmaxf(mx1, fmaxf(fmaxf(s[mt][2][2], s[mt][2][3]), fmaxf(s[mt][3][2], s[mt][3][3])));
            mx0 = fmaxf(mx0, __shfl_xor_sync(0xffffffff, mx0, 1));
            mx0 = fmaxf(mx0, __shfl_xor_sync(0xffffffff, mx0, 2));
            mx1 = fmaxf(mx1, __shfl_xor_sync(0xffffffff, mx1, 1));
            mx1 = fmaxf(mx1, __shfl_xor_sync(0xffffffff, mx1, 2));
            const float mn0 = fmaxf(mrow[mt][0], mx0);
            const float mn1 = fmaxf(mrow[mt][1], mx1);
            const float cor0 = ex2(mrow[mt][0] - mn0);
            const float cor1 = ex2(mrow[mt][1] - mn1);
            mrow[mt][0] = mn0; mrow[mt][1] = mn1;
#pragma unroll
            for (int dn = 0; dn < 4; dn++) {
                o[mt][dn][0] *= cor0; o[mt][dn][1] *= cor0;
                o[mt][dn][2] *= cor1; o[mt][dn][3] *= cor1;
            }
            float sm0 = 0.f, sm1 = 0.f;
#pragma unroll
            for (int nt = 0; nt < 4; nt++) {
                float p0 = ex2(s[mt][nt][0] - mn0);
                float p1 = ex2(s[mt][nt][1] - mn0);
                float p2 = ex2(s[mt][nt][2] - mn1);
                float p3 = ex2(s[mt][nt][3] - mn1);
                sm0 += p0 + p1; sm1 += p2 + p3;
                *(float2*)&Pw[(mt * 16 + q) * 36 + nt * 8 + 2 * t] = make_float2(p0, p1);
                *(float2*)&Pw[(mt * 16 + q + 8) * 36 + nt * 8 + 2 * t] = make_float2(p2, p3);
            }
            lrow[mt][0] = lrow[mt][0] * cor0 + sm0;
            lrow[mt][1] = lrow[mt][1] * cor1 + sm1;
        }
        __syncwarp();

#pragma unroll
        for (int kk = 0; kk < 4; kk++) {
            unsigned pa[2][4];
            ldsm4(pa[0], Pw + ((g8 & 1) * 8 + r8) * 36 + kk * 8 + (g8 >> 1) * 4);
            ldsm4(pa[1], Pw + (16 + (g8 & 1) * 8 + r8) * 36 + kk * 8 + (g8 >> 1) * 4);
            unsigned vf0[4], vf1[4];
            ldsm4(vf0, Vb + ((g8 >> 1) * 8 + r8) * 36 + kk * 8 + (g8 & 1) * 4);
            ldsm4(vf1, Vb + ((2 + (g8 >> 1)) * 8 + r8) * 36 + kk * 8 + (g8 & 1) * 4);
            mma_tf32(o[0][0], pa[0], &vf0[0]);
            mma_tf32(o[0][1], pa[0], &vf0[2]);
            mma_tf32(o[0][2], pa[0], &vf1[0]);
            mma_tf32(o[0][3], pa[0], &vf1[2]);
            mma_tf32(o[1][0], pa[1], &vf0[0]);
            mma_tf32(o[1][1], pa[1], &vf0[2]);
            mma_tf32(o[1][2], pa[1], &vf1[0]);
            mma_tf32(o[1][3], pa[1], &vf1[2]);
        }
        __syncwarp();
    }

    const int bimg = win >> 6, wh = (win >> 3) & 7, ww = win & 7;
#pragma unroll
    for (int mt = 0; mt < 2; mt++) {
        float l0 = lrow[mt][0], l1 = lrow[mt][1];
        l0 += __shfl_xor_sync(0xffffffff, l0, 1);
        l0 += __shfl_xor_sync(0xffffffff, l0, 2);
        l1 += __shfl_xor_sync(0xffffffff, l1, 1);
        l1 += __shfl_xor_sync(0xffffffff, l1, 2);
        const float inv0 = 1.f / l0;
        const float inv1 = 1.f / l1;
        const int tk0 = wb + mt * 16 + q;
#pragma unroll
        for (int half = 0; half < 2; half++) {
            const int tk = tk0 + half * 8;
            const float inv = half ? inv1 : inv0;
            const int gr = wh * 16 + (tk >> 4), gc = ww * 16 + (tk & 15);
            float* op = g_o + ((bimg * 128 + gr) * 128 + gc) * 256 + hd * 32;
#pragma unroll
            for (int dn = 0; dn < 4; dn++) {
                float a = to_tf32(o[mt][dn][half * 2] * inv);
                float b = to_tf32(o[mt][dn][half * 2 + 1] * inv);
                *(float2*)(op + dn * 8 + t * 2) = make_float2(a, b);
            }
        }
    }
}

// ---------------------------------------------------------------------------
extern "C" void kernel_launch(void* const* d_in, const int* in_sizes, int n_in,
                              void* d_out, int out_size) {
    (void)in_sizes; (void)n_in; (void)out_size;
    const float* x_wsa      = (const float*)d_in[0];
    const float* x_original = (const float*)d_in[1];
    const float* q_w        = (const float*)d_in[2];
    const float* q_b        = (const float*)d_in[3];
    const float* kv_w       = (const float*)d_in[4];
    const float* kv_b       = (const float*)d_in[5];
    const float* out_w      = (const float*)d_in[6];
    const float* out_b      = (const float*)d_in[7];
    const float* bias_table = (const float*)d_in[8];
    const float* rezero     = (const float*)d_in[9];
    float* out = (float*)d_out;

    cudaFuncSetAttribute(convkv_mma, cudaFuncAttributeMaxDynamicSharedMemorySize, CONV_SMEM_B);
    cudaFuncSetAttribute(gemm_mma<0>, cudaFuncAttributeMaxDynamicSharedMemorySize, GEMM_SMEM_B0);
    cudaFuncSetAttribute(gemm_mma<1>, cudaFuncAttributeMaxDynamicSharedMemorySize, GEMM_SMEM_B1);
    cudaFuncSetAttribute(attn_mma, cudaFuncAttributeMaxDynamicSharedMemorySize, ATT_SMEM_B);

    prep_misc<<<2560, 256>>>(bias_table, q_w, out_w);           // #1
    prep_conv_w<<<1600, 256>>>(kv_w);                           // #2
    gemm_mma<0><<<dim3(512, 4), 256, GEMM_SMEM_B0>>>(x_wsa, q_b, nullptr, nullptr);  // #3
    convkv_mma<<<dim3(64, 32), 256, CONV_SMEM_B>>>(x_original, kv_b);                // #4 <- profiled
    attn_mma<<<dim3(256, 8), 256, ATT_SMEM_B>>>();                                   // #5
    gemm_mma<1><<<dim3(512, 4), 256, GEMM_SMEM_B1>>>(nullptr, out_b, rezero, out);   // #6
}

// round 13
// speedup vs baseline: 2.1774x; 1.1701x over previous
#include <cuda_runtime.h>
#include <cuda_fp16.h>

// B=4, H=W=128, C=256, heads=8, d=32, win=16 -> 256 windows x 256 tokens
// Scratch (fp16): g_qh [win][head][tok][d]; g_kh [win][head][key][d];
//                 g_vh TRANSPOSED [win][head][d][key]. g_o stays fp32.
__device__ __half g_qh[16777216];
__device__ __half g_kh[16777216];
__device__ __half g_vh[16777216];
__device__ float g_o[16777216];
__device__ float g_bias[524288];    // [head][256 q][256 k], pre-scaled by log2(e)
__device__ float g_wt[133120];      // 2 x [256 n][260 pitch k]: tf32(qw^T), tf32(ow^T)
__device__ __half g_wcth[204800];   // conv weights fp16: [(g*64+oc)][25 taps * 32 k] pitch 800

__device__ __forceinline__ float to_tf32(float x) {
    unsigned u;
    asm("cvt.rna.tf32.f32 %0, %1;" : "=r"(u) : "f"(x));
    return __uint_as_float(u);
}

__device__ __forceinline__ float ex2(float x) {
    float r;
    asm("ex2.approx.ftz.f32 %0, %1;" : "=f"(r) : "f"(x));
    return r;
}

__device__ __forceinline__ void mma_tf32b(float* c, const unsigned* a, unsigned b0, unsigned b1) {
    asm volatile(
        "mma.sync.aligned.m16n8k8.row.col.f32.tf32.tf32.f32 "
        "{%0,%1,%2,%3},{%4,%5,%6,%7},{%8,%9},{%0,%1,%2,%3};"
        : "+f"(c[0]), "+f"(c[1]), "+f"(c[2]), "+f"(c[3])
        : "r"(a[0]), "r"(a[1]), "r"(a[2]), "r"(a[3]), "r"(b0), "r"(b1));
}

// fp16 mma m16n8k16, fp32 accumulate (fp16 mantissa == tf32 mantissa: 10 bits)
__device__ __forceinline__ void mma_f16(float* c, const unsigned* a, unsigned b0, unsigned b1) {
    asm volatile(
        "mma.sync.aligned.m16n8k16.row.col.f32.f16.f16.f32 "
        "{%0,%1,%2,%3},{%4,%5,%6,%7},{%8,%9},{%0,%1,%2,%3};"
        : "+f"(c[0]), "+f"(c[1]), "+f"(c[2]), "+f"(c[3])
        : "r"(a[0]), "r"(a[1]), "r"(a[2]), "r"(a[3]), "r"(b0), "r"(b1));
}

__device__ __forceinline__ void ldsm4(unsigned* r, const float* p) {
    unsigned a = (unsigned)__cvta_generic_to_shared(p);
    asm volatile("ldmatrix.sync.aligned.m8n8.x4.shared.b16 {%0,%1,%2,%3}, [%4];"
                 : "=r"(r[0]), "=r"(r[1]), "=r"(r[2]), "=r"(r[3]) : "r"(a));
}
__device__ __forceinline__ void ldsm4h(unsigned* r, const __half* p) {
    unsigned a = (unsigned)__cvta_generic_to_shared(p);
    asm volatile("ldmatrix.sync.aligned.m8n8.x4.shared.b16 {%0,%1,%2,%3}, [%4];"
                 : "=r"(r[0]), "=r"(r[1]), "=r"(r[2]), "=r"(r[3]) : "r"(a));
}

__device__ __forceinline__ void cpa16(float* dst, const float* src) {
    unsigned d = (unsigned)__cvta_generic_to_shared(dst);
    asm volatile("cp.async.cg.shared.global [%0], [%1], 16;" :: "r"(d), "l"(src));
}
__device__ __forceinline__ void cpa16h(__half* dst, const __half* src) {
    unsigned d = (unsigned)__cvta_generic_to_shared(dst);
    asm volatile("cp.async.cg.shared.global [%0], [%1], 16;" :: "r"(d), "l"(src));
}

// ---------------------------------------------------------------------------
// Prep (ONE kernel): bias expansion + GEMM weight transposes + conv weights.
// ---------------------------------------------------------------------------
__global__ void prep_all(const float* __restrict__ bt,
                         const float* __restrict__ qw,
                         const float* __restrict__ ow,
                         const float* __restrict__ Wc) {
    const int idx = blockIdx.x * 256 + threadIdx.x;
    if (idx < 524288) {
        const int hd = idx >> 16, qt = (idx >> 8) & 255, kt = idx & 255;
        const int qy = qt >> 4, qx = qt & 15, ky = kt >> 4, kx = kt & 15;
        const int rel = (qy - ky + 15) * 31 + (qx - kx + 15);
        g_bias[idx] = bt[rel * 8 + hd] * 1.4426950408889634f;
    } else if (idx < 655360) {
        const int i2 = idx - 524288;
        const int slot = i2 >> 16;
        const int r = i2 & 65535;
        const int n = r >> 8, k = r & 255;
        const float* W = slot ? ow : qw;
        g_wt[slot * 66560 + n * 260 + k] = to_tf32(W[k * 256 + n]);
    } else {
        const int i3 = idx - 655360;           // 0..409599
        const int k = i3 & 31;
        const int tap = (i3 >> 5) % 25;
        const int ocg = i3 / 800;
        const int g = ocg >> 6, oc = ocg & 63;
        g_wcth[ocg * 800 + tap * 32 + k] = __float2half_rn(Wc[(tap * 32 + k) * 512 + g * 64 + oc]);
    }
}

// ---------------------------------------------------------------------------
// Conv 5x5 grouped (pad 2, groups=8) — fp16 mma m16n8k16 (R12 mainloop).
// Epilogue now writes fp16: K [key][d], V transposed [d][key].
// ---------------------------------------------------------------------------
#define CONV_PATCH_H 16000    // 400 * 40 halfs
#define CONV_WTAP_H  2560     // 64 oc * 40 halfs
#define CONV_WPAIR_H (2*CONV_WTAP_H)
#define CONV_SMEM_B  (CONV_PATCH_H*2 + 3*CONV_WPAIR_H*2)   // 62720 B

__global__ __launch_bounds__(256, 2) void convkv_mma(const float* __restrict__ X,
                                                     const float* __restrict__ bias) {
    extern __shared__ char smc[];
    __half* patch = (__half*)smc;
    __half* wring = patch + CONV_PATCH_H;

    const int tid = threadIdx.x;
    const int lane = tid & 31, warp = tid >> 5;
    const int wm = warp & 3, wn = warp >> 2;
    const int g8 = lane >> 3, r8 = lane & 7;
    const int tile = blockIdx.x;
    const int ty0 = (tile >> 3) * 16, tx0 = (tile & 7) * 16;
    const int b = blockIdx.y >> 3, g = blockIdx.y & 7;

    const __half* wsrc = g_wcth + (g * 64) * 800;

#pragma unroll
    for (int pr = 0; pr < 2; pr++) {
#pragma unroll
        for (int c = 0; c < 2; c++) {
            const int idx = c * 256 + tid;
            const int t2 = idx >> 8, rest = idx & 255;
            const int row = rest >> 2, seg = (rest & 3) * 8;
            cpa16h(wring + pr * CONV_WPAIR_H + t2 * CONV_WTAP_H + row * 40 + seg,
                   wsrc + row * 800 + (pr * 2 + t2) * 32 + seg);
        }
        asm volatile("cp.async.commit_group;");
    }

    for (int p = tid; p < 400; p += 256) {
        int py = p / 20, px = p - py * 20;
        int gy = ty0 + py - 2, gx = tx0 + px - 2;
        bool ok = (gy >= 0 && gy < 128 && gx >= 0 && gx < 128);
        const float4* src = (const float4*)(X + ((b * 128 + gy) * 128 + gx) * 256 + g * 32);
#pragma unroll
        for (int s = 0; s < 4; s++) {
            float4 v0 = ok ? src[s * 2]     : make_float4(0.f, 0.f, 0.f, 0.f);
            float4 v1 = ok ? src[s * 2 + 1] : make_float4(0.f, 0.f, 0.f, 0.f);
            __half2 h0 = __floats2half2_rn(v0.x, v0.y);
            __half2 h1 = __floats2half2_rn(v0.z, v0.w);
            __half2 h2 = __floats2half2_rn(v1.x, v1.y);
            __half2 h3 = __floats2half2_rn(v1.z, v1.w);
            uint4 u;
            u.x = *(unsigned*)&h0; u.y = *(unsigned*)&h1;
            u.z = *(unsigned*)&h2; u.w = *(unsigned*)&h3;
            *(uint4*)&patch[p * 40 + s * 8] = u;
        }
    }

    float acc[4][4][4] = {};

#pragma unroll 1
    for (int rnd = 0; rnd < 13; rnd++) {
        if (rnd < 11) asm volatile("cp.async.wait_group 1;");
        else          asm volatile("cp.async.wait_group 0;");
        __syncthreads();
        if (rnd < 11) {
            const int np = rnd + 2;
            __half* dst = wring + (np % 3) * CONV_WPAIR_H;
#pragma unroll
            for (int c = 0; c < 2; c++) {
                const int idx = c * 256 + tid;
                const int t2 = idx >> 8, rest = idx & 255;
                const int row = rest >> 2, seg = (rest & 3) * 8;
                const int tap = np * 2 + t2;
                if (tap < 25)
                    cpa16h(dst + t2 * CONV_WTAP_H + row * 40 + seg,
                           wsrc + row * 800 + tap * 32 + seg);
            }
            asm volatile("cp.async.commit_group;");
        } else {
            asm volatile("cp.async.commit_group;");
        }

#pragma unroll
        for (int t2 = 0; t2 < 2; t2++) {
            const int tap = rnd * 2 + t2;
            if (tap < 25) {
                const int ky = tap / 5, kx = tap - ky * 5;
                const __half* wcur = wring + (rnd % 3) * CONV_WPAIR_H + t2 * CONV_WTAP_H;
#pragma unroll
                for (int kc = 0; kc < 2; kc++) {
                    unsigned a[4][4];
#pragma unroll
                    for (int i = 0; i < 4; i++) {
                        const __half* ap = patch
                            + ((wm * 4 + i + ky) * 20 + (g8 & 1) * 8 + r8 + kx) * 40
                            + kc * 16 + (g8 >> 1) * 8;
                        ldsm4h(a[i], ap);
                    }
                    unsigned bf0[4], bf1[4];
                    ldsm4h(bf0, wcur + (wn * 32 + (g8 & 1) * 8 + r8) * 40 + kc * 16 + (g8 >> 1) * 8);
                    ldsm4h(bf1, wcur + (wn * 32 + 16 + (g8 & 1) * 8 + r8) * 40 + kc * 16 + (g8 >> 1) * 8);
#pragma unroll
                    for (int i = 0; i < 4; i++) {
                        mma_f16(acc[i][0], a[i], bf0[0], bf0[2]);
                        mma_f16(acc[i][1], a[i], bf0[1], bf0[3]);
                        mma_f16(acc[i][2], a[i], bf1[0], bf1[2]);
                        mma_f16(acc[i][3], a[i], bf1[1], bf1[3]);
                    }
                }
            }
        }
    }

    const int win = b * 64 + (tile >> 3) * 8 + (tile & 7);
    const int head = (g & 3) * 2 + wn;
    if (g < 4) {   // K: [key][d] fp16
        __half* base = g_kh + ((win * 8 + head) * 256) * 32;
#pragma unroll
        for (int i = 0; i < 4; i++) {
            const int p0 = wm * 64 + i * 16 + (lane >> 2);
#pragma unroll
            for (int j = 0; j < 4; j++) {
                const int col = wn * 32 + j * 8 + (lane & 3) * 2;
                const int d = col & 31;
                float b0 = bias[g * 64 + col], b1 = bias[g * 64 + col + 1];
                *(__half2*)(base + p0 * 32 + d) =
                    __floats2half2_rn(acc[i][j][0] + b0, acc[i][j][1] + b1);
                *(__half2*)(base + (p0 + 8) * 32 + d) =
                    __floats2half2_rn(acc[i][j][2] + b0, acc[i][j][3] + b1);
            }
        }
    } else {       // V transposed: [d][key] fp16
        __half* base = g_vh + ((win * 8 + head) * 32) * 256;
#pragma unroll
        for (int i = 0; i < 4; i++) {
            const int p0 = wm * 64 + i * 16 + (lane >> 2);
#pragma unroll
            for (int j = 0; j < 4; j++) {
                const int col = wn * 32 + j * 8 + (lane & 3) * 2;
                const int d0 = col & 31;
                float b0 = bias[g * 64 + col], b1 = bias[g * 64 + col + 1];
                base[d0 * 256 + p0]           = __float2half_rn(acc[i][j][0] + b0);
                base[(d0 + 1) * 256 + p0]     = __float2half_rn(acc[i][j][1] + b1);
                base[d0 * 256 + p0 + 8]       = __float2half_rn(acc[i][j][2] + b0);
                base[(d0 + 1) * 256 + p0 + 8] = __float2half_rn(acc[i][j][3] + b1);
            }
        }
    }
}

// ---------------------------------------------------------------------------
// tf32 GEMM: MODE 0 qproj (-> g_qh fp16), MODE 1 outproj (g_o -> out).
// ---------------------------------------------------------------------------
#define GEMM_A_FL 4608
#define GEMM_B_FL 2304
#define GEMM_SLOT_FL (GEMM_A_FL + GEMM_B_FL)
#define GEMM_SMEM_B0 ((2*GEMM_A_FL + 3*GEMM_B_FL) * 4)
#define GEMM_SMEM_B1 ((3*GEMM_SLOT_FL) * 4)

template <int MODE>
__global__ __launch_bounds__(256, 2) void gemm_mma(const float* __restrict__ Aparam,
                                                   const float* __restrict__ bias,
                                                   const float* __restrict__ rz,
                                                   float* __restrict__ out) {
    extern __shared__ float smem[];

    const float* A = (MODE == 1) ? (const float*)g_o : Aparam;
    const float* wt = g_wt + MODE * 66560;

    const int tid = threadIdx.x;
    const int lane = tid & 31, warp = tid >> 5;
    const int wm = warp & 3, wn = warp >> 2;
    const int g8 = lane >> 3, r8 = lane & 7;
    const int m0 = blockIdx.x * 128;
    const int n0 = blockIdx.y * 64;

    const int arow = tid >> 1, akoff = (tid & 1) * 16;

#pragma unroll
    for (int c0 = 0; c0 < 2; c0++) {
        if (MODE == 1) {
            float* sa = smem + c0 * GEMM_SLOT_FL;
#pragma unroll
            for (int c = 0; c < 4; c++) {
                const int idx = c * 256 + tid;
                cpa16(sa + (idx >> 3) * 36 + (idx & 7) * 4,
                      A + (m0 + (idx >> 3)) * 256 + c0 * 32 + (idx & 7) * 4);
            }
            float* sb = sa + GEMM_A_FL;
#pragma unroll
            for (int c = 0; c < 2; c++) {
                const int idx = c * 256 + tid;
                cpa16(sb + (idx >> 3) * 36 + (idx & 7) * 4,
                      wt + (n0 + (idx >> 3)) * 260 + c0 * 32 + (idx & 7) * 4);
            }
        } else {
            float* sb = smem + 2 * GEMM_A_FL + c0 * GEMM_B_FL;
#pragma unroll
            for (int c = 0; c < 2; c++) {
                const int idx = c * 256 + tid;
                cpa16(sb + (idx >> 3) * 36 + (idx & 7) * 4,
                      wt + (n0 + (idx >> 3)) * 260 + c0 * 32 + (idx & 7) * 4);
            }
        }
        asm volatile("cp.async.commit_group;");
    }

    if (MODE == 0) {
        const float4* ga = (const float4*)(A + (m0 + arow) * 256 + akoff);
        float* da = smem + arow * 36 + akoff;
#pragma unroll
        for (int c4 = 0; c4 < 4; c4++) {
            float4 v = ga[c4];
            *(float4*)(da + c4 * 4) = make_float4(to_tf32(v.x), to_tf32(v.y), to_tf32(v.z), to_tf32(v.w));
        }
    }

    float acc[2][4][4] = {};

#pragma unroll 1
    for (int kt = 0; kt < 8; kt++) {
        float4 pa[4];
        if (MODE == 0 && kt < 7) {
            const float4* ga = (const float4*)(A + (m0 + arow) * 256 + (kt + 1) * 32 + akoff);
#pragma unroll
            for (int c4 = 0; c4 < 4; c4++) pa[c4] = ga[c4];
        }
        if (kt < 6) asm volatile("cp.async.wait_group 1;");
        else        asm volatile("cp.async.wait_group 0;");
        __syncthreads();
        if (kt < 6) {
            const int nt = kt + 2;
            if (MODE == 1) {
                float* sa = smem + (nt % 3) * GEMM_SLOT_FL;
#pragma unroll
                for (int c = 0; c < 4; c++) {
                    const int idx = c * 256 + tid;
                    cpa16(sa + (idx >> 3) * 36 + (idx & 7) * 4,
                          A + (m0 + (idx >> 3)) * 256 + nt * 32 + (idx & 7) * 4);
                }
                float* sb = sa + GEMM_A_FL;
#pragma unroll
                for (int c = 0; c < 2; c++) {
                    const int idx = c * 256 + tid;
                    cpa16(sb + (idx >> 3) * 36 + (idx & 7) * 4,
                          wt + (n0 + (idx >> 3)) * 260 + nt * 32 + (idx & 7) * 4);
                }
            } else {
                float* sb = smem + 2 * GEMM_A_FL + (nt % 3) * GEMM_B_FL;
#pragma unroll
                for (int c = 0; c < 2; c++) {
                    const int idx = c * 256 + tid;
                    cpa16(sb + (idx >> 3) * 36 + (idx & 7) * 4,
                          wt + (n0 + (idx >> 3)) * 260 + nt * 32 + (idx & 7) * 4);
                }
            }
            asm volatile("cp.async.commit_group;");
        }
        const float* acur = (MODE == 1) ? (smem + (kt % 3) * GEMM_SLOT_FL)
                                        : (smem + (kt & 1) * GEMM_A_FL);
        const float* bcur = (MODE == 1) ? (smem + (kt % 3) * GEMM_SLOT_FL + GEMM_A_FL)
                                        : (smem + 2 * GEMM_A_FL + (kt % 3) * GEMM_B_FL);
#pragma unroll
        for (int kc = 0; kc < 4; kc++) {
            unsigned a[2][4];
#pragma unroll
            for (int i = 0; i < 2; i++) {
                const float* ap = acur + (wm * 32 + i * 16 + (g8 & 1) * 8 + r8) * 36
                                  + kc * 8 + (g8 >> 1) * 4;
                ldsm4(a[i], ap);
            }
            unsigned bfa[4], bfb[4];
            ldsm4(bfa, bcur + (wn * 32 + g8 * 8 + r8) * 36 + kc * 8);
            ldsm4(bfb, bcur + (wn * 32 + g8 * 8 + r8) * 36 + kc * 8 + 4);
#pragma unroll
            for (int j = 0; j < 4; j++)
#pragma unroll
                for (int i = 0; i < 2; i++) mma_tf32b(acc[i][j], a[i], bfa[j], bfb[j]);
        }
        if (MODE == 0 && kt < 7) {
            float* da = smem + ((kt + 1) & 1) * GEMM_A_FL + arow * 36 + akoff;
#pragma unroll
            for (int c4 = 0; c4 < 4; c4++)
                *(float4*)(da + c4 * 4) = make_float4(to_tf32(pa[c4].x), to_tf32(pa[c4].y),
                                                      to_tf32(pa[c4].z), to_tf32(pa[c4].w));
        }
    }

    const float scale = 0.17677669529663687f * 1.4426950408889634f;
    const float r = (MODE == 1) ? rz[0] : 0.f;
#pragma unroll
    for (int i = 0; i < 2; i++) {
        const int m = m0 + wm * 32 + i * 16 + (lane >> 2);
#pragma unroll
        for (int j = 0; j < 4; j++) {
            const int col = n0 + wn * 32 + j * 8 + (lane & 3) * 2;
            const float b0 = bias[col], b1 = bias[col + 1];
            if (MODE == 0) {
                const int bi = m >> 14, rr = (m >> 7) & 127, cc = m & 127;
                const int win = bi * 64 + ((rr >> 4) << 3) + (cc >> 4);
                const int t = (rr & 15) * 16 + (cc & 15);
                const int head = col >> 5, d = col & 31;
                __half* p = g_qh + ((win * 8 + head) * 256 + t) * 32 + d;
                *(__half2*)p = __floats2half2_rn((acc[i][j][0] + b0) * scale,
                                                 (acc[i][j][1] + b1) * scale);
                *(__half2*)(p + 8 * 32) = __floats2half2_rn((acc[i][j][2] + b0) * scale,
                                                            (acc[i][j][3] + b1) * scale);
            } else {
                float* p = out + m * 256 + col;
                *(float2*)p = make_float2(r * (acc[i][j][0] + b0), r * (acc[i][j][1] + b1));
                *(float2*)(p + 8 * 256) = make_float2(r * (acc[i][j][2] + b0), r * (acc[i][j][3] + b1));
            }
        }
    }
}

// ---------------------------------------------------------------------------
// fp16 flash attention (R7 structure, m16n8k16): mma/ldsm/traffic all halved.
// Pitch 40 halfs (80B rows) -> ldmatrix conflict-free. Softmax stays fp32.
// ---------------------------------------------------------------------------
#define ATT_QS_H 10240          // 256*40
#define ATT_KS_H (3*1280)       // 3 stages * 32*40
#define ATT_VS_H (3*1280)
#define ATT_PS_H 10240          // 8 warps * 32*40
#define ATT_SMEM_B ((ATT_QS_H + ATT_KS_H + ATT_VS_H + ATT_PS_H) * 2)  // 56320 B

__global__ __launch_bounds__(256, 2) void attn_mma() {
    extern __shared__ char smc[];
    __half* Qs = (__half*)smc;
    __half* Ks = Qs + ATT_QS_H;
    __half* Vs = Ks + ATT_KS_H;
    __half* Ps = Vs + ATT_VS_H;

    const int win = blockIdx.x, hd = blockIdx.y;
    const int tid = threadIdx.x;
    const int lane = tid & 31, warp = tid >> 5;
    const int q = lane >> 2, t = lane & 3;
    const int g8 = lane >> 3, r8 = lane & 7;
    const int wb = warp * 32;
    __half* Pw = Ps + warp * 1280;

    const __half* qh = g_qh + (win * 8 + hd) * 8192;
    const __half* kh = g_kh + (win * 8 + hd) * 8192;
    const __half* vth = g_vh + (win * 8 + hd) * 8192;   // [32 d][256 key]
    const float* bb = g_bias + (hd << 16);

    // Stage Q (plain LDG.128)
#pragma unroll
    for (int c = 0; c < 4; c++) {
        const int i = c * 256 + tid;             // 0..1023
        const int row = i >> 2, seg = (i & 3) * 8;
        *(uint4*)&Qs[row * 40 + seg] = *(const uint4*)&qh[row * 32 + seg];
    }
    // K/V chunks 0,1 via cp.async (tid<128: K, tid>=128: V; 1 cpa16/thread)
    {
        const int r = (tid & 127) >> 2, sg = (tid & 3) * 8;
#pragma unroll
        for (int c = 0; c < 2; c++) {
            if (tid < 128) cpa16h(Ks + c * 1280 + r * 40 + sg, kh + (c * 32 + r) * 32 + sg);
            else           cpa16h(Vs + c * 1280 + r * 40 + sg, vth + r * 256 + c * 32 + sg);
            asm volatile("cp.async.commit_group;");
        }
    }
    __syncthreads();

    // Q fragments -> registers (once): 2 mt x 2 kc(k16) x 4 regs
    unsigned qa[2][2][4];
#pragma unroll
    for (int mt = 0; mt < 2; mt++)
#pragma unroll
        for (int kc = 0; kc < 2; kc++)
            ldsm4h(qa[mt][kc], Qs + (wb + mt * 16 + (g8 & 1) * 8 + r8) * 40 + kc * 16 + (g8 >> 1) * 8);

    float o[2][4][4] = {};
    float mrow[2][2] = {{-1e30f, -1e30f}, {-1e30f, -1e30f}};
    float lrow[2][2] = {};

#pragma unroll 1
    for (int sb = 0; sb < 8; sb++) {
        asm volatile("cp.async.wait_group 1;");
        __syncthreads();

        if (sb < 6) {
            const int slot = (sb + 2) % 3;
            const int r = (tid & 127) >> 2, sg = (tid & 3) * 8;
            if (tid < 128) cpa16h(Ks + slot * 1280 + r * 40 + sg, kh + ((sb + 2) * 32 + r) * 32 + sg);
            else           cpa16h(Vs + slot * 1280 + r * 40 + sg, vth + r * 256 + (sb + 2) * 32 + sg);
        }
        asm volatile("cp.async.commit_group;");

        const __half* Kb = Ks + (sb % 3) * 1280;
        const __half* Vb = Vs + (sb % 3) * 1280;

        // ---- S = Q K^T (fp16 k16), bias as accumulator init ----
        float s[2][4][4];
#pragma unroll
        for (int mt = 0; mt < 2; mt++) {
            const float* br0 = bb + (wb + mt * 16 + q) * 256 + sb * 32 + t * 2;
            const float* br1 = br0 + 8 * 256;
#pragma unroll
            for (int nt = 0; nt < 4; nt++) {
                float2 b0 = *(const float2*)(br0 + nt * 8);
                float2 b1 = *(const float2*)(br1 + nt * 8);
                s[mt][nt][0] = b0.x; s[mt][nt][1] = b0.y;
                s[mt][nt][2] = b1.x; s[mt][nt][3] = b1.y;
            }
        }
#pragma unroll
        for (int kc = 0; kc < 2; kc++) {
#pragma unroll
            for (int nt16 = 0; nt16 < 2; nt16++) {
                unsigned kf[4];
                ldsm4h(kf, Kb + (nt16 * 16 + (g8 & 1) * 8 + r8) * 40 + kc * 16 + (g8 >> 1) * 8);
                mma_f16(s[0][nt16 * 2 + 0], qa[0][kc], kf[0], kf[2]);
                mma_f16(s[0][nt16 * 2 + 1], qa[0][kc], kf[1], kf[3]);
                mma_f16(s[1][nt16 * 2 + 0], qa[1][kc], kf[0], kf[2]);
                mma_f16(s[1][nt16 * 2 + 1], qa[1][kc], kf[1], kf[3]);
            }
        }

        // ---- online softmax per m-tile; P -> warp-private smem (fp16) ----
#pragma unroll
        for (int mt = 0; mt < 2; mt++) {
            float mx0 = fmaxf(fmaxf(s[mt][0][0], s[mt][0][1]), fmaxf(s[mt][1][0], s[mt][1][1]));
            float mx1 = fmaxf(fmaxf(s[mt][0][2], s[mt][0][3]), fmaxf(s[mt][1][2], s[mt][1][3]));
            mx0 = fmaxf(mx0, fmaxf(fmaxf(s[mt][2][0], s[mt][2][1]), fmaxf(s[mt][3][0], s[mt][3][1])));
            mx1 = fmaxf(mx1, fmaxf(fmaxf(s[mt][2][2], s[mt][2][3]), fmaxf(s[mt][3][2], s[mt][3][3])));
            mx0 = fmaxf(mx0, __shfl_xor_sync(0xffffffff, mx0, 1));
            mx0 = fmaxf(mx0, __shfl_xor_sync(0xffffffff, mx0, 2));
            mx1 = fmaxf(mx1, __shfl_xor_sync(0xffffffff, mx1, 1));
            mx1 = fmaxf(mx1, __shfl_xor_sync(0xffffffff, mx1, 2));
            const float mn0 = fmaxf(mrow[mt][0], mx0);
            const float mn1 = fmaxf(mrow[mt][1], mx1);
            const float cor0 = ex2(mrow[mt][0] - mn0);
            const float cor1 = ex2(mrow[mt][1] - mn1);
            mrow[mt][0] = mn0; mrow[mt][1] = mn1;
#pragma unroll
            for (int dn = 0; dn < 4; dn++) {
                o[mt][dn][0] *= cor0; o[mt][dn][1] *= cor0;
                o[mt][dn][2] *= cor1; o[mt][dn][3] *= cor1;
            }
            float sm0 = 0.f, sm1 = 0.f;
#pragma unroll
            for (int nt = 0; nt < 4; nt++) {
                float p0 = ex2(s[mt][nt][0] - mn0);
                float p1 = ex2(s[mt][nt][1] - mn0);
                float p2 = ex2(s[mt][nt][2] - mn1);
                float p3 = ex2(s[mt][nt][3] - mn1);
                sm0 += p0 + p1; sm1 += p2 + p3;
                *(__half2*)&Pw[(mt * 16 + q) * 40 + nt * 8 + 2 * t] = __floats2half2_rn(p0, p1);
                *(__half2*)&Pw[(mt * 16 + q + 8) * 40 + nt * 8 + 2 * t] = __floats2half2_rn(p2, p3);
            }
            lrow[mt][0] = lrow[mt][0] * cor0 + sm0;
            lrow[mt][1] = lrow[mt][1] * cor1 + sm1;
        }
        __syncwarp();

        // ---- O += P V (fp16 k16) ----
#pragma unroll
        for (int kk = 0; kk < 2; kk++) {
            unsigned pa[2][4];
            ldsm4h(pa[0], Pw + ((g8 & 1) * 8 + r8) * 40 + kk * 16 + (g8 >> 1) * 8);
            ldsm4h(pa[1], Pw + (16 + (g8 & 1) * 8 + r8) * 40 + kk * 16 + (g8 >> 1) * 8);
#pragma unroll
            for (int dn16 = 0; dn16 < 2; dn16++) {
                unsigned vf[4];
                ldsm4h(vf, Vb + (dn16 * 16 + (g8 & 1) * 8 + r8) * 40 + kk * 16 + (g8 >> 1) * 8);
                mma_f16(o[0][dn16 * 2 + 0], pa[0], vf[0], vf[2]);
                mma_f16(o[0][dn16 * 2 + 1], pa[0], vf[1], vf[3]);
                mma_f16(o[1][dn16 * 2 + 0], pa[1], vf[0], vf[2]);
                mma_f16(o[1][dn16 * 2 + 1], pa[1], vf[1], vf[3]);
            }
        }
        __syncwarp();
    }

    // Epilogue: reduce l partials, normalize, write tf32-rounded fp32 g_o
    const int bimg = win >> 6, wh = (win >> 3) & 7, ww = win & 7;
#pragma unroll
    for (int mt = 0; mt < 2; mt++) {
        float l0 = lrow[mt][0], l1 = lrow[mt][1];
        l0 += __shfl_xor_sync(0xffffffff, l0, 1);
        l0 += __shfl_xor_sync(0xffffffff, l0, 2);
        l1 += __shfl_xor_sync(0xffffffff, l1, 1);
        l1 += __shfl_xor_sync(0xffffffff, l1, 2);
        const float inv0 = 1.f / l0;
        const float inv1 = 1.f / l1;
        const int tk0 = wb + mt * 16 + q;
#pragma unroll
        for (int half = 0; half < 2; half++) {
            const int tk = tk0 + half * 8;
            const float inv = half ? inv1 : inv0;
            const int gr = wh * 16 + (tk >> 4), gc = ww * 16 + (tk & 15);
            float* op = g_o + ((bimg * 128 + gr) * 128 + gc) * 256 + hd * 32;
#pragma unroll
            for (int dn = 0; dn < 4; dn++) {
                float a = to_tf32(o[mt][dn][half * 2] * inv);
                float b = to_tf32(o[mt][dn][half * 2 + 1] * inv);
                *(float2*)(op + dn * 8 + t * 2) = make_float2(a, b);
            }
        }
    }
}

// ---------------------------------------------------------------------------
extern "C" void kernel_launch(void* const* d_in, const int* in_sizes, int n_in,
                              void* d_out, int out_size) {
    (void)in_sizes; (void)n_in; (void)out_size;
    const float* x_wsa      = (const float*)d_in[0];
    const float* x_original = (const float*)d_in[1];
    const float* q_w        = (const float*)d_in[2];
    const float* q_b        = (const float*)d_in[3];
    const float* kv_w       = (const float*)d_in[4];
    const float* kv_b       = (const float*)d_in[5];
    const float* out_w      = (const float*)d_in[6];
    const float* out_b      = (const float*)d_in[7];
    const float* bias_table = (const float*)d_in[8];
    const float* rezero     = (const float*)d_in[9];
    float* out = (float*)d_out;

    cudaFuncSetAttribute(convkv_mma, cudaFuncAttributeMaxDynamicSharedMemorySize, CONV_SMEM_B);
    cudaFuncSetAttribute(gemm_mma<0>, cudaFuncAttributeMaxDynamicSharedMemorySize, GEMM_SMEM_B0);
    cudaFuncSetAttribute(gemm_mma<1>, cudaFuncAttributeMaxDynamicSharedMemorySize, GEMM_SMEM_B1);
    cudaFuncSetAttribute(attn_mma, cudaFuncAttributeMaxDynamicSharedMemorySize, ATT_SMEM_B);

    prep_all<<<4160, 256>>>(bias_table, q_w, out_w, kv_w);                          // #1
    gemm_mma<0><<<dim3(512, 4), 256, GEMM_SMEM_B0>>>(x_wsa, q_b, nullptr, nullptr); // #2
    convkv_mma<<<dim3(64, 32), 256, CONV_SMEM_B>>>(x_original, kv_b);               // #3
    attn_mma<<<dim3(256, 8), 256, ATT_SMEM_B>>>();                                  // #4 <- profiled
    gemm_mma<1><<<dim3(512, 4), 256, GEMM_SMEM_B1>>>(nullptr, out_b, rezero, out);  // #5
}

// round 14
// speedup vs baseline: 2.3926x; 1.0989x over previous
#include <cuda_runtime.h>
#include <cuda_fp16.h>

// B=4, H=W=128, C=256, heads=8, d=32, win=16 -> 256 windows x 256 tokens
// Scratch (fp16): g_qh [win][head][tok][d]; g_kh [win][head][key][d];
//                 g_vh TRANSPOSED [win][head][d][key]; g_oh [B,H,W,C].
__device__ __half g_qh[16777216];
__device__ __half g_kh[16777216];
__device__ __half g_vh[16777216];
__device__ __half g_oh[16777216];
__device__ float g_bias[524288];    // [head][256 q][256 k], pre-scaled by log2(e)
__device__ __half g_wth[135168];    // 2 x [256 n][264 pitch k] fp16: qw^T, ow^T
__device__ __half g_wcth[204800];   // conv weights fp16: [(g*64+oc)][25 taps * 32 k] pitch 800

__device__ __forceinline__ float ex2(float x) {
    float r;
    asm("ex2.approx.ftz.f32 %0, %1;" : "=f"(r) : "f"(x));
    return r;
}

// fp16 mma m16n8k16, fp32 accumulate (fp16 mantissa == tf32 mantissa: 10 bits)
__device__ __forceinline__ void mma_f16(float* c, const unsigned* a, unsigned b0, unsigned b1) {
    asm volatile(
        "mma.sync.aligned.m16n8k16.row.col.f32.f16.f16.f32 "
        "{%0,%1,%2,%3},{%4,%5,%6,%7},{%8,%9},{%0,%1,%2,%3};"
        : "+f"(c[0]), "+f"(c[1]), "+f"(c[2]), "+f"(c[3])
        : "r"(a[0]), "r"(a[1]), "r"(a[2]), "r"(a[3]), "r"(b0), "r"(b1));
}

__device__ __forceinline__ void ldsm4h(unsigned* r, const __half* p) {
    unsigned a = (unsigned)__cvta_generic_to_shared(p);
    asm volatile("ldmatrix.sync.aligned.m8n8.x4.shared.b16 {%0,%1,%2,%3}, [%4];"
                 : "=r"(r[0]), "=r"(r[1]), "=r"(r[2]), "=r"(r[3]) : "r"(a));
}

__device__ __forceinline__ void cpa16h(__half* dst, const __half* src) {
    unsigned d = (unsigned)__cvta_generic_to_shared(dst);
    asm volatile("cp.async.cg.shared.global [%0], [%1], 16;" :: "r"(d), "l"(src));
}

// ---------------------------------------------------------------------------
// Prep (ONE kernel): bias + fp16 GEMM weight transposes + fp16 conv weights.
// ---------------------------------------------------------------------------
__global__ void prep_all(const float* __restrict__ bt,
                         const float* __restrict__ qw,
                         const float* __restrict__ ow,
                         const float* __restrict__ Wc) {
    const int idx = blockIdx.x * 256 + threadIdx.x;
    if (idx < 524288) {
        const int hd = idx >> 16, qt = (idx >> 8) & 255, kt = idx & 255;
        const int qy = qt >> 4, qx = qt & 15, ky = kt >> 4, kx = kt & 15;
        const int rel = (qy - ky + 15) * 31 + (qx - kx + 15);
        g_bias[idx] = bt[rel * 8 + hd] * 1.4426950408889634f;
    } else if (idx < 655360) {
        const int i2 = idx - 524288;
        const int slot = i2 >> 16;
        const int r = i2 & 65535;
        const int n = r >> 8, k = r & 255;
        const float* W = slot ? ow : qw;
        g_wth[slot * 67584 + n * 264 + k] = __float2half_rn(W[k * 256 + n]);
    } else {
        const int i3 = idx - 655360;           // 0..409599
        const int k = i3 & 31;
        const int tap = (i3 >> 5) % 25;
        const int ocg = i3 / 800;
        const int g = ocg >> 6, oc = ocg & 63;
        g_wcth[ocg * 800 + tap * 32 + k] = __float2half_rn(Wc[(tap * 32 + k) * 512 + g * 64 + oc]);
    }
}

// ---------------------------------------------------------------------------
// Conv 5x5 grouped (pad 2, groups=8) — fp16 mma m16n8k16 (unchanged R13).
// ---------------------------------------------------------------------------
#define CONV_PATCH_H 16000    // 400 * 40 halfs
#define CONV_WTAP_H  2560
#define CONV_WPAIR_H (2*CONV_WTAP_H)
#define CONV_SMEM_B  (CONV_PATCH_H*2 + 3*CONV_WPAIR_H*2)   // 62720 B

__global__ __launch_bounds__(256, 2) void convkv_mma(const float* __restrict__ X,
                                                     const float* __restrict__ bias) {
    extern __shared__ char smc[];
    __half* patch = (__half*)smc;
    __half* wring = patch + CONV_PATCH_H;

    const int tid = threadIdx.x;
    const int lane = tid & 31, warp = tid >> 5;
    const int wm = warp & 3, wn = warp >> 2;
    const int g8 = lane >> 3, r8 = lane & 7;
    const int tile = blockIdx.x;
    const int ty0 = (tile >> 3) * 16, tx0 = (tile & 7) * 16;
    const int b = blockIdx.y >> 3, g = blockIdx.y & 7;

    const __half* wsrc = g_wcth + (g * 64) * 800;

#pragma unroll
    for (int pr = 0; pr < 2; pr++) {
#pragma unroll
        for (int c = 0; c < 2; c++) {
            const int idx = c * 256 + tid;
            const int t2 = idx >> 8, rest = idx & 255;
            const int row = rest >> 2, seg = (rest & 3) * 8;
            cpa16h(wring + pr * CONV_WPAIR_H + t2 * CONV_WTAP_H + row * 40 + seg,
                   wsrc + row * 800 + (pr * 2 + t2) * 32 + seg);
        }
        asm volatile("cp.async.commit_group;");
    }

    for (int p = tid; p < 400; p += 256) {
        int py = p / 20, px = p - py * 20;
        int gy = ty0 + py - 2, gx = tx0 + px - 2;
        bool ok = (gy >= 0 && gy < 128 && gx >= 0 && gx < 128);
        const float4* src = (const float4*)(X + ((b * 128 + gy) * 128 + gx) * 256 + g * 32);
#pragma unroll
        for (int s = 0; s < 4; s++) {
            float4 v0 = ok ? src[s * 2]     : make_float4(0.f, 0.f, 0.f, 0.f);
            float4 v1 = ok ? src[s * 2 + 1] : make_float4(0.f, 0.f, 0.f, 0.f);
            __half2 h0 = __floats2half2_rn(v0.x, v0.y);
            __half2 h1 = __floats2half2_rn(v0.z, v0.w);
            __half2 h2 = __floats2half2_rn(v1.x, v1.y);
            __half2 h3 = __floats2half2_rn(v1.z, v1.w);
            uint4 u;
            u.x = *(unsigned*)&h0; u.y = *(unsigned*)&h1;
            u.z = *(unsigned*)&h2; u.w = *(unsigned*)&h3;
            *(uint4*)&patch[p * 40 + s * 8] = u;
        }
    }

    float acc[4][4][4] = {};

#pragma unroll 1
    for (int rnd = 0; rnd < 13; rnd++) {
        if (rnd < 11) asm volatile("cp.async.wait_group 1;");
        else          asm volatile("cp.async.wait_group 0;");
        __syncthreads();
        if (rnd < 11) {
            const int np = rnd + 2;
            __half* dst = wring + (np % 3) * CONV_WPAIR_H;
#pragma unroll
            for (int c = 0; c < 2; c++) {
                const int idx = c * 256 + tid;
                const int t2 = idx >> 8, rest = idx & 255;
                const int row = rest >> 2, seg = (rest & 3) * 8;
                const int tap = np * 2 + t2;
                if (tap < 25)
                    cpa16h(dst + t2 * CONV_WTAP_H + row * 40 + seg,
                           wsrc + row * 800 + tap * 32 + seg);
            }
            asm volatile("cp.async.commit_group;");
        } else {
            asm volatile("cp.async.commit_group;");
        }

#pragma unroll
        for (int t2 = 0; t2 < 2; t2++) {
            const int tap = rnd * 2 + t2;
            if (tap < 25) {
                const int ky = tap / 5, kx = tap - ky * 5;
                const __half* wcur = wring + (rnd % 3) * CONV_WPAIR_H + t2 * CONV_WTAP_H;
#pragma unroll
                for (int kc = 0; kc < 2; kc++) {
                    unsigned a[4][4];
#pragma unroll
                    for (int i = 0; i < 4; i++) {
                        const __half* ap = patch
                            + ((wm * 4 + i + ky) * 20 + (g8 & 1) * 8 + r8 + kx) * 40
                            + kc * 16 + (g8 >> 1) * 8;
                        ldsm4h(a[i], ap);
                    }
                    unsigned bf0[4], bf1[4];
                    ldsm4h(bf0, wcur + (wn * 32 + (g8 & 1) * 8 + r8) * 40 + kc * 16 + (g8 >> 1) * 8);
                    ldsm4h(bf1, wcur + (wn * 32 + 16 + (g8 & 1) * 8 + r8) * 40 + kc * 16 + (g8 >> 1) * 8);
#pragma unroll
                    for (int i = 0; i < 4; i++) {
                        mma_f16(acc[i][0], a[i], bf0[0], bf0[2]);
                        mma_f16(acc[i][1], a[i], bf0[1], bf0[3]);
                        mma_f16(acc[i][2], a[i], bf1[0], bf1[2]);
                        mma_f16(acc[i][3], a[i], bf1[1], bf1[3]);
                    }
                }
            }
        }
    }

    const int win = b * 64 + (tile >> 3) * 8 + (tile & 7);
    const int head = (g & 3) * 2 + wn;
    if (g < 4) {   // K: [key][d] fp16
        __half* base = g_kh + ((win * 8 + head) * 256) * 32;
#pragma unroll
        for (int i = 0; i < 4; i++) {
            const int p0 = wm * 64 + i * 16 + (lane >> 2);
#pragma unroll
            for (int j = 0; j < 4; j++) {
                const int col = wn * 32 + j * 8 + (lane & 3) * 2;
                const int d = col & 31;
                float b0 = bias[g * 64 + col], b1 = bias[g * 64 + col + 1];
                *(__half2*)(base + p0 * 32 + d) =
                    __floats2half2_rn(acc[i][j][0] + b0, acc[i][j][1] + b1);
                *(__half2*)(base + (p0 + 8) * 32 + d) =
                    __floats2half2_rn(acc[i][j][2] + b0, acc[i][j][3] + b1);
            }
        }
    } else {       // V transposed: [d][key] fp16
        __half* base = g_vh + ((win * 8 + head) * 32) * 256;
#pragma unroll
        for (int i = 0; i < 4; i++) {
            const int p0 = wm * 64 + i * 16 + (lane >> 2);
#pragma unroll
            for (int j = 0; j < 4; j++) {
                const int col = wn * 32 + j * 8 + (lane & 3) * 2;
                const int d0 = col & 31;
                float b0 = bias[g * 64 + col], b1 = bias[g * 64 + col + 1];
                base[d0 * 256 + p0]           = __float2half_rn(acc[i][j][0] + b0);
                base[(d0 + 1) * 256 + p0]     = __float2half_rn(acc[i][j][1] + b1);
                base[d0 * 256 + p0 + 8]       = __float2half_rn(acc[i][j][2] + b0);
                base[(d0 + 1) * 256 + p0 + 8] = __float2half_rn(acc[i][j][3] + b1);
            }
        }
    }
}

// ---------------------------------------------------------------------------
// fp16 GEMM m16n8k16: MODE 0 qproj (x_wsa fp32 -> LDG/cvt/STS A; -> g_qh),
//                     MODE 1 outproj (g_oh fp16 -> pure cp.async A; -> out).
// B fp16 pre-transposed in g_wth -> cp.async ring + ldsm fragments.
// ---------------------------------------------------------------------------
#define GEMM_A_H 5120    // 128 rows * 40 halfs
#define GEMM_B_H 2560    // 64 n * 40 halfs
#define GEMM_SLOT_H (GEMM_A_H + GEMM_B_H)
#define GEMM_SMEM_B0 ((2*GEMM_A_H + 3*GEMM_B_H) * 2)   // 35840 B
#define GEMM_SMEM_B1 ((3*GEMM_SLOT_H) * 2)             // 46080 B

template <int MODE>
__global__ __launch_bounds__(256, 2) void gemm_mma(const float* __restrict__ Aparam,
                                                   const float* __restrict__ bias,
                                                   const float* __restrict__ rz,
                                                   float* __restrict__ out) {
    extern __shared__ char smc[];
    __half* smem = (__half*)smc;

    const float* Af = Aparam;                 // MODE 0 source (fp32)
    const __half* Ah = g_oh;                  // MODE 1 source (fp16)
    const __half* wt = g_wth + MODE * 67584;

    const int tid = threadIdx.x;
    const int lane = tid & 31, warp = tid >> 5;
    const int wm = warp & 3, wn = warp >> 2;
    const int g8 = lane >> 3, r8 = lane & 7;
    const int m0 = blockIdx.x * 128;
    const int n0 = blockIdx.y * 64;

    const int arow = tid >> 1, akoff = (tid & 1) * 16;

    // Prologue: issue chunks 0,1
#pragma unroll
    for (int c0 = 0; c0 < 2; c0++) {
        if (MODE == 1) {
            __half* sa = smem + c0 * GEMM_SLOT_H;
#pragma unroll
            for (int c = 0; c < 2; c++) {
                const int idx = c * 256 + tid;          // 0..511
                const int row = idx >> 2, seg = (idx & 3) * 8;
                cpa16h(sa + row * 40 + seg, Ah + (m0 + row) * 256 + c0 * 32 + seg);
            }
            __half* sb = sa + GEMM_A_H;
            {
                const int row = tid >> 2, seg = (tid & 3) * 8;
                if (tid < 256) cpa16h(sb + row * 40 + seg,
                                      wt + (n0 + row) * 264 + c0 * 32 + seg);
            }
        } else {
            __half* sb = smem + 2 * GEMM_A_H + c0 * GEMM_B_H;
            const int row = tid >> 2, seg = (tid & 3) * 8;
            cpa16h(sb + row * 40 + seg, wt + (n0 + row) * 264 + c0 * 32 + seg);
        }
        asm volatile("cp.async.commit_group;");
    }

    if (MODE == 0) {   // A chunk 0 -> abuf 0 (LDG + cvt + STS)
        const float4* ga = (const float4*)(Af + (m0 + arow) * 256 + akoff);
        __half* da = smem + arow * 40 + akoff;
#pragma unroll
        for (int c8 = 0; c8 < 2; c8++) {
            float4 v0 = ga[c8 * 2], v1 = ga[c8 * 2 + 1];
            __half2 h0 = __floats2half2_rn(v0.x, v0.y);
            __half2 h1 = __floats2half2_rn(v0.z, v0.w);
            __half2 h2 = __floats2half2_rn(v1.x, v1.y);
            __half2 h3 = __floats2half2_rn(v1.z, v1.w);
            uint4 u;
            u.x = *(unsigned*)&h0; u.y = *(unsigned*)&h1;
            u.z = *(unsigned*)&h2; u.w = *(unsigned*)&h3;
            *(uint4*)(da + c8 * 8) = u;
        }
    }

    float acc[2][4][4] = {};

#pragma unroll 1
    for (int kt = 0; kt < 8; kt++) {
        float4 pa[4];
        if (MODE == 0 && kt < 7) {
            const float4* ga = (const float4*)(Af + (m0 + arow) * 256 + (kt + 1) * 32 + akoff);
#pragma unroll
            for (int c4 = 0; c4 < 4; c4++) pa[c4] = ga[c4];
        }
        if (kt < 6) asm volatile("cp.async.wait_group 1;");
        else        asm volatile("cp.async.wait_group 0;");
        __syncthreads();
        if (kt < 6) {
            const int nt = kt + 2;
            if (MODE == 1) {
                __half* sa = smem + (nt % 3) * GEMM_SLOT_H;
#pragma unroll
                for (int c = 0; c < 2; c++) {
                    const int idx = c * 256 + tid;
                    const int row = idx >> 2, seg = (idx & 3) * 8;
                    cpa16h(sa + row * 40 + seg, Ah + (m0 + row) * 256 + nt * 32 + seg);
                }
                __half* sb = sa + GEMM_A_H;
                const int row = tid >> 2, seg = (tid & 3) * 8;
                cpa16h(sb + row * 40 + seg, wt + (n0 + row) * 264 + nt * 32 + seg);
            } else {
                __half* sb = smem + 2 * GEMM_A_H + (nt % 3) * GEMM_B_H;
                const int row = tid >> 2, seg = (tid & 3) * 8;
                cpa16h(sb + row * 40 + seg, wt + (n0 + row) * 264 + nt * 32 + seg);
            }
            asm volatile("cp.async.commit_group;");
        }
        const __half* acur = (MODE == 1) ? (smem + (kt % 3) * GEMM_SLOT_H)
                                         : (smem + (kt & 1) * GEMM_A_H);
        const __half* bcur = (MODE == 1) ? (smem + (kt % 3) * GEMM_SLOT_H + GEMM_A_H)
                                         : (smem + 2 * GEMM_A_H + (kt % 3) * GEMM_B_H);
#pragma unroll
        for (int kc = 0; kc < 2; kc++) {
            unsigned a[2][4];
#pragma unroll
            for (int i = 0; i < 2; i++) {
                const __half* ap = acur + (wm * 32 + i * 16 + (g8 & 1) * 8 + r8) * 40
                                   + kc * 16 + (g8 >> 1) * 8;
                ldsm4h(a[i], ap);
            }
            unsigned bf0[4], bf1[4];
            ldsm4h(bf0, bcur + (wn * 32 + (g8 & 1) * 8 + r8) * 40 + kc * 16 + (g8 >> 1) * 8);
            ldsm4h(bf1, bcur + (wn * 32 + 16 + (g8 & 1) * 8 + r8) * 40 + kc * 16 + (g8 >> 1) * 8);
#pragma unroll
            for (int i = 0; i < 2; i++) {
                mma_f16(acc[i][0], a[i], bf0[0], bf0[2]);
                mma_f16(acc[i][1], a[i], bf0[1], bf0[3]);
                mma_f16(acc[i][2], a[i], bf1[0], bf1[2]);
                mma_f16(acc[i][3], a[i], bf1[1], bf1[3]);
            }
        }
        if (MODE == 0 && kt < 7) {
            __half* da = smem + ((kt + 1) & 1) * GEMM_A_H + arow * 40 + akoff;
#pragma unroll
            for (int c8 = 0; c8 < 2; c8++) {
                float4 v0 = pa[c8 * 2], v1 = pa[c8 * 2 + 1];
                __half2 h0 = __floats2half2_rn(v0.x, v0.y);
                __half2 h1 = __floats2half2_rn(v0.z, v0.w);
                __half2 h2 = __floats2half2_rn(v1.x, v1.y);
                __half2 h3 = __floats2half2_rn(v1.z, v1.w);
                uint4 u;
                u.x = *(unsigned*)&h0; u.y = *(unsigned*)&h1;
                u.z = *(unsigned*)&h2; u.w = *(unsigned*)&h3;
                *(uint4*)(da + c8 * 8) = u;
            }
        }
    }

    const float scale = 0.17677669529663687f * 1.4426950408889634f;  // qproj folds log2(e)
    const float r = (MODE == 1) ? rz[0] : 0.f;
#pragma unroll
    for (int i = 0; i < 2; i++) {
        const int m = m0 + wm * 32 + i * 16 + (lane >> 2);
#pragma unroll
        for (int j = 0; j < 4; j++) {
            const int col = n0 + wn * 32 + j * 8 + (lane & 3) * 2;
            const float b0 = bias[col], b1 = bias[col + 1];
            if (MODE == 0) {
                const int bi = m >> 14, rr = (m >> 7) & 127, cc = m & 127;
                const int win = bi * 64 + ((rr >> 4) << 3) + (cc >> 4);
                const int t = (rr & 15) * 16 + (cc & 15);
                const int head = col >> 5, d = col & 31;
                __half* p = g_qh + ((win * 8 + head) * 256 + t) * 32 + d;
                *(__half2*)p = __floats2half2_rn((acc[i][j][0] + b0) * scale,
                                                 (acc[i][j][1] + b1) * scale);
                *(__half2*)(p + 8 * 32) = __floats2half2_rn((acc[i][j][2] + b0) * scale,
                                                            (acc[i][j][3] + b1) * scale);
            } else {
                float* p = out + m * 256 + col;
                *(float2*)p = make_float2(r * (acc[i][j][0] + b0), r * (acc[i][j][1] + b1));
                *(float2*)(p + 8 * 256) = make_float2(r * (acc[i][j][2] + b0), r * (acc[i][j][3] + b1));
            }
        }
    }
}

// ---------------------------------------------------------------------------
// fp16 flash attention (R13 mainloop; epilogue writes fp16 g_oh).
// ---------------------------------------------------------------------------
#define ATT_QS_H 10240
#define ATT_KS_H (3*1280)
#define ATT_VS_H (3*1280)
#define ATT_PS_H 10240
#define ATT_SMEM_B ((ATT_QS_H + ATT_KS_H + ATT_VS_H + ATT_PS_H) * 2)

__global__ __launch_bounds__(256, 2) void attn_mma() {
    extern __shared__ char smc[];
    __half* Qs = (__half*)smc;
    __half* Ks = Qs + ATT_QS_H;
    __half* Vs = Ks + ATT_KS_H;
    __half* Ps = Vs + ATT_VS_H;

    const int win = blockIdx.x, hd = blockIdx.y;
    const int tid = threadIdx.x;
    const int lane = tid & 31, warp = tid >> 5;
    const int q = lane >> 2, t = lane & 3;
    const int g8 = lane >> 3, r8 = lane & 7;
    const int wb = warp * 32;
    __half* Pw = Ps + warp * 1280;

    const __half* qh = g_qh + (win * 8 + hd) * 8192;
    const __half* kh = g_kh + (win * 8 + hd) * 8192;
    const __half* vth = g_vh + (win * 8 + hd) * 8192;
    const float* bb = g_bias + (hd << 16);

#pragma unroll
    for (int c = 0; c < 4; c++) {
        const int i = c * 256 + tid;
        const int row = i >> 2, seg = (i & 3) * 8;
        *(uint4*)&Qs[row * 40 + seg] = *(const uint4*)&qh[row * 32 + seg];
    }
    {
        const int r = (tid & 127) >> 2, sg = (tid & 3) * 8;
#pragma unroll
        for (int c = 0; c < 2; c++) {
            if (tid < 128) cpa16h(Ks + c * 1280 + r * 40 + sg, kh + (c * 32 + r) * 32 + sg);
            else           cpa16h(Vs + c * 1280 + r * 40 + sg, vth + r * 256 + c * 32 + sg);
            asm volatile("cp.async.commit_group;");
        }
    }
    __syncthreads();

    unsigned qa[2][2][4];
#pragma unroll
    for (int mt = 0; mt < 2; mt++)
#pragma unroll
        for (int kc = 0; kc < 2; kc++)
            ldsm4h(qa[mt][kc], Qs + (wb + mt * 16 + (g8 & 1) * 8 + r8) * 40 + kc * 16 + (g8 >> 1) * 8);

    float o[2][4][4] = {};
    float mrow[2][2] = {{-1e30f, -1e30f}, {-1e30f, -1e30f}};
    float lrow[2][2] = {};

#pragma unroll 1
    for (int sb = 0; sb < 8; sb++) {
        asm volatile("cp.async.wait_group 1;");
        __syncthreads();

        if (sb < 6) {
            const int slot = (sb + 2) % 3;
            const int r = (tid & 127) >> 2, sg = (tid & 3) * 8;
            if (tid < 128) cpa16h(Ks + slot * 1280 + r * 40 + sg, kh + ((sb + 2) * 32 + r) * 32 + sg);
            else           cpa16h(Vs + slot * 1280 + r * 40 + sg, vth + r * 256 + (sb + 2) * 32 + sg);
        }
        asm volatile("cp.async.commit_group;");

        const __half* Kb = Ks + (sb % 3) * 1280;
        const __half* Vb = Vs + (sb % 3) * 1280;

        float s[2][4][4];
#pragma unroll
        for (int mt = 0; mt < 2; mt++) {
            const float* br0 = bb + (wb + mt * 16 + q) * 256 + sb * 32 + t * 2;
            const float* br1 = br0 + 8 * 256;
#pragma unroll
            for (int nt = 0; nt < 4; nt++) {
                float2 b0 = *(const float2*)(br0 + nt * 8);
                float2 b1 = *(const float2*)(br1 + nt * 8);
                s[mt][nt][0] = b0.x; s[mt][nt][1] = b0.y;
                s[mt][nt][2] = b1.x; s[mt][nt][3] = b1.y;
            }
        }
#pragma unroll
        for (int kc = 0; kc < 2; kc++) {
#pragma unroll
            for (int nt16 = 0; nt16 < 2; nt16++) {
                unsigned kf[4];
                ldsm4h(kf, Kb + (nt16 * 16 + (g8 & 1) * 8 + r8) * 40 + kc * 16 + (g8 >> 1) * 8);
                mma_f16(s[0][nt16 * 2 + 0], qa[0][kc], kf[0], kf[2]);
                mma_f16(s[0][nt16 * 2 + 1], qa[0][kc], kf[1], kf[3]);
                mma_f16(s[1][nt16 * 2 + 0], qa[1][kc], kf[0], kf[2]);
                mma_f16(s[1][nt16 * 2 + 1], qa[1][kc], kf[1], kf[3]);
            }
        }

#pragma unroll
        for (int mt = 0; mt < 2; mt++) {
            float mx0 = fmaxf(fmaxf(s[mt][0][0], s[mt][0][1]), fmaxf(s[mt][1][0], s[mt][1][1]));
            float mx1 = fmaxf(fmaxf(s[mt][0][2], s[mt][0][3]), fmaxf(s[mt][1][2], s[mt][1][3]));
            mx0 = fmaxf(mx0, fmaxf(fmaxf(s[mt][2][0], s[mt][2][1]), fmaxf(s[mt][3][0], s[mt][3][1])));
            mx1 = fmaxf(mx1, fmaxf(fmaxf(s[mt][2][2], s[mt][2][3]), fmaxf(s[mt][3][2], s[mt][3][3])));
            mx0 = fmaxf(mx0, __shfl_xor_sync(0xffffffff, mx0, 1));
            mx0 = fmaxf(mx0, __shfl_xor_sync(0xffffffff, mx0, 2));
            mx1 = fmaxf(mx1, __shfl_xor_sync(0xffffffff, mx1, 1));
            mx1 = fmaxf(mx1, __shfl_xor_sync(0xffffffff, mx1, 2));
            const float mn0 = fmaxf(mrow[mt][0], mx0);
            const float mn1 = fmaxf(mrow[mt][1], mx1);
            const float cor0 = ex2(mrow[mt][0] - mn0);
            const float cor1 = ex2(mrow[mt][1] - mn1);
            mrow[mt][0] = mn0; mrow[mt][1] = mn1;
#pragma unroll
            for (int dn = 0; dn < 4; dn++) {
                o[mt][dn][0] *= cor0; o[mt][dn][1] *= cor0;
                o[mt][dn][2] *= cor1; o[mt][dn][3] *= cor1;
            }
            float sm0 = 0.f, sm1 = 0.f;
#pragma unroll
            for (int nt = 0; nt < 4; nt++) {
                float p0 = ex2(s[mt][nt][0] - mn0);
                float p1 = ex2(s[mt][nt][1] - mn0);
                float p2 = ex2(s[mt][nt][2] - mn1);
                float p3 = ex2(s[mt][nt][3] - mn1);
                sm0 += p0 + p1; sm1 += p2 + p3;
                *(__half2*)&Pw[(mt * 16 + q) * 40 + nt * 8 + 2 * t] = __floats2half2_rn(p0, p1);
                *(__half2*)&Pw[(mt * 16 + q + 8) * 40 + nt * 8 + 2 * t] = __floats2half2_rn(p2, p3);
            }
            lrow[mt][0] = lrow[mt][0] * cor0 + sm0;
            lrow[mt][1] = lrow[mt][1] * cor1 + sm1;
        }
        __syncwarp();

#pragma unroll
        for (int kk = 0; kk < 2; kk++) {
            unsigned pa[2][4];
            ldsm4h(pa[0], Pw + ((g8 & 1) * 8 + r8) * 40 + kk * 16 + (g8 >> 1) * 8);
            ldsm4h(pa[1], Pw + (16 + (g8 & 1) * 8 + r8) * 40 + kk * 16 + (g8 >> 1) * 8);
#pragma unroll
            for (int dn16 = 0; dn16 < 2; dn16++) {
                unsigned vf[4];
                ldsm4h(vf, Vb + (dn16 * 16 + (g8 & 1) * 8 + r8) * 40 + kk * 16 + (g8 >> 1) * 8);
                mma_f16(o[0][dn16 * 2 + 0], pa[0], vf[0], vf[2]);
                mma_f16(o[0][dn16 * 2 + 1], pa[0], vf[1], vf[3]);
                mma_f16(o[1][dn16 * 2 + 0], pa[1], vf[0], vf[2]);
                mma_f16(o[1][dn16 * 2 + 1], pa[1], vf[1], vf[3]);
            }
        }
        __syncwarp();
    }

    // Epilogue: write fp16 g_oh (B,H,W,C)
    const int bimg = win >> 6, wh = (win >> 3) & 7, ww = win & 7;
#pragma unroll
    for (int mt = 0; mt < 2; mt++) {
        float l0 = lrow[mt][0], l1 = lrow[mt][1];
        l0 += __shfl_xor_sync(0xffffffff, l0, 1);
        l0 += __shfl_xor_sync(0xffffffff, l0, 2);
        l1 += __shfl_xor_sync(0xffffffff, l1, 1);
        l1 += __shfl_xor_sync(0xffffffff, l1, 2);
        const float inv0 = 1.f / l0;
        const float inv1 = 1.f / l1;
        const int tk0 = wb + mt * 16 + q;
#pragma unroll
        for (int half = 0; half < 2; half++) {
            const int tk = tk0 + half * 8;
            const float inv = half ? inv1 : inv0;
            const int gr = wh * 16 + (tk >> 4), gc = ww * 16 + (tk & 15);
            __half* op = g_oh + ((bimg * 128 + gr) * 128 + gc) * 256 + hd * 32;
#pragma unroll
            for (int dn = 0; dn < 4; dn++) {
                *(__half2*)(op + dn * 8 + t * 2) =
                    __floats2half2_rn(o[mt][dn][half * 2] * inv, o[mt][dn][half * 2 + 1] * inv);
            }
        }
    }
}

// ---------------------------------------------------------------------------
extern "C" void kernel_launch(void* const* d_in, const int* in_sizes, int n_in,
                              void* d_out, int out_size) {
    (void)in_sizes; (void)n_in; (void)out_size;
    const float* x_wsa      = (const float*)d_in[0];
    const float* x_original = (const float*)d_in[1];
    const float* q_w        = (const float*)d_in[2];
    const float* q_b        = (const float*)d_in[3];
    const float* kv_w       = (const float*)d_in[4];
    const float* kv_b       = (const float*)d_in[5];
    const float* out_w      = (const float*)d_in[6];
    const float* out_b      = (const float*)d_in[7];
    const float* bias_table = (const float*)d_in[8];
    const float* rezero     = (const float*)d_in[9];
    float* out = (float*)d_out;

    cudaFuncSetAttribute(convkv_mma, cudaFuncAttributeMaxDynamicSharedMemorySize, CONV_SMEM_B);
    cudaFuncSetAttribute(gemm_mma<0>, cudaFuncAttributeMaxDynamicSharedMemorySize, GEMM_SMEM_B0);
    cudaFuncSetAttribute(gemm_mma<1>, cudaFuncAttributeMaxDynamicSharedMemorySize, GEMM_SMEM_B1);
    cudaFuncSetAttribute(attn_mma, cudaFuncAttributeMaxDynamicSharedMemorySize, ATT_SMEM_B);

    prep_all<<<4160, 256>>>(bias_table, q_w, out_w, kv_w);                          // #1
    gemm_mma<0><<<dim3(512, 4), 256, GEMM_SMEM_B0>>>(x_wsa, q_b, nullptr, nullptr); // #2
    convkv_mma<<<dim3(64, 32), 256, CONV_SMEM_B>>>(x_original, kv_b);               // #3
    attn_mma<<<dim3(256, 8), 256, ATT_SMEM_B>>>();                                  // #4 <- profiled
    gemm_mma<1><<<dim3(512, 4), 256, GEMM_SMEM_B1>>>(nullptr, out_b, rezero, out);  // #5
}

// round 15
// speedup vs baseline: 2.4601x; 1.0282x over previous
#include <cuda_runtime.h>
#include <cuda_fp16.h>

// B=4, H=W=128, C=256, heads=8, d=32, win=16 -> 256 windows x 256 tokens
// Scratch (fp16): g_qh [win][head][tok][d]; g_kh [win][head][key][d];
//                 g_vh TRANSPOSED [win][head][d][key]; g_oh [B,H,W,C].
__device__ __half g_qh[16777216];
__device__ __half g_kh[16777216];
__device__ __half g_vh[16777216];
__device__ __half g_oh[16777216];
__device__ float g_bias[524288];    // [head][256 q][256 k], = bt*log2e - 8 (static softmax shift)
__device__ __half g_wth[135168];    // 2 x [256 n][264 pitch k] fp16: qw^T, ow^T
__device__ __half g_wcth[204800];   // conv weights fp16: [(g*64+oc)][25 taps * 32 k] pitch 800

__device__ __forceinline__ float ex2(float x) {
    float r;
    asm("ex2.approx.ftz.f32 %0, %1;" : "=f"(r) : "f"(x));
    return r;
}

// fp16 mma m16n8k16, fp32 accumulate (fp16 mantissa == tf32 mantissa: 10 bits)
__device__ __forceinline__ void mma_f16(float* c, const unsigned* a, unsigned b0, unsigned b1) {
    asm volatile(
        "mma.sync.aligned.m16n8k16.row.col.f32.f16.f16.f32 "
        "{%0,%1,%2,%3},{%4,%5,%6,%7},{%8,%9},{%0,%1,%2,%3};"
        : "+f"(c[0]), "+f"(c[1]), "+f"(c[2]), "+f"(c[3])
        : "r"(a[0]), "r"(a[1]), "r"(a[2]), "r"(a[3]), "r"(b0), "r"(b1));
}

__device__ __forceinline__ void ldsm4h(unsigned* r, const __half* p) {
    unsigned a = (unsigned)__cvta_generic_to_shared(p);
    asm volatile("ldmatrix.sync.aligned.m8n8.x4.shared.b16 {%0,%1,%2,%3}, [%4];"
                 : "=r"(r[0]), "=r"(r[1]), "=r"(r[2]), "=r"(r[3]) : "r"(a));
}

__device__ __forceinline__ void cpa16h(__half* dst, const __half* src) {
    unsigned d = (unsigned)__cvta_generic_to_shared(dst);
    asm volatile("cp.async.cg.shared.global [%0], [%1], 16;" :: "r"(d), "l"(src));
}

// ---------------------------------------------------------------------------
// Prep (ONE kernel): bias (log2e-scaled, -8 static softmax shift) + fp16
// GEMM weight transposes + fp16 conv weights.
// ---------------------------------------------------------------------------
__global__ void prep_all(const float* __restrict__ bt,
                         const float* __restrict__ qw,
                         const float* __restrict__ ow,
                         const float* __restrict__ Wc) {
    const int idx = blockIdx.x * 256 + threadIdx.x;
    if (idx < 524288) {
        const int hd = idx >> 16, qt = (idx >> 8) & 255, kt = idx & 255;
        const int qy = qt >> 4, qx = qt & 15, ky = kt >> 4, kx = kt & 15;
        const int rel = (qy - ky + 15) * 31 + (qx - kx + 15);
        g_bias[idx] = bt[rel * 8 + hd] * 1.4426950408889634f - 8.0f;
    } else if (idx < 655360) {
        const int i2 = idx - 524288;
        const int slot = i2 >> 16;
        const int r = i2 & 65535;
        const int n = r >> 8, k = r & 255;
        const float* W = slot ? ow : qw;
        g_wth[slot * 67584 + n * 264 + k] = __float2half_rn(W[k * 256 + n]);
    } else {
        const int i3 = idx - 655360;           // 0..409599
        const int k = i3 & 31;
        const int tap = (i3 >> 5) % 25;
        const int ocg = i3 / 800;
        const int g = ocg >> 6, oc = ocg & 63;
        g_wcth[ocg * 800 + tap * 32 + k] = __float2half_rn(Wc[(tap * 32 + k) * 512 + g * 64 + oc]);
    }
}

// ---------------------------------------------------------------------------
// Conv 5x5 grouped (pad 2, groups=8) — fp16 mma m16n8k16 (unchanged).
// ---------------------------------------------------------------------------
#define CONV_PATCH_H 16000    // 400 * 40 halfs
#define CONV_WTAP_H  2560
#define CONV_WPAIR_H (2*CONV_WTAP_H)
#define CONV_SMEM_B  (CONV_PATCH_H*2 + 3*CONV_WPAIR_H*2)   // 62720 B

__global__ __launch_bounds__(256, 2) void convkv_mma(const float* __restrict__ X,
                                                     const float* __restrict__ bias) {
    extern __shared__ char smc[];
    __half* patch = (__half*)smc;
    __half* wring = patch + CONV_PATCH_H;

    const int tid = threadIdx.x;
    const int lane = tid & 31, warp = tid >> 5;
    const int wm = warp & 3, wn = warp >> 2;
    const int g8 = lane >> 3, r8 = lane & 7;
    const int tile = blockIdx.x;
    const int ty0 = (tile >> 3) * 16, tx0 = (tile & 7) * 16;
    const int b = blockIdx.y >> 3, g = blockIdx.y & 7;

    const __half* wsrc = g_wcth + (g * 64) * 800;

#pragma unroll
    for (int pr = 0; pr < 2; pr++) {
#pragma unroll
        for (int c = 0; c < 2; c++) {
            const int idx = c * 256 + tid;
            const int t2 = idx >> 8, rest = idx & 255;
            const int row = rest >> 2, seg = (rest & 3) * 8;
            cpa16h(wring + pr * CONV_WPAIR_H + t2 * CONV_WTAP_H + row * 40 + seg,
                   wsrc + row * 800 + (pr * 2 + t2) * 32 + seg);
        }
        asm volatile("cp.async.commit_group;");
    }

    for (int p = tid; p < 400; p += 256) {
        int py = p / 20, px = p - py * 20;
        int gy = ty0 + py - 2, gx = tx0 + px - 2;
        bool ok = (gy >= 0 && gy < 128 && gx >= 0 && gx < 128);
        const float4* src = (const float4*)(X + ((b * 128 + gy) * 128 + gx) * 256 + g * 32);
#pragma unroll
        for (int s = 0; s < 4; s++) {
            float4 v0 = ok ? src[s * 2]     : make_float4(0.f, 0.f, 0.f, 0.f);
            float4 v1 = ok ? src[s * 2 + 1] : make_float4(0.f, 0.f, 0.f, 0.f);
            __half2 h0 = __floats2half2_rn(v0.x, v0.y);
            __half2 h1 = __floats2half2_rn(v0.z, v0.w);
            __half2 h2 = __floats2half2_rn(v1.x, v1.y);
            __half2 h3 = __floats2half2_rn(v1.z, v1.w);
            uint4 u;
            u.x = *(unsigned*)&h0; u.y = *(unsigned*)&h1;
            u.z = *(unsigned*)&h2; u.w = *(unsigned*)&h3;
            *(uint4*)&patch[p * 40 + s * 8] = u;
        }
    }

    float acc[4][4][4] = {};

#pragma unroll 1
    for (int rnd = 0; rnd < 13; rnd++) {
        if (rnd < 11) asm volatile("cp.async.wait_group 1;");
        else          asm volatile("cp.async.wait_group 0;");
        __syncthreads();
        if (rnd < 11) {
            const int np = rnd + 2;
            __half* dst = wring + (np % 3) * CONV_WPAIR_H;
#pragma unroll
            for (int c = 0; c < 2; c++) {
                const int idx = c * 256 + tid;
                const int t2 = idx >> 8, rest = idx & 255;
                const int row = rest >> 2, seg = (rest & 3) * 8;
                const int tap = np * 2 + t2;
                if (tap < 25)
                    cpa16h(dst + t2 * CONV_WTAP_H + row * 40 + seg,
                           wsrc + row * 800 + tap * 32 + seg);
            }
            asm volatile("cp.async.commit_group;");
        } else {
            asm volatile("cp.async.commit_group;");
        }

#pragma unroll
        for (int t2 = 0; t2 < 2; t2++) {
            const int tap = rnd * 2 + t2;
            if (tap < 25) {
                const int ky = tap / 5, kx = tap - ky * 5;
                const __half* wcur = wring + (rnd % 3) * CONV_WPAIR_H + t2 * CONV_WTAP_H;
#pragma unroll
                for (int kc = 0; kc < 2; kc++) {
                    unsigned a[4][4];
#pragma unroll
                    for (int i = 0; i < 4; i++) {
                        const __half* ap = patch
                            + ((wm * 4 + i + ky) * 20 + (g8 & 1) * 8 + r8 + kx) * 40
                            + kc * 16 + (g8 >> 1) * 8;
                        ldsm4h(a[i], ap);
                    }
                    unsigned bf0[4], bf1[4];
                    ldsm4h(bf0, wcur + (wn * 32 + (g8 & 1) * 8 + r8) * 40 + kc * 16 + (g8 >> 1) * 8);
                    ldsm4h(bf1, wcur + (wn * 32 + 16 + (g8 & 1) * 8 + r8) * 40 + kc * 16 + (g8 >> 1) * 8);
#pragma unroll
                    for (int i = 0; i < 4; i++) {
                        mma_f16(acc[i][0], a[i], bf0[0], bf0[2]);
                        mma_f16(acc[i][1], a[i], bf0[1], bf0[3]);
                        mma_f16(acc[i][2], a[i], bf1[0], bf1[2]);
                        mma_f16(acc[i][3], a[i], bf1[1], bf1[3]);
                    }
                }
            }
        }
    }

    const int win = b * 64 + (tile >> 3) * 8 + (tile & 7);
    const int head = (g & 3) * 2 + wn;
    if (g < 4) {   // K: [key][d] fp16
        __half* base = g_kh + ((win * 8 + head) * 256) * 32;
#pragma unroll
        for (int i = 0; i < 4; i++) {
            const int p0 = wm * 64 + i * 16 + (lane >> 2);
#pragma unroll
            for (int j = 0; j < 4; j++) {
                const int col = wn * 32 + j * 8 + (lane & 3) * 2;
                const int d = col & 31;
                float b0 = bias[g * 64 + col], b1 = bias[g * 64 + col + 1];
                *(__half2*)(base + p0 * 32 + d) =
                    __floats2half2_rn(acc[i][j][0] + b0, acc[i][j][1] + b1);
                *(__half2*)(base + (p0 + 8) * 32 + d) =
                    __floats2half2_rn(acc[i][j][2] + b0, acc[i][j][3] + b1);
            }
        }
    } else {       // V transposed: [d][key] fp16
        __half* base = g_vh + ((win * 8 + head) * 32) * 256;
#pragma unroll
        for (int i = 0; i < 4; i++) {
            const int p0 = wm * 64 + i * 16 + (lane >> 2);
#pragma unroll
            for (int j = 0; j < 4; j++) {
                const int col = wn * 32 + j * 8 + (lane & 3) * 2;
                const int d0 = col & 31;
                float b0 = bias[g * 64 + col], b1 = bias[g * 64 + col + 1];
                base[d0 * 256 + p0]           = __float2half_rn(acc[i][j][0] + b0);
                base[(d0 + 1) * 256 + p0]     = __float2half_rn(acc[i][j][1] + b1);
                base[d0 * 256 + p0 + 8]       = __float2half_rn(acc[i][j][2] + b0);
                base[(d0 + 1) * 256 + p0 + 8] = __float2half_rn(acc[i][j][3] + b1);
            }
        }
    }
}

// ---------------------------------------------------------------------------
// fp16 GEMM m16n8k16 (unchanged from R14).
// ---------------------------------------------------------------------------
#define GEMM_A_H 5120
#define GEMM_B_H 2560
#define GEMM_SLOT_H (GEMM_A_H + GEMM_B_H)
#define GEMM_SMEM_B0 ((2*GEMM_A_H + 3*GEMM_B_H) * 2)
#define GEMM_SMEM_B1 ((3*GEMM_SLOT_H) * 2)

template <int MODE>
__global__ __launch_bounds__(256, 2) void gemm_mma(const float* __restrict__ Aparam,
                                                   const float* __restrict__ bias,
                                                   const float* __restrict__ rz,
                                                   float* __restrict__ out) {
    extern __shared__ char smc[];
    __half* smem = (__half*)smc;

    const float* Af = Aparam;
    const __half* Ah = g_oh;
    const __half* wt = g_wth + MODE * 67584;

    const int tid = threadIdx.x;
    const int lane = tid & 31, warp = tid >> 5;
    const int wm = warp & 3, wn = warp >> 2;
    const int g8 = lane >> 3, r8 = lane & 7;
    const int m0 = blockIdx.x * 128;
    const int n0 = blockIdx.y * 64;

    const int arow = tid >> 1, akoff = (tid & 1) * 16;

#pragma unroll
    for (int c0 = 0; c0 < 2; c0++) {
        if (MODE == 1) {
            __half* sa = smem + c0 * GEMM_SLOT_H;
#pragma unroll
            for (int c = 0; c < 2; c++) {
                const int idx = c * 256 + tid;
                const int row = idx >> 2, seg = (idx & 3) * 8;
                cpa16h(sa + row * 40 + seg, Ah + (m0 + row) * 256 + c0 * 32 + seg);
            }
            __half* sb = sa + GEMM_A_H;
            {
                const int row = tid >> 2, seg = (tid & 3) * 8;
                cpa16h(sb + row * 40 + seg, wt + (n0 + row) * 264 + c0 * 32 + seg);
            }
        } else {
            __half* sb = smem + 2 * GEMM_A_H + c0 * GEMM_B_H;
            const int row = tid >> 2, seg = (tid & 3) * 8;
            cpa16h(sb + row * 40 + seg, wt + (n0 + row) * 264 + c0 * 32 + seg);
        }
        asm volatile("cp.async.commit_group;");
    }

    if (MODE == 0) {
        const float4* ga = (const float4*)(Af + (m0 + arow) * 256 + akoff);
        __half* da = smem + arow * 40 + akoff;
#pragma unroll
        for (int c8 = 0; c8 < 2; c8++) {
            float4 v0 = ga[c8 * 2], v1 = ga[c8 * 2 + 1];
            __half2 h0 = __floats2half2_rn(v0.x, v0.y);
            __half2 h1 = __floats2half2_rn(v0.z, v0.w);
            __half2 h2 = __floats2half2_rn(v1.x, v1.y);
            __half2 h3 = __floats2half2_rn(v1.z, v1.w);
            uint4 u;
            u.x = *(unsigned*)&h0; u.y = *(unsigned*)&h1;
            u.z = *(unsigned*)&h2; u.w = *(unsigned*)&h3;
            *(uint4*)(da + c8 * 8) = u;
        }
    }

    float acc[2][4][4] = {};

#pragma unroll 1
    for (int kt = 0; kt < 8; kt++) {
        float4 pa[4];
        if (MODE == 0 && kt < 7) {
            const float4* ga = (const float4*)(Af + (m0 + arow) * 256 + (kt + 1) * 32 + akoff);
#pragma unroll
            for (int c4 = 0; c4 < 4; c4++) pa[c4] = ga[c4];
        }
        if (kt < 6) asm volatile("cp.async.wait_group 1;");
        else        asm volatile("cp.async.wait_group 0;");
        __syncthreads();
        if (kt < 6) {
            const int nt = kt + 2;
            if (MODE == 1) {
                __half* sa = smem + (nt % 3) * GEMM_SLOT_H;
#pragma unroll
                for (int c = 0; c < 2; c++) {
                    const int idx = c * 256 + tid;
                    const int row = idx >> 2, seg = (idx & 3) * 8;
                    cpa16h(sa + row * 40 + seg, Ah + (m0 + row) * 256 + nt * 32 + seg);
                }
                __half* sb = sa + GEMM_A_H;
                const int row = tid >> 2, seg = (tid & 3) * 8;
                cpa16h(sb + row * 40 + seg, wt + (n0 + row) * 264 + nt * 32 + seg);
            } else {
                __half* sb = smem + 2 * GEMM_A_H + (nt % 3) * GEMM_B_H;
                const int row = tid >> 2, seg = (tid & 3) * 8;
                cpa16h(sb + row * 40 + seg, wt + (n0 + row) * 264 + nt * 32 + seg);
            }
            asm volatile("cp.async.commit_group;");
        }
        const __half* acur = (MODE == 1) ? (smem + (kt % 3) * GEMM_SLOT_H)
                                         : (smem + (kt & 1) * GEMM_A_H);
        const __half* bcur = (MODE == 1) ? (smem + (kt % 3) * GEMM_SLOT_H + GEMM_A_H)
                                         : (smem + 2 * GEMM_A_H + (kt % 3) * GEMM_B_H);
#pragma unroll
        for (int kc = 0; kc < 2; kc++) {
            unsigned a[2][4];
#pragma unroll
            for (int i = 0; i < 2; i++) {
                const __half* ap = acur + (wm * 32 + i * 16 + (g8 & 1) * 8 + r8) * 40
                                   + kc * 16 + (g8 >> 1) * 8;
                ldsm4h(a[i], ap);
            }
            unsigned bf0[4], bf1[4];
            ldsm4h(bf0, bcur + (wn * 32 + (g8 & 1) * 8 + r8) * 40 + kc * 16 + (g8 >> 1) * 8);
            ldsm4h(bf1, bcur + (wn * 32 + 16 + (g8 & 1) * 8 + r8) * 40 + kc * 16 + (g8 >> 1) * 8);
#pragma unroll
            for (int i = 0; i < 2; i++) {
                mma_f16(acc[i][0], a[i], bf0[0], bf0[2]);
                mma_f16(acc[i][1], a[i], bf0[1], bf0[3]);
                mma_f16(acc[i][2], a[i], bf1[0], bf1[2]);
                mma_f16(acc[i][3], a[i], bf1[1], bf1[3]);
            }
        }
        if (MODE == 0 && kt < 7) {
            __half* da = smem + ((kt + 1) & 1) * GEMM_A_H + arow * 40 + akoff;
#pragma unroll
            for (int c8 = 0; c8 < 2; c8++) {
                float4 v0 = pa[c8 * 2], v1 = pa[c8 * 2 + 1];
                __half2 h0 = __floats2half2_rn(v0.x, v0.y);
                __half2 h1 = __floats2half2_rn(v0.z, v0.w);
                __half2 h2 = __floats2half2_rn(v1.x, v1.y);
                __half2 h3 = __floats2half2_rn(v1.z, v1.w);
                uint4 u;
                u.x = *(unsigned*)&h0; u.y = *(unsigned*)&h1;
                u.z = *(unsigned*)&h2; u.w = *(unsigned*)&h3;
                *(uint4*)(da + c8 * 8) = u;
            }
        }
    }

    const float scale = 0.17677669529663687f * 1.4426950408889634f;
    const float r = (MODE == 1) ? rz[0] : 0.f;
#pragma unroll
    for (int i = 0; i < 2; i++) {
        const int m = m0 + wm * 32 + i * 16 + (lane >> 2);
#pragma unroll
        for (int j = 0; j < 4; j++) {
            const int col = n0 + wn * 32 + j * 8 + (lane & 3) * 2;
            const float b0 = bias[col], b1 = bias[col + 1];
            if (MODE == 0) {
                const int bi = m >> 14, rr = (m >> 7) & 127, cc = m & 127;
                const int win = bi * 64 + ((rr >> 4) << 3) + (cc >> 4);
                const int t = (rr & 15) * 16 + (cc & 15);
                const int head = col >> 5, d = col & 31;
                __half* p = g_qh + ((win * 8 + head) * 256 + t) * 32 + d;
                *(__half2*)p = __floats2half2_rn((acc[i][j][0] + b0) * scale,
                                                 (acc[i][j][1] + b1) * scale);
                *(__half2*)(p + 8 * 32) = __floats2half2_rn((acc[i][j][2] + b0) * scale,
                                                            (acc[i][j][3] + b1) * scale);
            } else {
                float* p = out + m * 256 + col;
                *(float2*)p = make_float2(r * (acc[i][j][0] + b0), r * (acc[i][j][1] + b1));
                *(float2*)(p + 8 * 256) = make_float2(r * (acc[i][j][2] + b0), r * (acc[i][j][3] + b1));
            }
        }
    }
}

// ---------------------------------------------------------------------------
// fp16 flash attention with STATIC softmax shift (-8 folded into g_bias):
// no running max, no rescaling — p = ex2(s) directly, l = plain sum.
// Exact softmax (shift-invariance); scores bounded |S|<~2 << fp16 range.
// ---------------------------------------------------------------------------
#define ATT_QS_H 10240
#define ATT_KS_H (3*1280)
#define ATT_VS_H (3*1280)
#define ATT_PS_H 10240
#define ATT_SMEM_B ((ATT_QS_H + ATT_KS_H + ATT_VS_H + ATT_PS_H) * 2)

__global__ __launch_bounds__(256, 2) void attn_mma() {
    extern __shared__ char smc[];
    __half* Qs = (__half*)smc;
    __half* Ks = Qs + ATT_QS_H;
    __half* Vs = Ks + ATT_KS_H;
    __half* Ps = Vs + ATT_VS_H;

    const int win = blockIdx.x, hd = blockIdx.y;
    const int tid = threadIdx.x;
    const int lane = tid & 31, warp = tid >> 5;
    const int q = lane >> 2, t = lane & 3;
    const int g8 = lane >> 3, r8 = lane & 7;
    const int wb = warp * 32;
    __half* Pw = Ps + warp * 1280;

    const __half* qh = g_qh + (win * 8 + hd) * 8192;
    const __half* kh = g_kh + (win * 8 + hd) * 8192;
    const __half* vth = g_vh + (win * 8 + hd) * 8192;
    const float* bb = g_bias + (hd << 16);

#pragma unroll
    for (int c = 0; c < 4; c++) {
        const int i = c * 256 + tid;
        const int row = i >> 2, seg = (i & 3) * 8;
        *(uint4*)&Qs[row * 40 + seg] = *(const uint4*)&qh[row * 32 + seg];
    }
    {
        const int r = (tid & 127) >> 2, sg = (tid & 3) * 8;
#pragma unroll
        for (int c = 0; c < 2; c++) {
            if (tid < 128) cpa16h(Ks + c * 1280 + r * 40 + sg, kh + (c * 32 + r) * 32 + sg);
            else           cpa16h(Vs + c * 1280 + r * 40 + sg, vth + r * 256 + c * 32 + sg);
            asm volatile("cp.async.commit_group;");
        }
    }
    __syncthreads();

    unsigned qa[2][2][4];
#pragma unroll
    for (int mt = 0; mt < 2; mt++)
#pragma unroll
        for (int kc = 0; kc < 2; kc++)
            ldsm4h(qa[mt][kc], Qs + (wb + mt * 16 + (g8 & 1) * 8 + r8) * 40 + kc * 16 + (g8 >> 1) * 8);

    float o[2][4][4] = {};
    float lrow[2][2] = {};   // plain sums (static shift -> no rescale)

#pragma unroll 1
    for (int sb = 0; sb < 8; sb++) {
        asm volatile("cp.async.wait_group 1;");
        __syncthreads();

        if (sb < 6) {
            const int slot = (sb + 2) % 3;
            const int r = (tid & 127) >> 2, sg = (tid & 3) * 8;
            if (tid < 128) cpa16h(Ks + slot * 1280 + r * 40 + sg, kh + ((sb + 2) * 32 + r) * 32 + sg);
            else           cpa16h(Vs + slot * 1280 + r * 40 + sg, vth + r * 256 + (sb + 2) * 32 + sg);
        }
        asm volatile("cp.async.commit_group;");

        const __half* Kb = Ks + (sb % 3) * 1280;
        const __half* Vb = Vs + (sb % 3) * 1280;

        // ---- S = Q K^T, bias (incl. static -8 shift) as accumulator init ----
        float s[2][4][4];
#pragma unroll
        for (int mt = 0; mt < 2; mt++) {
            const float* br0 = bb + (wb + mt * 16 + q) * 256 + sb * 32 + t * 2;
            const float* br1 = br0 + 8 * 256;
#pragma unroll
            for (int nt = 0; nt < 4; nt++) {
                float2 b0 = *(const float2*)(br0 + nt * 8);
                float2 b1 = *(const float2*)(br1 + nt * 8);
                s[mt][nt][0] = b0.x; s[mt][nt][1] = b0.y;
                s[mt][nt][2] = b1.x; s[mt][nt][3] = b1.y;
            }
        }
#pragma unroll
        for (int kc = 0; kc < 2; kc++) {
#pragma unroll
            for (int nt16 = 0; nt16 < 2; nt16++) {
                unsigned kf[4];
                ldsm4h(kf, Kb + (nt16 * 16 + (g8 & 1) * 8 + r8) * 40 + kc * 16 + (g8 >> 1) * 8);
                mma_f16(s[0][nt16 * 2 + 0], qa[0][kc], kf[0], kf[2]);
                mma_f16(s[0][nt16 * 2 + 1], qa[0][kc], kf[1], kf[3]);
                mma_f16(s[1][nt16 * 2 + 0], qa[1][kc], kf[0], kf[2]);
                mma_f16(s[1][nt16 * 2 + 1], qa[1][kc], kf[1], kf[3]);
            }
        }

        // ---- p = ex2(s); accumulate l; P -> warp-private smem (fp16) ----
#pragma unroll
        for (int mt = 0; mt < 2; mt++) {
            float sm0 = 0.f, sm1 = 0.f;
#pragma unroll
            for (int nt = 0; nt < 4; nt++) {
                float p0 = ex2(s[mt][nt][0]);
                float p1 = ex2(s[mt][nt][1]);
                float p2 = ex2(s[mt][nt][2]);
                float p3 = ex2(s[mt][nt][3]);
                sm0 += p0 + p1; sm1 += p2 + p3;
                *(__half2*)&Pw[(mt * 16 + q) * 40 + nt * 8 + 2 * t] = __floats2half2_rn(p0, p1);
                *(__half2*)&Pw[(mt * 16 + q + 8) * 40 + nt * 8 + 2 * t] = __floats2half2_rn(p2, p3);
            }
            lrow[mt][0] += sm0;
            lrow[mt][1] += sm1;
        }
        __syncwarp();

        // ---- O += P V (no rescale needed) ----
#pragma unroll
        for (int kk = 0; kk < 2; kk++) {
            unsigned pa[2][4];
            ldsm4h(pa[0], Pw + ((g8 & 1) * 8 + r8) * 40 + kk * 16 + (g8 >> 1) * 8);
            ldsm4h(pa[1], Pw + (16 + (g8 & 1) * 8 + r8) * 40 + kk * 16 + (g8 >> 1) * 8);
#pragma unroll
            for (int dn16 = 0; dn16 < 2; dn16++) {
                unsigned vf[4];
                ldsm4h(vf, Vb + (dn16 * 16 + (g8 & 1) * 8 + r8) * 40 + kk * 16 + (g8 >> 1) * 8);
                mma_f16(o[0][dn16 * 2 + 0], pa[0], vf[0], vf[2]);
                mma_f16(o[0][dn16 * 2 + 1], pa[0], vf[1], vf[3]);
                mma_f16(o[1][dn16 * 2 + 0], pa[1], vf[0], vf[2]);
                mma_f16(o[1][dn16 * 2 + 1], pa[1], vf[1], vf[3]);
            }
        }
        __syncwarp();
    }

    // Epilogue: reduce l partials, normalize, write fp16 g_oh (B,H,W,C)
    const int bimg = win >> 6, wh = (win >> 3) & 7, ww = win & 7;
#pragma unroll
    for (int mt = 0; mt < 2; mt++) {
        float l0 = lrow[mt][0], l1 = lrow[mt][1];
        l0 += __shfl_xor_sync(0xffffffff, l0, 1);
        l0 += __shfl_xor_sync(0xffffffff, l0, 2);
        l1 += __shfl_xor_sync(0xffffffff, l1, 1);
        l1 += __shfl_xor_sync(0xffffffff, l1, 2);
        const float inv0 = 1.f / l0;
        const float inv1 = 1.f / l1;
        const int tk0 = wb + mt * 16 + q;
#pragma unroll
        for (int half = 0; half < 2; half++) {
            const int tk = tk0 + half * 8;
            const float inv = half ? inv1 : inv0;
            const int gr = wh * 16 + (tk >> 4), gc = ww * 16 + (tk & 15);
            __half* op = g_oh + ((bimg * 128 + gr) * 128 + gc) * 256 + hd * 32;
#pragma unroll
            for (int dn = 0; dn < 4; dn++) {
                *(__half2*)(op + dn * 8 + t * 2) =
                    __floats2half2_rn(o[mt][dn][half * 2] * inv, o[mt][dn][half * 2 + 1] * inv);
            }
        }
    }
}

// ---------------------------------------------------------------------------
extern "C" void kernel_launch(void* const* d_in, const int* in_sizes, int n_in,
                              void* d_out, int out_size) {
    (void)in_sizes; (void)n_in; (void)out_size;
    const float* x_wsa      = (const float*)d_in[0];
    const float* x_original = (const float*)d_in[1];
    const float* q_w        = (const float*)d_in[2];
    const float* q_b        = (const float*)d_in[3];
    const float* kv_w       = (const float*)d_in[4];
    const float* kv_b       = (const float*)d_in[5];
    const float* out_w      = (const float*)d_in[6];
    const float* out_b      = (const float*)d_in[7];
    const float* bias_table = (const float*)d_in[8];
    const float* rezero     = (const float*)d_in[9];
    float* out = (float*)d_out;

    cudaFuncSetAttribute(convkv_mma, cudaFuncAttributeMaxDynamicSharedMemorySize, CONV_SMEM_B);
    cudaFuncSetAttribute(gemm_mma<0>, cudaFuncAttributeMaxDynamicSharedMemorySize, GEMM_SMEM_B0);
    cudaFuncSetAttribute(gemm_mma<1>, cudaFuncAttributeMaxDynamicSharedMemorySize, GEMM_SMEM_B1);
    cudaFuncSetAttribute(attn_mma, cudaFuncAttributeMaxDynamicSharedMemorySize, ATT_SMEM_B);

    prep_all<<<4160, 256>>>(bias_table, q_w, out_w, kv_w);                          // #1
    gemm_mma<0><<<dim3(512, 4), 256, GEMM_SMEM_B0>>>(x_wsa, q_b, nullptr, nullptr); // #2
    convkv_mma<<<dim3(64, 32), 256, CONV_SMEM_B>>>(x_original, kv_b);               // #3
    attn_mma<<<dim3(256, 8), 256, ATT_SMEM_B>>>();                                  // #4 <- profiled
    gemm_mma<1><<<dim3(512, 4), 256, GEMM_SMEM_B1>>>(nullptr, out_b, rezero, out);  // #5
}

// round 16
// speedup vs baseline: 2.4607x; 1.0002x over previous
#include <cuda_runtime.h>
#include <cuda_fp16.h>

// B=4, H=W=128, C=256, heads=8, d=32, win=16 -> 256 windows x 256 tokens
__device__ __half g_qh[16777216];
__device__ __half g_kh[16777216];
__device__ __half g_vh[16777216];
__device__ __half g_oh[16777216];
__device__ float g_bias[524288];    // [head][256 q][256 k], = bt*log2e - 8 (static shift)
__device__ __half g_wth[135168];    // 2 x [256 n][264 pitch k] fp16: qw^T, ow^T
__device__ __half g_wcth[204800];   // conv weights fp16: [(g*64+oc)][25 taps * 32 k] pitch 800

__device__ __forceinline__ float ex2(float x) {
    float r;
    asm("ex2.approx.ftz.f32 %0, %1;" : "=f"(r) : "f"(x));
    return r;
}

__device__ __forceinline__ void mma_f16(float* c, const unsigned* a, unsigned b0, unsigned b1) {
    asm volatile(
        "mma.sync.aligned.m16n8k16.row.col.f32.f16.f16.f32 "
        "{%0,%1,%2,%3},{%4,%5,%6,%7},{%8,%9},{%0,%1,%2,%3};"
        : "+f"(c[0]), "+f"(c[1]), "+f"(c[2]), "+f"(c[3])
        : "r"(a[0]), "r"(a[1]), "r"(a[2]), "r"(a[3]), "r"(b0), "r"(b1));
}

__device__ __forceinline__ void ldsm4h(unsigned* r, const __half* p) {
    unsigned a = (unsigned)__cvta_generic_to_shared(p);
    asm volatile("ldmatrix.sync.aligned.m8n8.x4.shared.b16 {%0,%1,%2,%3}, [%4];"
                 : "=r"(r[0]), "=r"(r[1]), "=r"(r[2]), "=r"(r[3]) : "r"(a));
}

__device__ __forceinline__ void cpa16h(__half* dst, const __half* src) {
    unsigned d = (unsigned)__cvta_generic_to_shared(dst);
    asm volatile("cp.async.cg.shared.global [%0], [%1], 16;" :: "r"(d), "l"(src));
}

// ---------------------------------------------------------------------------
// Prep (ONE kernel).
// ---------------------------------------------------------------------------
__global__ void prep_all(const float* __restrict__ bt,
                         const float* __restrict__ qw,
                         const float* __restrict__ ow,
                         const float* __restrict__ Wc) {
    const int idx = blockIdx.x * 256 + threadIdx.x;
    if (idx < 524288) {
        const int hd = idx >> 16, qt = (idx >> 8) & 255, kt = idx & 255;
        const int qy = qt >> 4, qx = qt & 15, ky = kt >> 4, kx = kt & 15;
        const int rel = (qy - ky + 15) * 31 + (qx - kx + 15);
        g_bias[idx] = bt[rel * 8 + hd] * 1.4426950408889634f - 8.0f;
    } else if (idx < 655360) {
        const int i2 = idx - 524288;
        const int slot = i2 >> 16;
        const int r = i2 & 65535;
        const int n = r >> 8, k = r & 255;
        const float* W = slot ? ow : qw;
        g_wth[slot * 67584 + n * 264 + k] = __float2half_rn(W[k * 256 + n]);
    } else {
        const int i3 = idx - 655360;
        const int k = i3 & 31;
        const int tap = (i3 >> 5) % 25;
        const int ocg = i3 / 800;
        const int g = ocg >> 6, oc = ocg & 63;
        g_wcth[ocg * 800 + tap * 32 + k] = __float2half_rn(Wc[(tap * 32 + k) * 512 + g * 64 + oc]);
    }
}

// ---------------------------------------------------------------------------
// Conv 5x5 grouped — fp16 mma, FOUR taps per pipeline round (7 rounds).
// ---------------------------------------------------------------------------
#define CONV_PATCH_H 16000    // 400 * 40 halfs
#define CONV_WTAP_H  2560     // 64 oc * 40 halfs
#define CONV_WQUAD_H (4*CONV_WTAP_H)
#define CONV_SMEM_B  (CONV_PATCH_H*2 + 3*CONV_WQUAD_H*2)   // 93440 B

__global__ __launch_bounds__(256, 2) void convkv_mma(const float* __restrict__ X,
                                                     const float* __restrict__ bias) {
    extern __shared__ char smc[];
    __half* patch = (__half*)smc;
    __half* wring = patch + CONV_PATCH_H;

    const int tid = threadIdx.x;
    const int lane = tid & 31, warp = tid >> 5;
    const int wm = warp & 3, wn = warp >> 2;
    const int g8 = lane >> 3, r8 = lane & 7;
    const int tile = blockIdx.x;
    const int ty0 = (tile >> 3) * 16, tx0 = (tile & 7) * 16;
    const int b = blockIdx.y >> 3, g = blockIdx.y & 7;

    const __half* wsrc = g_wcth + (g * 64) * 800;

    // Issue weight quads 0 and 1 (taps 0..7) into ring slots 0,1
#pragma unroll
    for (int qd = 0; qd < 2; qd++) {
#pragma unroll
        for (int c = 0; c < 4; c++) {
            const int idx = c * 256 + tid;              // 0..1023
            const int t4 = idx >> 8, rest = idx & 255;
            const int row = rest >> 2, seg = (rest & 3) * 8;
            cpa16h(wring + qd * CONV_WQUAD_H + t4 * CONV_WTAP_H + row * 40 + seg,
                   wsrc + row * 800 + (qd * 4 + t4) * 32 + seg);
        }
        asm volatile("cp.async.commit_group;");
    }

    for (int p = tid; p < 400; p += 256) {
        int py = p / 20, px = p - py * 20;
        int gy = ty0 + py - 2, gx = tx0 + px - 2;
        bool ok = (gy >= 0 && gy < 128 && gx >= 0 && gx < 128);
        const float4* src = (const float4*)(X + ((b * 128 + gy) * 128 + gx) * 256 + g * 32);
#pragma unroll
        for (int s = 0; s < 4; s++) {
            float4 v0 = ok ? src[s * 2]     : make_float4(0.f, 0.f, 0.f, 0.f);
            float4 v1 = ok ? src[s * 2 + 1] : make_float4(0.f, 0.f, 0.f, 0.f);
            __half2 h0 = __floats2half2_rn(v0.x, v0.y);
            __half2 h1 = __floats2half2_rn(v0.z, v0.w);
            __half2 h2 = __floats2half2_rn(v1.x, v1.y);
            __half2 h3 = __floats2half2_rn(v1.z, v1.w);
            uint4 u;
            u.x = *(unsigned*)&h0; u.y = *(unsigned*)&h1;
            u.z = *(unsigned*)&h2; u.w = *(unsigned*)&h3;
            *(uint4*)&patch[p * 40 + s * 8] = u;
        }
    }

    float acc[4][4][4] = {};

#pragma unroll 1
    for (int rnd = 0; rnd < 7; rnd++) {
        if (rnd < 5) asm volatile("cp.async.wait_group 1;");
        else         asm volatile("cp.async.wait_group 0;");
        __syncthreads();
        if (rnd < 5) {
            const int nq = rnd + 2;                     // quad to issue (taps 4nq..4nq+3)
            __half* dst = wring + (nq % 3) * CONV_WQUAD_H;
#pragma unroll
            for (int c = 0; c < 4; c++) {
                const int idx = c * 256 + tid;
                const int t4 = idx >> 8, rest = idx & 255;
                const int row = rest >> 2, seg = (rest & 3) * 8;
                const int tap = nq * 4 + t4;
                if (tap < 25)
                    cpa16h(dst + t4 * CONV_WTAP_H + row * 40 + seg,
                           wsrc + row * 800 + tap * 32 + seg);
            }
            asm volatile("cp.async.commit_group;");
        }

#pragma unroll
        for (int t4 = 0; t4 < 4; t4++) {
            const int tap = rnd * 4 + t4;
            if (tap < 25) {
                const int ky = tap / 5, kx = tap - ky * 5;
                const __half* wcur = wring + (rnd % 3) * CONV_WQUAD_H + t4 * CONV_WTAP_H;
#pragma unroll
                for (int kc = 0; kc < 2; kc++) {
                    unsigned a[4][4];
#pragma unroll
                    for (int i = 0; i < 4; i++) {
                        const __half* ap = patch
                            + ((wm * 4 + i + ky) * 20 + (g8 & 1) * 8 + r8 + kx) * 40
                            + kc * 16 + (g8 >> 1) * 8;
                        ldsm4h(a[i], ap);
                    }
                    unsigned bf0[4], bf1[4];
                    ldsm4h(bf0, wcur + (wn * 32 + (g8 & 1) * 8 + r8) * 40 + kc * 16 + (g8 >> 1) * 8);
                    ldsm4h(bf1, wcur + (wn * 32 + 16 + (g8 & 1) * 8 + r8) * 40 + kc * 16 + (g8 >> 1) * 8);
#pragma unroll
                    for (int i = 0; i < 4; i++) {
                        mma_f16(acc[i][0], a[i], bf0[0], bf0[2]);
                        mma_f16(acc[i][1], a[i], bf0[1], bf0[3]);
                        mma_f16(acc[i][2], a[i], bf1[0], bf1[2]);
                        mma_f16(acc[i][3], a[i], bf1[1], bf1[3]);
                    }
                }
            }
        }
    }

    const int win = b * 64 + (tile >> 3) * 8 + (tile & 7);
    const int head = (g & 3) * 2 + wn;
    if (g < 4) {   // K: [key][d] fp16
        __half* base = g_kh + ((win * 8 + head) * 256) * 32;
#pragma unroll
        for (int i = 0; i < 4; i++) {
            const int p0 = wm * 64 + i * 16 + (lane >> 2);
#pragma unroll
            for (int j = 0; j < 4; j++) {
                const int col = wn * 32 + j * 8 + (lane & 3) * 2;
                const int d = col & 31;
                float b0 = bias[g * 64 + col], b1 = bias[g * 64 + col + 1];
                *(__half2*)(base + p0 * 32 + d) =
                    __floats2half2_rn(acc[i][j][0] + b0, acc[i][j][1] + b1);
                *(__half2*)(base + (p0 + 8) * 32 + d) =
                    __floats2half2_rn(acc[i][j][2] + b0, acc[i][j][3] + b1);
            }
        }
    } else {       // V transposed: [d][key] fp16
        __half* base = g_vh + ((win * 8 + head) * 32) * 256;
#pragma unroll
        for (int i = 0; i < 4; i++) {
            const int p0 = wm * 64 + i * 16 + (lane >> 2);
#pragma unroll
            for (int j = 0; j < 4; j++) {
                const int col = wn * 32 + j * 8 + (lane & 3) * 2;
                const int d0 = col & 31;
                float b0 = bias[g * 64 + col], b1 = bias[g * 64 + col + 1];
                base[d0 * 256 + p0]           = __float2half_rn(acc[i][j][0] + b0);
                base[(d0 + 1) * 256 + p0]     = __float2half_rn(acc[i][j][1] + b1);
                base[d0 * 256 + p0 + 8]       = __float2half_rn(acc[i][j][2] + b0);
                base[(d0 + 1) * 256 + p0 + 8] = __float2half_rn(acc[i][j][3] + b1);
            }
        }
    }
}

// ---------------------------------------------------------------------------
// fp16 GEMM m16n8k16 (unchanged from R14/R15).
// ---------------------------------------------------------------------------
#define GEMM_A_H 5120
#define GEMM_B_H 2560
#define GEMM_SLOT_H (GEMM_A_H + GEMM_B_H)
#define GEMM_SMEM_B0 ((2*GEMM_A_H + 3*GEMM_B_H) * 2)
#define GEMM_SMEM_B1 ((3*GEMM_SLOT_H) * 2)

template <int MODE>
__global__ __launch_bounds__(256, 2) void gemm_mma(const float* __restrict__ Aparam,
                                                   const float* __restrict__ bias,
                                                   const float* __restrict__ rz,
                                                   float* __restrict__ out) {
    extern __shared__ char smc[];
    __half* smem = (__half*)smc;

    const float* Af = Aparam;
    const __half* Ah = g_oh;
    const __half* wt = g_wth + MODE * 67584;

    const int tid = threadIdx.x;
    const int lane = tid & 31, warp = tid >> 5;
    const int wm = warp & 3, wn = warp >> 2;
    const int g8 = lane >> 3, r8 = lane & 7;
    const int m0 = blockIdx.x * 128;
    const int n0 = blockIdx.y * 64;

    const int arow = tid >> 1, akoff = (tid & 1) * 16;

#pragma unroll
    for (int c0 = 0; c0 < 2; c0++) {
        if (MODE == 1) {
            __half* sa = smem + c0 * GEMM_SLOT_H;
#pragma unroll
            for (int c = 0; c < 2; c++) {
                const int idx = c * 256 + tid;
                const int row = idx >> 2, seg = (idx & 3) * 8;
                cpa16h(sa + row * 40 + seg, Ah + (m0 + row) * 256 + c0 * 32 + seg);
            }
            __half* sb = sa + GEMM_A_H;
            const int row = tid >> 2, seg = (tid & 3) * 8;
            cpa16h(sb + row * 40 + seg, wt + (n0 + row) * 264 + c0 * 32 + seg);
        } else {
            __half* sb = smem + 2 * GEMM_A_H + c0 * GEMM_B_H;
            const int row = tid >> 2, seg = (tid & 3) * 8;
            cpa16h(sb + row * 40 + seg, wt + (n0 + row) * 264 + c0 * 32 + seg);
        }
        asm volatile("cp.async.commit_group;");
    }

    if (MODE == 0) {
        const float4* ga = (const float4*)(Af + (m0 + arow) * 256 + akoff);
        __half* da = smem + arow * 40 + akoff;
#pragma unroll
        for (int c8 = 0; c8 < 2; c8++) {
            float4 v0 = ga[c8 * 2], v1 = ga[c8 * 2 + 1];
            __half2 h0 = __floats2half2_rn(v0.x, v0.y);
            __half2 h1 = __floats2half2_rn(v0.z, v0.w);
            __half2 h2 = __floats2half2_rn(v1.x, v1.y);
            __half2 h3 = __floats2half2_rn(v1.z, v1.w);
            uint4 u;
            u.x = *(unsigned*)&h0; u.y = *(unsigned*)&h1;
            u.z = *(unsigned*)&h2; u.w = *(unsigned*)&h3;
            *(uint4*)(da + c8 * 8) = u;
        }
    }

    float acc[2][4][4] = {};

#pragma unroll 1
    for (int kt = 0; kt < 8; kt++) {
        float4 pa[4];
        if (MODE == 0 && kt < 7) {
            const float4* ga = (const float4*)(Af + (m0 + arow) * 256 + (kt + 1) * 32 + akoff);
#pragma unroll
            for (int c4 = 0; c4 < 4; c4++) pa[c4] = ga[c4];
        }
        if (kt < 6) asm volatile("cp.async.wait_group 1;");
        else        asm volatile("cp.async.wait_group 0;");
        __syncthreads();
        if (kt < 6) {
            const int nt = kt + 2;
            if (MODE == 1) {
                __half* sa = smem + (nt % 3) * GEMM_SLOT_H;
#pragma unroll
                for (int c = 0; c < 2; c++) {
                    const int idx = c * 256 + tid;
                    const int row = idx >> 2, seg = (idx & 3) * 8;
                    cpa16h(sa + row * 40 + seg, Ah + (m0 + row) * 256 + nt * 32 + seg);
                }
                __half* sb = sa + GEMM_A_H;
                const int row = tid >> 2, seg = (tid & 3) * 8;
                cpa16h(sb + row * 40 + seg, wt + (n0 + row) * 264 + nt * 32 + seg);
            } else {
                __half* sb = smem + 2 * GEMM_A_H + (nt % 3) * GEMM_B_H;
                const int row = tid >> 2, seg = (tid & 3) * 8;
                cpa16h(sb + row * 40 + seg, wt + (n0 + row) * 264 + nt * 32 + seg);
            }
            asm volatile("cp.async.commit_group;");
        }
        const __half* acur = (MODE == 1) ? (smem + (kt % 3) * GEMM_SLOT_H)
                                         : (smem + (kt & 1) * GEMM_A_H);
        const __half* bcur = (MODE == 1) ? (smem + (kt % 3) * GEMM_SLOT_H + GEMM_A_H)
                                         : (smem + 2 * GEMM_A_H + (kt % 3) * GEMM_B_H);
#pragma unroll
        for (int kc = 0; kc < 2; kc++) {
            unsigned a[2][4];
#pragma unroll
            for (int i = 0; i < 2; i++) {
                const __half* ap = acur + (wm * 32 + i * 16 + (g8 & 1) * 8 + r8) * 40
                                   + kc * 16 + (g8 >> 1) * 8;
                ldsm4h(a[i], ap);
            }
            unsigned bf0[4], bf1[4];
            ldsm4h(bf0, bcur + (wn * 32 + (g8 & 1) * 8 + r8) * 40 + kc * 16 + (g8 >> 1) * 8);
            ldsm4h(bf1, bcur + (wn * 32 + 16 + (g8 & 1) * 8 + r8) * 40 + kc * 16 + (g8 >> 1) * 8);
#pragma unroll
            for (int i = 0; i < 2; i++) {
                mma_f16(acc[i][0], a[i], bf0[0], bf0[2]);
                mma_f16(acc[i][1], a[i], bf0[1], bf0[3]);
                mma_f16(acc[i][2], a[i], bf1[0], bf1[2]);
                mma_f16(acc[i][3], a[i], bf1[1], bf1[3]);
            }
        }
        if (MODE == 0 && kt < 7) {
            __half* da = smem + ((kt + 1) & 1) * GEMM_A_H + arow * 40 + akoff;
#pragma unroll
            for (int c8 = 0; c8 < 2; c8++) {
                float4 v0 = pa[c8 * 2], v1 = pa[c8 * 2 + 1];
                __half2 h0 = __floats2half2_rn(v0.x, v0.y);
                __half2 h1 = __floats2half2_rn(v0.z, v0.w);
                __half2 h2 = __floats2half2_rn(v1.x, v1.y);
                __half2 h3 = __floats2half2_rn(v1.z, v1.w);
                uint4 u;
                u.x = *(unsigned*)&h0; u.y = *(unsigned*)&h1;
                u.z = *(unsigned*)&h2; u.w = *(unsigned*)&h3;
                *(uint4*)(da + c8 * 8) = u;
            }
        }
    }

    const float scale = 0.17677669529663687f * 1.4426950408889634f;
    const float r = (MODE == 1) ? rz[0] : 0.f;
#pragma unroll
    for (int i = 0; i < 2; i++) {
        const int m = m0 + wm * 32 + i * 16 + (lane >> 2);
#pragma unroll
        for (int j = 0; j < 4; j++) {
            const int col = n0 + wn * 32 + j * 8 + (lane & 3) * 2;
            const float b0 = bias[col], b1 = bias[col + 1];
            if (MODE == 0) {
                const int bi = m >> 14, rr = (m >> 7) & 127, cc = m & 127;
                const int win = bi * 64 + ((rr >> 4) << 3) + (cc >> 4);
                const int t = (rr & 15) * 16 + (cc & 15);
                const int head = col >> 5, d = col & 31;
                __half* p = g_qh + ((win * 8 + head) * 256 + t) * 32 + d;
                *(__half2*)p = __floats2half2_rn((acc[i][j][0] + b0) * scale,
                                                 (acc[i][j][1] + b1) * scale);
                *(__half2*)(p + 8 * 32) = __floats2half2_rn((acc[i][j][2] + b0) * scale,
                                                            (acc[i][j][3] + b1) * scale);
            } else {
                float* p = out + m * 256 + col;
                *(float2*)p = make_float2(r * (acc[i][j][0] + b0), r * (acc[i][j][1] + b1));
                *(float2*)(p + 8 * 256) = make_float2(r * (acc[i][j][2] + b0), r * (acc[i][j][3] + b1));
            }
        }
    }
}

// ---------------------------------------------------------------------------
// fp16 flash attention, static softmax shift, 64 KEYS PER ROUND (4 rounds):
// pair-slot ring; two independent sub-chunks per round with separate P
// buffers -> one syncwarp between exp phase and a doubled PV phase.
// ---------------------------------------------------------------------------
#define ATT_QS_H 10240            // 256*40
#define ATT_CH_H 1280             // one 32-key chunk: 32*40
#define ATT_PAIR_H (2*ATT_CH_H)
#define ATT_KS_H (3*ATT_PAIR_H)   // 7680
#define ATT_VS_H (3*ATT_PAIR_H)
#define ATT_PS_H 20480            // 8 warps * 2 bufs * 1280
#define ATT_SMEM_B ((ATT_QS_H + ATT_KS_H + ATT_VS_H + ATT_PS_H) * 2)  // 92160 B

__global__ __launch_bounds__(256, 2) void attn_mma() {
    extern __shared__ char smc[];
    __half* Qs = (__half*)smc;
    __half* Ks = Qs + ATT_QS_H;
    __half* Vs = Ks + ATT_KS_H;
    __half* Ps = Vs + ATT_VS_H;

    const int win = blockIdx.x, hd = blockIdx.y;
    const int tid = threadIdx.x;
    const int lane = tid & 31, warp = tid >> 5;
    const int q = lane >> 2, t = lane & 3;
    const int g8 = lane >> 3, r8 = lane & 7;
    const int wb = warp * 32;
    __half* Pw = Ps + warp * 2560;   // two 1280 buffers

    const __half* qh = g_qh + (win * 8 + hd) * 8192;
    const __half* kh = g_kh + (win * 8 + hd) * 8192;
    const __half* vth = g_vh + (win * 8 + hd) * 8192;
    const float* bb = g_bias + (hd << 16);

    // Stage Q (LDG.128)
#pragma unroll
    for (int c = 0; c < 4; c++) {
        const int i = c * 256 + tid;
        const int row = i >> 2, seg = (i & 3) * 8;
        *(uint4*)&Qs[row * 40 + seg] = *(const uint4*)&qh[row * 32 + seg];
    }
    // K/V pairs 0,1 (chunks 0..3) via cp.async
    {
        const int r = (tid & 127) >> 2, sg = (tid & 3) * 8;
#pragma unroll
        for (int pr = 0; pr < 2; pr++) {
#pragma unroll
            for (int c = 0; c < 2; c++) {
                const int ch = pr * 2 + c;
                if (tid < 128) cpa16h(Ks + pr * ATT_PAIR_H + c * ATT_CH_H + r * 40 + sg,
                                      kh + (ch * 32 + r) * 32 + sg);
                else           cpa16h(Vs + pr * ATT_PAIR_H + c * ATT_CH_H + r * 40 + sg,
                                      vth + r * 256 + ch * 32 + sg);
            }
            asm volatile("cp.async.commit_group;");
        }
    }
    __syncthreads();

    unsigned qa[2][2][4];
#pragma unroll
    for (int mt = 0; mt < 2; mt++)
#pragma unroll
        for (int kc = 0; kc < 2; kc++)
            ldsm4h(qa[mt][kc], Qs + (wb + mt * 16 + (g8 & 1) * 8 + r8) * 40 + kc * 16 + (g8 >> 1) * 8);

    float o[2][4][4] = {};
    float lrow[2][2] = {};

#pragma unroll 1
    for (int rnd = 0; rnd < 4; rnd++) {
        if (rnd < 3) asm volatile("cp.async.wait_group 1;");
        else         asm volatile("cp.async.wait_group 0;");
        __syncthreads();

        if (rnd < 2) {
            const int np = rnd + 2;
            const int slot = np % 3;
            const int r = (tid & 127) >> 2, sg = (tid & 3) * 8;
#pragma unroll
            for (int c = 0; c < 2; c++) {
                const int ch = np * 2 + c;
                if (tid < 128) cpa16h(Ks + slot * ATT_PAIR_H + c * ATT_CH_H + r * 40 + sg,
                                      kh + (ch * 32 + r) * 32 + sg);
                else           cpa16h(Vs + slot * ATT_PAIR_H + c * ATT_CH_H + r * 40 + sg,
                                      vth + r * 256 + ch * 32 + sg);
            }
            asm volatile("cp.async.commit_group;");
        }

        const __half* Kp = Ks + (rnd % 3) * ATT_PAIR_H;
        const __half* Vp = Vs + (rnd % 3) * ATT_PAIR_H;

        // ---- Phase 1: S and exp for both sub-chunks -> P_A, P_B ----
#pragma unroll
        for (int sub = 0; sub < 2; sub++) {
            const __half* Kb = Kp + sub * ATT_CH_H;
            __half* Pb = Pw + sub * ATT_CH_H;
            const int sbk = rnd * 2 + sub;
            float s[2][4][4];
#pragma unroll
            for (int mt = 0; mt < 2; mt++) {
                const float* br0 = bb + (wb + mt * 16 + q) * 256 + sbk * 32 + t * 2;
                const float* br1 = br0 + 8 * 256;
#pragma unroll
                for (int nt = 0; nt < 4; nt++) {
                    float2 b0 = *(const float2*)(br0 + nt * 8);
                    float2 b1 = *(const float2*)(br1 + nt * 8);
                    s[mt][nt][0] = b0.x; s[mt][nt][1] = b0.y;
                    s[mt][nt][2] = b1.x; s[mt][nt][3] = b1.y;
                }
            }
#pragma unroll
            for (int kc = 0; kc < 2; kc++) {
#pragma unroll
                for (int nt16 = 0; nt16 < 2; nt16++) {
                    unsigned kf[4];
                    ldsm4h(kf, Kb + (nt16 * 16 + (g8 & 1) * 8 + r8) * 40 + kc * 16 + (g8 >> 1) * 8);
                    mma_f16(s[0][nt16 * 2 + 0], qa[0][kc], kf[0], kf[2]);
                    mma_f16(s[0][nt16 * 2 + 1], qa[0][kc], kf[1], kf[3]);
                    mma_f16(s[1][nt16 * 2 + 0], qa[1][kc], kf[0], kf[2]);
                    mma_f16(s[1][nt16 * 2 + 1], qa[1][kc], kf[1], kf[3]);
                }
            }
#pragma unroll
            for (int mt = 0; mt < 2; mt++) {
                float sm0 = 0.f, sm1 = 0.f;
#pragma unroll
                for (int nt = 0; nt < 4; nt++) {
                    float p0 = ex2(s[mt][nt][0]);
                    float p1 = ex2(s[mt][nt][1]);
                    float p2 = ex2(s[mt][nt][2]);
                    float p3 = ex2(s[mt][nt][3]);
                    sm0 += p0 + p1; sm1 += p2 + p3;
                    *(__half2*)&Pb[(mt * 16 + q) * 40 + nt * 8 + 2 * t] = __floats2half2_rn(p0, p1);
                    *(__half2*)&Pb[(mt * 16 + q + 8) * 40 + nt * 8 + 2 * t] = __floats2half2_rn(p2, p3);
                }
                lrow[mt][0] += sm0;
                lrow[mt][1] += sm1;
            }
        }
        __syncwarp();

        // ---- Phase 2: PV for both sub-chunks (independent mma chains) ----
#pragma unroll
        for (int sub = 0; sub < 2; sub++) {
            const __half* Vb = Vp + sub * ATT_CH_H;
            const __half* Pb = Pw + sub * ATT_CH_H;
#pragma unroll
            for (int kk = 0; kk < 2; kk++) {
                unsigned pa[2][4];
                ldsm4h(pa[0], Pb + ((g8 & 1) * 8 + r8) * 40 + kk * 16 + (g8 >> 1) * 8);
                ldsm4h(pa[1], Pb + (16 + (g8 & 1) * 8 + r8) * 40 + kk * 16 + (g8 >> 1) * 8);
#pragma unroll
                for (int dn16 = 0; dn16 < 2; dn16++) {
                    unsigned vf[4];
                    ldsm4h(vf, Vb + (dn16 * 16 + (g8 & 1) * 8 + r8) * 40 + kk * 16 + (g8 >> 1) * 8);
                    mma_f16(o[0][dn16 * 2 + 0], pa[0], vf[0], vf[2]);
                    mma_f16(o[0][dn16 * 2 + 1], pa[0], vf[1], vf[3]);
                    mma_f16(o[1][dn16 * 2 + 0], pa[1], vf[0], vf[2]);
                    mma_f16(o[1][dn16 * 2 + 1], pa[1], vf[1], vf[3]);
                }
            }
        }
        __syncwarp();
    }

    // Epilogue
    const int bimg = win >> 6, wh = (win >> 3) & 7, ww = win & 7;
#pragma unroll
    for (int mt = 0; mt < 2; mt++) {
        float l0 = lrow[mt][0], l1 = lrow[mt][1];
        l0 += __shfl_xor_sync(0xffffffff, l0, 1);
        l0 += __shfl_xor_sync(0xffffffff, l0, 2);
        l1 += __shfl_xor_sync(0xffffffff, l1, 1);
        l1 += __shfl_xor_sync(0xffffffff, l1, 2);
        const float inv0 = 1.f / l0;
        const float inv1 = 1.f / l1;
        const int tk0 = wb + mt * 16 + q;
#pragma unroll
        for (int half = 0; half < 2; half++) {
            const int tk = tk0 + half * 8;
            const float inv = half ? inv1 : inv0;
            const int gr = wh * 16 + (tk >> 4), gc = ww * 16 + (tk & 15);
            __half* op = g_oh + ((bimg * 128 + gr) * 128 + gc) * 256 + hd * 32;
#pragma unroll
            for (int dn = 0; dn < 4; dn++) {
                *(__half2*)(op + dn * 8 + t * 2) =
                    __floats2half2_rn(o[mt][dn][half * 2] * inv, o[mt][dn][half * 2 + 1] * inv);
            }
        }
    }
}

// ---------------------------------------------------------------------------
extern "C" void kernel_launch(void* const* d_in, const int* in_sizes, int n_in,
                              void* d_out, int out_size) {
    (void)in_sizes; (void)n_in; (void)out_size;
    const float* x_wsa      = (const float*)d_in[0];
    const float* x_original = (const float*)d_in[1];
    const float* q_w        = (const float*)d_in[2];
    const float* q_b        = (const float*)d_in[3];
    const float* kv_w       = (const float*)d_in[4];
    const float* kv_b       = (const float*)d_in[5];
    const float* out_w      = (const float*)d_in[6];
    const float* out_b      = (const float*)d_in[7];
    const float* bias_table = (const float*)d_in[8];
    const float* rezero     = (const float*)d_in[9];
    float* out = (float*)d_out;

    cudaFuncSetAttribute(convkv_mma, cudaFuncAttributeMaxDynamicSharedMemorySize, CONV_SMEM_B);
    cudaFuncSetAttribute(gemm_mma<0>, cudaFuncAttributeMaxDynamicSharedMemorySize, GEMM_SMEM_B0);
    cudaFuncSetAttribute(gemm_mma<1>, cudaFuncAttributeMaxDynamicSharedMemorySize, GEMM_SMEM_B1);
    cudaFuncSetAttribute(attn_mma, cudaFuncAttributeMaxDynamicSharedMemorySize, ATT_SMEM_B);

    prep_all<<<4160, 256>>>(bias_table, q_w, out_w, kv_w);                          // #1
    gemm_mma<0><<<dim3(512, 4), 256, GEMM_SMEM_B0>>>(x_wsa, q_b, nullptr, nullptr); // #2
    convkv_mma<<<dim3(64, 32), 256, CONV_SMEM_B>>>(x_original, kv_b);               // #3
    attn_mma<<<dim3(256, 8), 256, ATT_SMEM_B>>>();                                  // #4 <- profiled
    gemm_mma<1><<<dim3(512, 4), 256, GEMM_SMEM_B1>>>(nullptr, out_b, rezero, out);  // #5
}

// round 17
// speedup vs baseline: 2.5836x; 1.0499x over previous
#include <cuda_runtime.h>
#include <cuda_fp16.h>

// B=4, H=W=128, C=256, heads=8, d=32, win=16 -> 256 windows x 256 tokens
__device__ __half g_qh[16777216];
__device__ __half g_kh[16777216];
__device__ __half g_vh[16777216];
__device__ __half g_oh[16777216];
__device__ float g_bias[524288];    // [head][256 q][256 k], = bt*log2e - 8 (static shift)
__device__ __half g_wth[135168];    // 2 x [256 n][264 pitch k] fp16: qw^T, ow^T
__device__ __half g_wcth[204800];   // conv weights fp16: [(g*64+oc)][25 taps * 32 k] pitch 800

__device__ __forceinline__ float ex2(float x) {
    float r;
    asm("ex2.approx.ftz.f32 %0, %1;" : "=f"(r) : "f"(x));
    return r;
}

__device__ __forceinline__ void mma_f16(float* c, const unsigned* a, unsigned b0, unsigned b1) {
    asm volatile(
        "mma.sync.aligned.m16n8k16.row.col.f32.f16.f16.f32 "
        "{%0,%1,%2,%3},{%4,%5,%6,%7},{%8,%9},{%0,%1,%2,%3};"
        : "+f"(c[0]), "+f"(c[1]), "+f"(c[2]), "+f"(c[3])
        : "r"(a[0]), "r"(a[1]), "r"(a[2]), "r"(a[3]), "r"(b0), "r"(b1));
}

__device__ __forceinline__ void ldsm4h(unsigned* r, const __half* p) {
    unsigned a = (unsigned)__cvta_generic_to_shared(p);
    asm volatile("ldmatrix.sync.aligned.m8n8.x4.shared.b16 {%0,%1,%2,%3}, [%4];"
                 : "=r"(r[0]), "=r"(r[1]), "=r"(r[2]), "=r"(r[3]) : "r"(a));
}

__device__ __forceinline__ void cpa16h(__half* dst, const __half* src) {
    unsigned d = (unsigned)__cvta_generic_to_shared(dst);
    asm volatile("cp.async.cg.shared.global [%0], [%1], 16;" :: "r"(d), "l"(src));
}

__device__ __forceinline__ unsigned packh2(float a, float b) {
    __half2 h = __floats2half2_rn(a, b);
    return *(unsigned*)&h;
}

// ---------------------------------------------------------------------------
// Prep (ONE kernel).
// ---------------------------------------------------------------------------
__global__ void prep_all(const float* __restrict__ bt,
                         const float* __restrict__ qw,
                         const float* __restrict__ ow,
                         const float* __restrict__ Wc) {
    const int idx = blockIdx.x * 256 + threadIdx.x;
    if (idx < 524288) {
        const int hd = idx >> 16, qt = (idx >> 8) & 255, kt = idx & 255;
        const int qy = qt >> 4, qx = qt & 15, ky = kt >> 4, kx = kt & 15;
        const int rel = (qy - ky + 15) * 31 + (qx - kx + 15);
        g_bias[idx] = bt[rel * 8 + hd] * 1.4426950408889634f - 8.0f;
    } else if (idx < 655360) {
        const int i2 = idx - 524288;
        const int slot = i2 >> 16;
        const int r = i2 & 65535;
        const int n = r >> 8, k = r & 255;
        const float* W = slot ? ow : qw;
        g_wth[slot * 67584 + n * 264 + k] = __float2half_rn(W[k * 256 + n]);
    } else {
        const int i3 = idx - 655360;
        const int k = i3 & 31;
        const int tap = (i3 >> 5) % 25;
        const int ocg = i3 / 800;
        const int g = ocg >> 6, oc = ocg & 63;
        g_wcth[ocg * 800 + tap * 32 + k] = __float2half_rn(Wc[(tap * 32 + k) * 512 + g * 64 + oc]);
    }
}

// ---------------------------------------------------------------------------
// Conv 5x5 grouped — fp16 mma, FOUR taps per pipeline round (R16, kept).
// ---------------------------------------------------------------------------
#define CONV_PATCH_H 16000
#define CONV_WTAP_H  2560
#define CONV_WQUAD_H (4*CONV_WTAP_H)
#define CONV_SMEM_B  (CONV_PATCH_H*2 + 3*CONV_WQUAD_H*2)   // 93440 B

__global__ __launch_bounds__(256, 2) void convkv_mma(const float* __restrict__ X,
                                                     const float* __restrict__ bias) {
    extern __shared__ char smc[];
    __half* patch = (__half*)smc;
    __half* wring = patch + CONV_PATCH_H;

    const int tid = threadIdx.x;
    const int lane = tid & 31, warp = tid >> 5;
    const int wm = warp & 3, wn = warp >> 2;
    const int g8 = lane >> 3, r8 = lane & 7;
    const int tile = blockIdx.x;
    const int ty0 = (tile >> 3) * 16, tx0 = (tile & 7) * 16;
    const int b = blockIdx.y >> 3, g = blockIdx.y & 7;

    const __half* wsrc = g_wcth + (g * 64) * 800;

#pragma unroll
    for (int qd = 0; qd < 2; qd++) {
#pragma unroll
        for (int c = 0; c < 4; c++) {
            const int idx = c * 256 + tid;
            const int t4 = idx >> 8, rest = idx & 255;
            const int row = rest >> 2, seg = (rest & 3) * 8;
            cpa16h(wring + qd * CONV_WQUAD_H + t4 * CONV_WTAP_H + row * 40 + seg,
                   wsrc + row * 800 + (qd * 4 + t4) * 32 + seg);
        }
        asm volatile("cp.async.commit_group;");
    }

    for (int p = tid; p < 400; p += 256) {
        int py = p / 20, px = p - py * 20;
        int gy = ty0 + py - 2, gx = tx0 + px - 2;
        bool ok = (gy >= 0 && gy < 128 && gx >= 0 && gx < 128);
        const float4* src = (const float4*)(X + ((b * 128 + gy) * 128 + gx) * 256 + g * 32);
#pragma unroll
        for (int s = 0; s < 4; s++) {
            float4 v0 = ok ? src[s * 2]     : make_float4(0.f, 0.f, 0.f, 0.f);
            float4 v1 = ok ? src[s * 2 + 1] : make_float4(0.f, 0.f, 0.f, 0.f);
            __half2 h0 = __floats2half2_rn(v0.x, v0.y);
            __half2 h1 = __floats2half2_rn(v0.z, v0.w);
            __half2 h2 = __floats2half2_rn(v1.x, v1.y);
            __half2 h3 = __floats2half2_rn(v1.z, v1.w);
            uint4 u;
            u.x = *(unsigned*)&h0; u.y = *(unsigned*)&h1;
            u.z = *(unsigned*)&h2; u.w = *(unsigned*)&h3;
            *(uint4*)&patch[p * 40 + s * 8] = u;
        }
    }

    float acc[4][4][4] = {};

#pragma unroll 1
    for (int rnd = 0; rnd < 7; rnd++) {
        if (rnd < 5) asm volatile("cp.async.wait_group 1;");
        else         asm volatile("cp.async.wait_group 0;");
        __syncthreads();
        if (rnd < 5) {
            const int nq = rnd + 2;
            __half* dst = wring + (nq % 3) * CONV_WQUAD_H;
#pragma unroll
            for (int c = 0; c < 4; c++) {
                const int idx = c * 256 + tid;
                const int t4 = idx >> 8, rest = idx & 255;
                const int row = rest >> 2, seg = (rest & 3) * 8;
                const int tap = nq * 4 + t4;
                if (tap < 25)
                    cpa16h(dst + t4 * CONV_WTAP_H + row * 40 + seg,
                           wsrc + row * 800 + tap * 32 + seg);
            }
            asm volatile("cp.async.commit_group;");
        }

#pragma unroll
        for (int t4 = 0; t4 < 4; t4++) {
            const int tap = rnd * 4 + t4;
            if (tap < 25) {
                const int ky = tap / 5, kx = tap - ky * 5;
                const __half* wcur = wring + (rnd % 3) * CONV_WQUAD_H + t4 * CONV_WTAP_H;
#pragma unroll
                for (int kc = 0; kc < 2; kc++) {
                    unsigned a[4][4];
#pragma unroll
                    for (int i = 0; i < 4; i++) {
                        const __half* ap = patch
                            + ((wm * 4 + i + ky) * 20 + (g8 & 1) * 8 + r8 + kx) * 40
                            + kc * 16 + (g8 >> 1) * 8;
                        ldsm4h(a[i], ap);
                    }
                    unsigned bf0[4], bf1[4];
                    ldsm4h(bf0, wcur + (wn * 32 + (g8 & 1) * 8 + r8) * 40 + kc * 16 + (g8 >> 1) * 8);
                    ldsm4h(bf1, wcur + (wn * 32 + 16 + (g8 & 1) * 8 + r8) * 40 + kc * 16 + (g8 >> 1) * 8);
#pragma unroll
                    for (int i = 0; i < 4; i++) {
                        mma_f16(acc[i][0], a[i], bf0[0], bf0[2]);
                        mma_f16(acc[i][1], a[i], bf0[1], bf0[3]);
                        mma_f16(acc[i][2], a[i], bf1[0], bf1[2]);
                        mma_f16(acc[i][3], a[i], bf1[1], bf1[3]);
                    }
                }
            }
        }
    }

    const int win = b * 64 + (tile >> 3) * 8 + (tile & 7);
    const int head = (g & 3) * 2 + wn;
    if (g < 4) {
        __half* base = g_kh + ((win * 8 + head) * 256) * 32;
#pragma unroll
        for (int i = 0; i < 4; i++) {
            const int p0 = wm * 64 + i * 16 + (lane >> 2);
#pragma unroll
            for (int j = 0; j < 4; j++) {
                const int col = wn * 32 + j * 8 + (lane & 3) * 2;
                const int d = col & 31;
                float b0 = bias[g * 64 + col], b1 = bias[g * 64 + col + 1];
                *(__half2*)(base + p0 * 32 + d) =
                    __floats2half2_rn(acc[i][j][0] + b0, acc[i][j][1] + b1);
                *(__half2*)(base + (p0 + 8) * 32 + d) =
                    __floats2half2_rn(acc[i][j][2] + b0, acc[i][j][3] + b1);
            }
        }
    } else {
        __half* base = g_vh + ((win * 8 + head) * 32) * 256;
#pragma unroll
        for (int i = 0; i < 4; i++) {
            const int p0 = wm * 64 + i * 16 + (lane >> 2);
#pragma unroll
            for (int j = 0; j < 4; j++) {
                const int col = wn * 32 + j * 8 + (lane & 3) * 2;
                const int d0 = col & 31;
                float b0 = bias[g * 64 + col], b1 = bias[g * 64 + col + 1];
                base[d0 * 256 + p0]           = __float2half_rn(acc[i][j][0] + b0);
                base[(d0 + 1) * 256 + p0]     = __float2half_rn(acc[i][j][1] + b1);
                base[d0 * 256 + p0 + 8]       = __float2half_rn(acc[i][j][2] + b0);
                base[(d0 + 1) * 256 + p0 + 8] = __float2half_rn(acc[i][j][3] + b1);
            }
        }
    }
}

// ---------------------------------------------------------------------------
// fp16 GEMM m16n8k16 (unchanged).
// ---------------------------------------------------------------------------
#define GEMM_A_H 5120
#define GEMM_B_H 2560
#define GEMM_SLOT_H (GEMM_A_H + GEMM_B_H)
#define GEMM_SMEM_B0 ((2*GEMM_A_H + 3*GEMM_B_H) * 2)
#define GEMM_SMEM_B1 ((3*GEMM_SLOT_H) * 2)

template <int MODE>
__global__ __launch_bounds__(256, 2) void gemm_mma(const float* __restrict__ Aparam,
                                                   const float* __restrict__ bias,
                                                   const float* __restrict__ rz,
                                                   float* __restrict__ out) {
    extern __shared__ char smc[];
    __half* smem = (__half*)smc;

    const float* Af = Aparam;
    const __half* Ah = g_oh;
    const __half* wt = g_wth + MODE * 67584;

    const int tid = threadIdx.x;
    const int lane = tid & 31, warp = tid >> 5;
    const int wm = warp & 3, wn = warp >> 2;
    const int g8 = lane >> 3, r8 = lane & 7;
    const int m0 = blockIdx.x * 128;
    const int n0 = blockIdx.y * 64;

    const int arow = tid >> 1, akoff = (tid & 1) * 16;

#pragma unroll
    for (int c0 = 0; c0 < 2; c0++) {
        if (MODE == 1) {
            __half* sa = smem + c0 * GEMM_SLOT_H;
#pragma unroll
            for (int c = 0; c < 2; c++) {
                const int idx = c * 256 + tid;
                const int row = idx >> 2, seg = (idx & 3) * 8;
                cpa16h(sa + row * 40 + seg, Ah + (m0 + row) * 256 + c0 * 32 + seg);
            }
            __half* sb = sa + GEMM_A_H;
            const int row = tid >> 2, seg = (tid & 3) * 8;
            cpa16h(sb + row * 40 + seg, wt + (n0 + row) * 264 + c0 * 32 + seg);
        } else {
            __half* sb = smem + 2 * GEMM_A_H + c0 * GEMM_B_H;
            const int row = tid >> 2, seg = (tid & 3) * 8;
            cpa16h(sb + row * 40 + seg, wt + (n0 + row) * 264 + c0 * 32 + seg);
        }
        asm volatile("cp.async.commit_group;");
    }

    if (MODE == 0) {
        const float4* ga = (const float4*)(Af + (m0 + arow) * 256 + akoff);
        __half* da = smem + arow * 40 + akoff;
#pragma unroll
        for (int c8 = 0; c8 < 2; c8++) {
            float4 v0 = ga[c8 * 2], v1 = ga[c8 * 2 + 1];
            __half2 h0 = __floats2half2_rn(v0.x, v0.y);
            __half2 h1 = __floats2half2_rn(v0.z, v0.w);
            __half2 h2 = __floats2half2_rn(v1.x, v1.y);
            __half2 h3 = __floats2half2_rn(v1.z, v1.w);
            uint4 u;
            u.x = *(unsigned*)&h0; u.y = *(unsigned*)&h1;
            u.z = *(unsigned*)&h2; u.w = *(unsigned*)&h3;
            *(uint4*)(da + c8 * 8) = u;
        }
    }

    float acc[2][4][4] = {};

#pragma unroll 1
    for (int kt = 0; kt < 8; kt++) {
        float4 pa[4];
        if (MODE == 0 && kt < 7) {
            const float4* ga = (const float4*)(Af + (m0 + arow) * 256 + (kt + 1) * 32 + akoff);
#pragma unroll
            for (int c4 = 0; c4 < 4; c4++) pa[c4] = ga[c4];
        }
        if (kt < 6) asm volatile("cp.async.wait_group 1;");
        else        asm volatile("cp.async.wait_group 0;");
        __syncthreads();
        if (kt < 6) {
            const int nt = kt + 2;
            if (MODE == 1) {
                __half* sa = smem + (nt % 3) * GEMM_SLOT_H;
#pragma unroll
                for (int c = 0; c < 2; c++) {
                    const int idx = c * 256 + tid;
                    const int row = idx >> 2, seg = (idx & 3) * 8;
                    cpa16h(sa + row * 40 + seg, Ah + (m0 + row) * 256 + nt * 32 + seg);
                }
                __half* sb = sa + GEMM_A_H;
                const int row = tid >> 2, seg = (tid & 3) * 8;
                cpa16h(sb + row * 40 + seg, wt + (n0 + row) * 264 + nt * 32 + seg);
            } else {
                __half* sb = smem + 2 * GEMM_A_H + (nt % 3) * GEMM_B_H;
                const int row = tid >> 2, seg = (tid & 3) * 8;
                cpa16h(sb + row * 40 + seg, wt + (n0 + row) * 264 + nt * 32 + seg);
            }
            asm volatile("cp.async.commit_group;");
        }
        const __half* acur = (MODE == 1) ? (smem + (kt % 3) * GEMM_SLOT_H)
                                         : (smem + (kt & 1) * GEMM_A_H);
        const __half* bcur = (MODE == 1) ? (smem + (kt % 3) * GEMM_SLOT_H + GEMM_A_H)
                                         : (smem + 2 * GEMM_A_H + (kt % 3) * GEMM_B_H);
#pragma unroll
        for (int kc = 0; kc < 2; kc++) {
            unsigned a[2][4];
#pragma unroll
            for (int i = 0; i < 2; i++) {
                const __half* ap = acur + (wm * 32 + i * 16 + (g8 & 1) * 8 + r8) * 40
                                   + kc * 16 + (g8 >> 1) * 8;
                ldsm4h(a[i], ap);
            }
            unsigned bf0[4], bf1[4];
            ldsm4h(bf0, bcur + (wn * 32 + (g8 & 1) * 8 + r8) * 40 + kc * 16 + (g8 >> 1) * 8);
            ldsm4h(bf1, bcur + (wn * 32 + 16 + (g8 & 1) * 8 + r8) * 40 + kc * 16 + (g8 >> 1) * 8);
#pragma unroll
            for (int i = 0; i < 2; i++) {
                mma_f16(acc[i][0], a[i], bf0[0], bf0[2]);
                mma_f16(acc[i][1], a[i], bf0[1], bf0[3]);
                mma_f16(acc[i][2], a[i], bf1[0], bf1[2]);
                mma_f16(acc[i][3], a[i], bf1[1], bf1[3]);
            }
        }
        if (MODE == 0 && kt < 7) {
            __half* da = smem + ((kt + 1) & 1) * GEMM_A_H + arow * 40 + akoff;
#pragma unroll
            for (int c8 = 0; c8 < 2; c8++) {
                float4 v0 = pa[c8 * 2], v1 = pa[c8 * 2 + 1];
                __half2 h0 = __floats2half2_rn(v0.x, v0.y);
                __half2 h1 = __floats2half2_rn(v0.z, v0.w);
                __half2 h2 = __floats2half2_rn(v1.x, v1.y);
                __half2 h3 = __floats2half2_rn(v1.z, v1.w);
                uint4 u;
                u.x = *(unsigned*)&h0; u.y = *(unsigned*)&h1;
                u.z = *(unsigned*)&h2; u.w = *(unsigned*)&h3;
                *(uint4*)(da + c8 * 8) = u;
            }
        }
    }

    const float scale = 0.17677669529663687f * 1.4426950408889634f;
    const float r = (MODE == 1) ? rz[0] : 0.f;
#pragma unroll
    for (int i = 0; i < 2; i++) {
        const int m = m0 + wm * 32 + i * 16 + (lane >> 2);
#pragma unroll
        for (int j = 0; j < 4; j++) {
            const int col = n0 + wn * 32 + j * 8 + (lane & 3) * 2;
            const float b0 = bias[col], b1 = bias[col + 1];
            if (MODE == 0) {
                const int bi = m >> 14, rr = (m >> 7) & 127, cc = m & 127;
                const int win = bi * 64 + ((rr >> 4) << 3) + (cc >> 4);
                const int t = (rr & 15) * 16 + (cc & 15);
                const int head = col >> 5, d = col & 31;
                __half* p = g_qh + ((win * 8 + head) * 256 + t) * 32 + d;
                *(__half2*)p = __floats2half2_rn((acc[i][j][0] + b0) * scale,
                                                 (acc[i][j][1] + b1) * scale);
                *(__half2*)(p + 8 * 32) = __floats2half2_rn((acc[i][j][2] + b0) * scale,
                                                            (acc[i][j][3] + b1) * scale);
            } else {
                float* p = out + m * 256 + col;
                *(float2*)p = make_float2(r * (acc[i][j][0] + b0), r * (acc[i][j][1] + b1));
                *(float2*)(p + 8 * 256) = make_float2(r * (acc[i][j][2] + b0), r * (acc[i][j][3] + b1));
            }
        }
    }
}

// ---------------------------------------------------------------------------
// fp16 flash attention, static softmax shift, REGISTER P (FA-2 layout trick):
// the fp32 C-fragments of two adjacent n8 S-tiles, ex2'd and packed with
// __floats2half2_rn, ARE the A-fragment of the PV mma. No P smem, no
// syncwarp, no P ldsm — S->ex2->pack->PV all in registers.
// ---------------------------------------------------------------------------
#define ATT_QS_H 10240            // 256*40
#define ATT_KS_H (3*1280)         // 3 stages * 32*40
#define ATT_VS_H (3*1280)
#define ATT_SMEM_B ((ATT_QS_H + ATT_KS_H + ATT_VS_H) * 2)   // 35840 B

__global__ __launch_bounds__(256, 2) void attn_mma() {
    extern __shared__ char smc[];
    __half* Qs = (__half*)smc;
    __half* Ks = Qs + ATT_QS_H;
    __half* Vs = Ks + ATT_KS_H;

    const int win = blockIdx.x, hd = blockIdx.y;
    const int tid = threadIdx.x;
    const int lane = tid & 31, warp = tid >> 5;
    const int q = lane >> 2, t = lane & 3;
    const int g8 = lane >> 3, r8 = lane & 7;
    const int wb = warp * 32;

    const __half* qh = g_qh + (win * 8 + hd) * 8192;
    const __half* kh = g_kh + (win * 8 + hd) * 8192;
    const __half* vth = g_vh + (win * 8 + hd) * 8192;
    const float* bb = g_bias + (hd << 16);

    // Stage Q (LDG.128)
#pragma unroll
    for (int c = 0; c < 4; c++) {
        const int i = c * 256 + tid;
        const int row = i >> 2, seg = (i & 3) * 8;
        *(uint4*)&Qs[row * 40 + seg] = *(const uint4*)&qh[row * 32 + seg];
    }
    // K/V chunks 0,1 via cp.async
    {
        const int r = (tid & 127) >> 2, sg = (tid & 3) * 8;
#pragma unroll
        for (int c = 0; c < 2; c++) {
            if (tid < 128) cpa16h(Ks + c * 1280 + r * 40 + sg, kh + (c * 32 + r) * 32 + sg);
            else           cpa16h(Vs + c * 1280 + r * 40 + sg, vth + r * 256 + c * 32 + sg);
            asm volatile("cp.async.commit_group;");
        }
    }
    __syncthreads();

    unsigned qa[2][2][4];
#pragma unroll
    for (int mt = 0; mt < 2; mt++)
#pragma unroll
        for (int kc = 0; kc < 2; kc++)
            ldsm4h(qa[mt][kc], Qs + (wb + mt * 16 + (g8 & 1) * 8 + r8) * 40 + kc * 16 + (g8 >> 1) * 8);

    float o[2][4][4] = {};
    float lrow[2][2] = {};

#pragma unroll 1
    for (int sb = 0; sb < 8; sb++) {
        asm volatile("cp.async.wait_group 1;");
        __syncthreads();

        if (sb < 6) {
            const int slot = (sb + 2) % 3;
            const int r = (tid & 127) >> 2, sg = (tid & 3) * 8;
            if (tid < 128) cpa16h(Ks + slot * 1280 + r * 40 + sg, kh + ((sb + 2) * 32 + r) * 32 + sg);
            else           cpa16h(Vs + slot * 1280 + r * 40 + sg, vth + r * 256 + (sb + 2) * 32 + sg);
        }
        asm volatile("cp.async.commit_group;");

        const __half* Kb = Ks + (sb % 3) * 1280;
        const __half* Vb = Vs + (sb % 3) * 1280;

        // ---- S = Q K^T, bias (incl. static shift) as accumulator init ----
        float s[2][4][4];
#pragma unroll
        for (int mt = 0; mt < 2; mt++) {
            const float* br0 = bb + (wb + mt * 16 + q) * 256 + sb * 32 + t * 2;
            const float* br1 = br0 + 8 * 256;
#pragma unroll
            for (int nt = 0; nt < 4; nt++) {
                float2 b0 = *(const float2*)(br0 + nt * 8);
                float2 b1 = *(const float2*)(br1 + nt * 8);
                s[mt][nt][0] = b0.x; s[mt][nt][1] = b0.y;
                s[mt][nt][2] = b1.x; s[mt][nt][3] = b1.y;
            }
        }
#pragma unroll
        for (int kc = 0; kc < 2; kc++) {
#pragma unroll
            for (int nt16 = 0; nt16 < 2; nt16++) {
                unsigned kf[4];
                ldsm4h(kf, Kb + (nt16 * 16 + (g8 & 1) * 8 + r8) * 40 + kc * 16 + (g8 >> 1) * 8);
                mma_f16(s[0][nt16 * 2 + 0], qa[0][kc], kf[0], kf[2]);
                mma_f16(s[0][nt16 * 2 + 1], qa[0][kc], kf[1], kf[3]);
                mma_f16(s[1][nt16 * 2 + 0], qa[1][kc], kf[0], kf[2]);
                mma_f16(s[1][nt16 * 2 + 1], qa[1][kc], kf[1], kf[3]);
            }
        }

        // ---- p = ex2(s); pack C-frag -> A-frag IN REGISTERS ----
        unsigned pfr[2][2][4];   // [mt][kk = keys 16-block][4 A regs]
#pragma unroll
        for (int mt = 0; mt < 2; mt++) {
            float sm0 = 0.f, sm1 = 0.f;
#pragma unroll
            for (int nt = 0; nt < 4; nt++) {
                float p0 = ex2(s[mt][nt][0]);
                float p1 = ex2(s[mt][nt][1]);
                float p2 = ex2(s[mt][nt][2]);
                float p3 = ex2(s[mt][nt][3]);
                sm0 += p0 + p1; sm1 += p2 + p3;
                // n8-tile nt covers keys nt*8+2t{,+1}; rows r (p0,p1) and r+8 (p2,p3).
                // A-frag of 16x16 key-block kk=nt/2: even nt -> a0,a1; odd nt -> a2,a3.
                pfr[mt][nt >> 1][(nt & 1) * 2 + 0] = packh2(p0, p1);
                pfr[mt][nt >> 1][(nt & 1) * 2 + 1] = packh2(p2, p3);
            }
            lrow[mt][0] += sm0;
            lrow[mt][1] += sm1;
        }

        // ---- O += P V : P from registers, V via ldsm ----
#pragma unroll
        for (int kk = 0; kk < 2; kk++) {
#pragma unroll
            for (int dn16 = 0; dn16 < 2; dn16++) {
                unsigned vf[4];
                ldsm4h(vf, Vb + (dn16 * 16 + (g8 & 1) * 8 + r8) * 40 + kk * 16 + (g8 >> 1) * 8);
                mma_f16(o[0][dn16 * 2 + 0], pfr[0][kk], vf[0], vf[2]);
                mma_f16(o[0][dn16 * 2 + 1], pfr[0][kk], vf[1], vf[3]);
                mma_f16(o[1][dn16 * 2 + 0], pfr[1][kk], vf[0], vf[2]);
                mma_f16(o[1][dn16 * 2 + 1], pfr[1][kk], vf[1], vf[3]);
            }
        }
    }

    // Epilogue
    const int bimg = win >> 6, wh = (win >> 3) & 7, ww = win & 7;
#pragma unroll
    for (int mt = 0; mt < 2; mt++) {
        float l0 = lrow[mt][0], l1 = lrow[mt][1];
        l0 += __shfl_xor_sync(0xffffffff, l0, 1);
        l0 += __shfl_xor_sync(0xffffffff, l0, 2);
        l1 += __shfl_xor_sync(0xffffffff, l1, 1);
        l1 += __shfl_xor_sync(0xffffffff, l1, 2);
        const float inv0 = 1.f / l0;
        const float inv1 = 1.f / l1;
        const int tk0 = wb + mt * 16 + q;
#pragma unroll
        for (int half = 0; half < 2; half++) {
            const int tk = tk0 + half * 8;
            const float inv = half ? inv1 : inv0;
            const int gr = wh * 16 + (tk >> 4), gc = ww * 16 + (tk & 15);
            __half* op = g_oh + ((bimg * 128 + gr) * 128 + gc) * 256 + hd * 32;
#pragma unroll
            for (int dn = 0; dn < 4; dn++) {
                *(__half2*)(op + dn * 8 + t * 2) =
                    __floats2half2_rn(o[mt][dn][half * 2] * inv, o[mt][dn][half * 2 + 1] * inv);
            }
        }
    }
}

// ---------------------------------------------------------------------------
extern "C" void kernel_launch(void* const* d_in, const int* in_sizes, int n_in,
                              void* d_out, int out_size) {
    (void)in_sizes; (void)n_in; (void)out_size;
    const float* x_wsa      = (const float*)d_in[0];
    const float* x_original = (const float*)d_in[1];
    const float* q_w        = (const float*)d_in[2];
    const float* q_b        = (const float*)d_in[3];
    const float* kv_w       = (const float*)d_in[4];
    const float* kv_b       = (const float*)d_in[5];
    const float* out_w      = (const float*)d_in[6];
    const float* out_b      = (const float*)d_in[7];
    const float* bias_table = (const float*)d_in[8];
    const float* rezero     = (const float*)d_in[9];
    float* out = (float*)d_out;

    cudaFuncSetAttribute(convkv_mma, cudaFuncAttributeMaxDynamicSharedMemorySize, CONV_SMEM_B);
    cudaFuncSetAttribute(gemm_mma<0>, cudaFuncAttributeMaxDynamicSharedMemorySize, GEMM_SMEM_B0);
    cudaFuncSetAttribute(gemm_mma<1>, cudaFuncAttributeMaxDynamicSharedMemorySize, GEMM_SMEM_B1);
    cudaFuncSetAttribute(attn_mma, cudaFuncAttributeMaxDynamicSharedMemorySize, ATT_SMEM_B);

    prep_all<<<4160, 256>>>(bias_table, q_w, out_w, kv_w);                          // #1
    gemm_mma<0><<<dim3(512, 4), 256, GEMM_SMEM_B0>>>(x_wsa, q_b, nullptr, nullptr); // #2
    convkv_mma<<<dim3(64, 32), 256, CONV_SMEM_B>>>(x_original, kv_b);               // #3
    attn_mma<<<dim3(256, 8), 256, ATT_SMEM_B>>>();                                  // #4 <- profiled
    gemm_mma<1><<<dim3(512, 4), 256, GEMM_SMEM_B1>>>(nullptr, out_b, rezero, out);  // #5
}